// round 10
// baseline (speedup 1.0000x reference)
#include <cuda_runtime.h>
#include <cuda_bf16.h>
#include <math.h>
#include <stdint.h>

using bf16 = __nv_bfloat16;

#define NB   4
#define NS   2048
#define NH   16
#define NHD  128
#define NRD  64
#define NLAT 512
#define NHID 2048
#define NM   (NB*NS)

// ---------------- device scratch ----------------
__device__ float g_krr [(size_t)NM*NRD];
__device__ float g_qcr [(size_t)NM*2048];
__device__ float g_kc  [(size_t)NM*1024];
__device__ float g_ctx [(size_t)NM*NHID];
__device__ float g_cs  [NS*32];
__device__ float g_sn  [NS*32];

// bf16 split weights (6 weights; wo now int8)
__device__ bf16 g_xs    [2][(size_t)NM*NHID];
__device__ bf16 g_wd_f  [2][(size_t)1024*2048];
__device__ bf16 g_wuq_f [2][(size_t)2048*512];
__device__ bf16 g_wukv_f[2][(size_t)3072*512];
__device__ bf16 g_lat_s [2][(size_t)NM*1024];

__device__ bf16 g_Qh[(size_t)NM*NHID];
__device__ bf16 g_Ql[(size_t)NM*NHID];
__device__ bf16 g_Kh[(size_t)NM*NHID];
__device__ bf16 g_Kl[(size_t)NM*NHID];
__device__ bf16 g_Vh[(size_t)NM*NHID];
__device__ bf16 g_Vl[(size_t)NM*NHID];

// int8 out-projection path
__device__ float  g_woT [(size_t)2048*2048];   // wo transposed fp32 [N,K]
__device__ int8_t g_woq1[(size_t)2048*2048];
__device__ int8_t g_woq2[(size_t)2048*2048];
__device__ float  g_wosc[2048];
__device__ int8_t g_cq1 [(size_t)NM*NHID];
__device__ int8_t g_cq2 [(size_t)NM*NHID];
__device__ float  g_csc [NM];

// ---------------- PTX helpers ----------------
__device__ __forceinline__ void cp16(uint32_t s, const void* g) {
    asm volatile("cp.async.cg.shared.global [%0], [%1], 16;\n" :: "r"(s), "l"(g));
}

#define LDM_X4(R, addr) \
    asm volatile("ldmatrix.sync.aligned.m8n8.x4.shared.b16 {%0,%1,%2,%3}, [%4];" \
        : "=r"(R[0]), "=r"(R[1]), "=r"(R[2]), "=r"(R[3]) : "r"(addr))
#define LDM_X4_T(R, addr) \
    asm volatile("ldmatrix.sync.aligned.m8n8.x4.trans.shared.b16 {%0,%1,%2,%3}, [%4];" \
        : "=r"(R[0]), "=r"(R[1]), "=r"(R[2]), "=r"(R[3]) : "r"(addr))
#define MMA16816(D, A, B0, B1) \
    asm volatile("mma.sync.aligned.m16n8k16.row.col.f32.bf16.bf16.f32 " \
        "{%0,%1,%2,%3}, {%4,%5,%6,%7}, {%8,%9}, {%0,%1,%2,%3};" \
        : "+f"(D[0]), "+f"(D[1]), "+f"(D[2]), "+f"(D[3]) \
        : "r"(A[0]), "r"(A[1]), "r"(A[2]), "r"(A[3]), "r"(B0), "r"(B1))
#define IMMA16832(D, A, B0, B1) \
    asm volatile("mma.sync.aligned.m16n8k32.row.col.s32.s8.s8.s32 " \
        "{%0,%1,%2,%3}, {%4,%5,%6,%7}, {%8,%9}, {%0,%1,%2,%3};" \
        : "+r"(D[0]), "+r"(D[1]), "+r"(D[2]), "+r"(D[3]) \
        : "r"(A[0]), "r"(A[1]), "r"(A[2]), "r"(A[3]), "r"(B0), "r"(B1))

__device__ __forceinline__ uint32_t pack_bf16(float a, float b) {
    uint32_t r;
    asm("cvt.rn.bf16x2.f32 %0, %1, %2;" : "=r"(r) : "f"(b), "f"(a));
    return r;
}
__device__ __forceinline__ float rn_bf16(float f) {
    return __bfloat162float(__float2bfloat16(f));
}

// ---------------- splits ----------------
__global__ void split4_kernel(const float4* __restrict__ in,
                              uint32_t* __restrict__ hi, uint32_t* __restrict__ lo)
{
    size_t i = (size_t)blockIdx.x * blockDim.x + threadIdx.x;
    float4 f = in[i];
    float hx = rn_bf16(f.x), hy = rn_bf16(f.y), hz = rn_bf16(f.z), hw = rn_bf16(f.w);
    hi[2*i]   = pack_bf16(hx, hy);
    hi[2*i+1] = pack_bf16(hz, hw);
    lo[2*i]   = pack_bf16(f.x - hx, f.y - hy);
    lo[2*i+1] = pack_bf16(f.z - hz, f.w - hw);
}

// batched transpose + split for 6 bf16 weights
struct TAll {
    const float* src[6];
    bf16* hi[6];
    bf16* lo[6];
    int   K[6];
    int   N[6];
    int   start[7];
};

__global__ void tsplit_all_kernel(TAll ta)
{
    __shared__ float t[32][33];
    int bid = blockIdx.x;
    int i = 0;
    #pragma unroll
    for (int j = 1; j < 6; j++) if (bid >= ta.start[j]) i = j;
    int lb = bid - ta.start[i];
    int K = ta.K[i], N = ta.N[i];
    int nbx = N >> 5;
    int n0 = (lb % nbx) * 32, k0 = (lb / nbx) * 32;
    const float* src = ta.src[i];
    bf16* hi = ta.hi[i];
    bf16* lo = ta.lo[i];

    int tx = threadIdx.x, ty = threadIdx.y;
    #pragma unroll
    for (int j = 0; j < 4; j++)
        t[ty + j*8][tx] = src[(size_t)(k0 + ty + j*8) * N + n0 + tx];
    __syncthreads();
    #pragma unroll
    for (int j = 0; j < 4; j++) {
        float f = t[tx][ty + j*8];
        bf16 h = __float2bfloat16(f);
        size_t o = (size_t)(n0 + ty + j*8) * K + k0 + tx;
        hi[o] = h;
        lo[o] = __float2bfloat16(f - __bfloat162float(h));
    }
}

// fp32 transpose (for wo): W[K,N] -> Wt[N,K]
__global__ void ftrans_kernel(const float* __restrict__ in, float* __restrict__ out,
                              int K, int N)
{
    __shared__ float t[32][33];
    int n0 = blockIdx.x * 32, k0 = blockIdx.y * 32;
    int tx = threadIdx.x, ty = threadIdx.y;
    #pragma unroll
    for (int j = 0; j < 4; j++)
        t[ty + j*8][tx] = in[(size_t)(k0 + ty + j*8) * N + n0 + tx];
    __syncthreads();
    #pragma unroll
    for (int j = 0; j < 4; j++)
        out[(size_t)(n0 + ty + j*8) * K + k0 + tx] = t[tx][ty + j*8];
}

// ---------------- two-level int8 row quantization (K = 2048) ----------------
// src row-major [rows, 2048]. Each block = 1 row, 256 threads x 8 consecutive elems.
// A ~= s*q1 + (s/254)*q2.
__global__ void __launch_bounds__(256)
quant_rows2048_kernel(const float* __restrict__ src,
                      int8_t* __restrict__ q1, int8_t* __restrict__ q2,
                      float* __restrict__ sc)
{
    __shared__ float red[8];
    const int row = blockIdx.x;
    const int tid = threadIdx.x;
    const float* p = src + (size_t)row * 2048 + tid * 8;

    float4 v0 = *(const float4*)p;
    float4 v1 = *(const float4*)(p + 4);
    float v[8] = { v0.x, v0.y, v0.z, v0.w, v1.x, v1.y, v1.z, v1.w };

    float amax = 0.f;
    #pragma unroll
    for (int i = 0; i < 8; i++) amax = fmaxf(amax, fabsf(v[i]));
    #pragma unroll
    for (int off = 16; off > 0; off >>= 1)
        amax = fmaxf(amax, __shfl_xor_sync(0xffffffffu, amax, off));
    if ((tid & 31) == 0) red[tid >> 5] = amax;
    __syncthreads();
    if (tid < 8) {
        float m = red[tid];
        #pragma unroll
        for (int off = 4; off > 0; off >>= 1)
            m = fmaxf(m, __shfl_xor_sync(0xffu, m, off));
        if (tid == 0) red[0] = (m > 0.f) ? m : 1.f;
    }
    __syncthreads();
    float s  = red[0] / 127.f;
    float is = 1.f / s;
    float s2 = s / 254.f;
    float is2 = 1.f / s2;

    uint8_t b1[8], b2[8];
    #pragma unroll
    for (int i = 0; i < 8; i++) {
        int iq1 = __float2int_rn(v[i] * is);
        float r = v[i] - (float)iq1 * s;
        int iq2 = __float2int_rn(r * is2);
        iq2 = max(-127, min(127, iq2));
        b1[i] = (uint8_t)(int8_t)iq1;
        b2[i] = (uint8_t)(int8_t)iq2;
    }
    uint2 w1, w2;
    w1.x = b1[0] | (b1[1]<<8) | (b1[2]<<16) | ((uint32_t)b1[3]<<24);
    w1.y = b1[4] | (b1[5]<<8) | (b1[6]<<16) | ((uint32_t)b1[7]<<24);
    w2.x = b2[0] | (b2[1]<<8) | (b2[2]<<16) | ((uint32_t)b2[3]<<24);
    w2.y = b2[4] | (b2[5]<<8) | (b2[6]<<16) | ((uint32_t)b2[7]<<24);
    *(uint2*)(q1 + (size_t)row * 2048 + tid * 8) = w1;
    *(uint2*)(q2 + (size_t)row * 2048 + tid * 8) = w2;
    if (tid == 0) sc[row] = s;
}

// ---------------- int8 two-level GEMM (out projection) ----------------
// C[M,N] = SA[r]*SB[c]*(acc1 + acc2/254) + bias. A[M,K], Bt[N,K] int8 q1/q2.
// Block 128x128, BK=64 int8, 256 threads (8 warps, 2x4), warp tile 64x32.
#define I8_TILE_B (128*80)          // 10240 B per tile (64 data cols + pad to 80)
#define I8_SMEM   (8*I8_TILE_B)     // 81920 B

__device__ __forceinline__ void i8_fill(
    uint32_t sb, int buf,
    const int8_t* __restrict__ Aq1, const int8_t* __restrict__ Aq2,
    const int8_t* __restrict__ Bq1, const int8_t* __restrict__ Bq2,
    int tid, int row0, int col0, int k0, int K)
{
    #pragma unroll
    for (int j = 0; j < 2; j++) {
        int chunk = tid + 256*j;              // 512 chunks: 128 rows x 4 x 16B
        int r = chunk >> 2, cc = chunk & 3;
        size_t ga = (size_t)(row0 + r) * K + k0 + cc*16;
        size_t gb = (size_t)(col0 + r) * K + k0 + cc*16;
        uint32_t off = (uint32_t)(r*80 + cc*16);
        cp16(sb + (buf*4+0)*I8_TILE_B + off, Aq1 + ga);
        cp16(sb + (buf*4+1)*I8_TILE_B + off, Aq2 + ga);
        cp16(sb + (buf*4+2)*I8_TILE_B + off, Bq1 + gb);
        cp16(sb + (buf*4+3)*I8_TILE_B + off, Bq2 + gb);
    }
    asm volatile("cp.async.commit_group;");
}

__global__ void __launch_bounds__(256)
bgemm_i8_kernel(const int8_t* __restrict__ Aq1, const int8_t* __restrict__ Aq2,
                const int8_t* __restrict__ Bq1, const int8_t* __restrict__ Bq2,
                const float* __restrict__ SA, const float* __restrict__ SB,
                float* __restrict__ C, const float* __restrict__ bias,
                int K, int N)
{
    extern __shared__ char i8sm[];
    const uint32_t sb = (uint32_t)__cvta_generic_to_shared(i8sm);

    const int tid  = threadIdx.x;
    const int lane = tid & 31;
    const int wid  = tid >> 5;
    const int m0w  = (wid >> 2) * 64;
    const int n0w  = (wid & 3) * 32;
    const int row0 = blockIdx.y * 128;
    const int col0 = blockIdx.x * 128;

    int acc1[4][4][4], acc2[4][4][4];
    #pragma unroll
    for (int i = 0; i < 4; i++)
        #pragma unroll
        for (int j = 0; j < 4; j++)
            #pragma unroll
            for (int k = 0; k < 4; k++) { acc1[i][j][k] = 0; acc2[i][j][k] = 0; }

    const int niter = K >> 6;
    i8_fill(sb, 0, Aq1, Aq2, Bq1, Bq2, tid, row0, col0, 0, K);

    const int aRow = m0w + (lane & 15);
    const int bRow = n0w + (lane & 15);
    const int col16 = 16 * (lane >> 4);

    for (int it = 0; it < niter; ++it) {
        const int buf = it & 1;
        if (it + 1 < niter) {
            i8_fill(sb, buf ^ 1, Aq1, Aq2, Bq1, Bq2, tid, row0, col0, (it+1)*64, K);
            asm volatile("cp.async.wait_group 1;");
        } else {
            asm volatile("cp.async.wait_group 0;");
        }
        __syncthreads();

        #pragma unroll
        for (int sub = 0; sub < 64; sub += 32) {
            uint32_t a1[4][4], a2[4][4];
            #pragma unroll
            for (int mt = 0; mt < 4; mt++) {
                uint32_t addr = sb + (buf*4+0)*I8_TILE_B +
                    (uint32_t)((aRow + mt*16)*80 + sub + col16);
                LDM_X4(a1[mt], addr);
                LDM_X4(a2[mt], addr + I8_TILE_B);
            }
            // B frag pairs for int8 k32: n0-7 -> (r0,r2); n8-15 -> (r1,r3)
            #pragma unroll
            for (int ng = 0; ng < 2; ng++) {
                uint32_t b1[4], b2[4];
                uint32_t addr = sb + (buf*4+2)*I8_TILE_B +
                    (uint32_t)((bRow + ng*16)*80 + sub + col16);
                LDM_X4(b1, addr);
                LDM_X4(b2, addr + I8_TILE_B);
                #pragma unroll
                for (int half = 0; half < 2; half++) {
                    uint32_t b0q1 = b1[half], b1q1 = b1[half+2];
                    uint32_t b0q2 = b2[half], b1q2 = b2[half+2];
                    int nt = ng*2 + half;
                    #pragma unroll
                    for (int mt = 0; mt < 4; mt++) {
                        IMMA16832(acc1[mt][nt], a1[mt], b0q1, b1q1);
                        IMMA16832(acc2[mt][nt], a1[mt], b0q2, b1q2);
                        IMMA16832(acc2[mt][nt], a2[mt], b0q1, b1q1);
                    }
                }
            }
        }
        __syncthreads();
    }

    const float inv254 = 1.f / 254.f;
    #pragma unroll
    for (int mt = 0; mt < 4; mt++) {
        int r = row0 + m0w + mt*16 + (lane >> 2);
        float sa0 = SA[r], sa1 = SA[r+8];
        #pragma unroll
        for (int nt = 0; nt < 4; nt++) {
            int cc = col0 + n0w + nt*8 + (lane & 3)*2;
            float sb0 = SB[cc], sb1 = SB[cc+1];
            float bb0 = bias[cc], bb1 = bias[cc+1];
            float v00 = sa0*sb0*((float)acc1[mt][nt][0] + (float)acc2[mt][nt][0]*inv254) + bb0;
            float v01 = sa0*sb1*((float)acc1[mt][nt][1] + (float)acc2[mt][nt][1]*inv254) + bb1;
            float v10 = sa1*sb0*((float)acc1[mt][nt][2] + (float)acc2[mt][nt][2]*inv254) + bb0;
            float v11 = sa1*sb1*((float)acc1[mt][nt][3] + (float)acc2[mt][nt][3]*inv254) + bb1;
            *(float2*)(C + (size_t)r     * N + cc) = make_float2(v00, v01);
            *(float2*)(C + (size_t)(r+8) * N + cc) = make_float2(v10, v11);
        }
    }
}

// ---------------- mma.sync split-bf16 GEMM (unchanged structure) ----------------
#define SA_ELEMS (128*40)
#define BG_SMEM ((8*SA_ELEMS)*2)

__device__ __forceinline__ void bgemm_fill(
    uint32_t smem_base, int buf,
    const bf16* __restrict__ Ah, const bf16* __restrict__ Al,
    const bf16* __restrict__ Bh, const bf16* __restrict__ Bl,
    int tid, int row0, int col0, int k0, int lda, int ldb)
{
    #pragma unroll
    for (int j = 0; j < 4; j++) {
        int chunk = tid + 128*j;
        int r = chunk >> 2, cc = chunk & 3;
        size_t ga = (size_t)(row0 + r) * lda + k0 + cc*8;
        size_t gb = (size_t)(col0 + r) * ldb + k0 + cc*8;
        uint32_t off = (uint32_t)(r*40 + cc*8)*2;
        cp16(smem_base + (buf*2+0)*SA_ELEMS*2 + off, Ah + ga);
        cp16(smem_base + (buf*2+1)*SA_ELEMS*2 + off, Al + ga);
        cp16(smem_base + (4 + buf*2+0)*SA_ELEMS*2 + off, Bh + gb);
        cp16(smem_base + (4 + buf*2+1)*SA_ELEMS*2 + off, Bl + gb);
    }
    asm volatile("cp.async.commit_group;");
}

// EPI 0: fp32 (stride Nc). 2: bf16 hi/lo (stride Ns). 3: mixed at boundary.
template<int EPI>
__global__ void __launch_bounds__(128)
bgemm_kernel(const bf16* __restrict__ Ah, const bf16* __restrict__ Al,
             const bf16* __restrict__ Bh, const bf16* __restrict__ Bl,
             float* __restrict__ C, bf16* __restrict__ Chi, bf16* __restrict__ Clo,
             int lda, int K, int Nc, int Ns, int boundary)
{
    extern __shared__ bf16 smem_dyn[];
    const uint32_t smem_base = (uint32_t)__cvta_generic_to_shared(smem_dyn);

    const int tid  = threadIdx.x;
    const int lane = tid & 31;
    const int wid  = tid >> 5;
    const int m0w  = (wid >> 1) * 64;
    const int n0w  = (wid & 1) * 64;
    const int row0 = blockIdx.y * 128;
    const int col0 = blockIdx.x * 128;

    float acc[4][8][4];
    #pragma unroll
    for (int i = 0; i < 4; i++)
        #pragma unroll
        for (int j = 0; j < 8; j++)
            #pragma unroll
            for (int k = 0; k < 4; k++) acc[i][j][k] = 0.f;

    const int niter = K >> 5;
    bgemm_fill(smem_base, 0, Ah, Al, Bh, Bl, tid, row0, col0, 0, lda, K);

    const int aRow  = m0w + (lane & 15);
    const int aCol8 = 8 * (lane >> 4);
    const int bRow  = n0w + (lane & 15);

    for (int it = 0; it < niter; ++it) {
        const int buf = it & 1;
        if (it + 1 < niter) {
            bgemm_fill(smem_base, buf ^ 1, Ah, Al, Bh, Bl, tid, row0, col0, (it+1)*32, lda, K);
            asm volatile("cp.async.wait_group 1;");
        } else {
            asm volatile("cp.async.wait_group 0;");
        }
        __syncthreads();

        #pragma unroll
        for (int sub = 0; sub < 32; sub += 16) {
            uint32_t ah[4][4], al[4][4];
            #pragma unroll
            for (int mt = 0; mt < 4; mt++) {
                uint32_t addr = smem_base +
                    (uint32_t)((buf*2)*SA_ELEMS + (aRow + mt*16)*40 + sub + aCol8)*2;
                LDM_X4(ah[mt], addr);
                LDM_X4(al[mt], addr + SA_ELEMS*2);
            }
            #pragma unroll
            for (int ng = 0; ng < 4; ng++) {
                uint32_t bh[4], bl[4];
                uint32_t addr = smem_base +
                    (uint32_t)((4 + buf*2)*SA_ELEMS + (bRow + ng*16)*40 + sub + aCol8)*2;
                LDM_X4(bh, addr);
                LDM_X4(bl, addr + SA_ELEMS*2);
                #pragma unroll
                for (int half = 0; half < 2; half++) {
                    uint32_t b0h = bh[half], b1h = bh[half+2];
                    uint32_t b0l = bl[half], b1l = bl[half+2];
                    int nt = ng*2 + half;
                    #pragma unroll
                    for (int mt = 0; mt < 4; mt++) {
                        MMA16816(acc[mt][nt], ah[mt], b0h, b1h);
                        MMA16816(acc[mt][nt], ah[mt], b0l, b1l);
                        MMA16816(acc[mt][nt], al[mt], b0h, b1h);
                    }
                }
            }
        }
        __syncthreads();
    }

    const bool fp32_mode = (EPI == 0) || (EPI == 3 && col0 < boundary);
    #pragma unroll
    for (int mt = 0; mt < 4; mt++) {
        #pragma unroll
        for (int nt = 0; nt < 8; nt++) {
            int r  = row0 + m0w + mt*16 + (lane >> 2);
            int cc = col0 + n0w + nt*8 + (lane & 3)*2;
            float a0 = acc[mt][nt][0], a1 = acc[mt][nt][1];
            float a2 = acc[mt][nt][2], a3 = acc[mt][nt][3];
            if (fp32_mode) {
                *(float2*)(C + (size_t)r     * Nc + cc) = make_float2(a0, a1);
                *(float2*)(C + (size_t)(r+8) * Nc + cc) = make_float2(a2, a3);
            } else {
                int cs = (EPI == 3) ? (cc - boundary) : cc;
                float h0 = rn_bf16(a0), h1 = rn_bf16(a1);
                float h2 = rn_bf16(a2), h3 = rn_bf16(a3);
                *(uint32_t*)(Chi + (size_t)r     * Ns + cs) = pack_bf16(h0, h1);
                *(uint32_t*)(Clo + (size_t)r     * Ns + cs) = pack_bf16(a0 - h0, a1 - h1);
                *(uint32_t*)(Chi + (size_t)(r+8) * Ns + cs) = pack_bf16(h2, h3);
                *(uint32_t*)(Clo + (size_t)(r+8) * Ns + cs) = pack_bf16(a2 - h2, a3 - h3);
            }
        }
    }
}

// ---------------- fp32 SGEMM (tiny wk_rope, N=64) ----------------
__global__ void __launch_bounds__(256)
sgemm_kernel(const float* __restrict__ A, const float* __restrict__ W,
             float* __restrict__ C, int N, int K)
{
    __shared__ float As[16][132];
    __shared__ float Bs[16][128];

    const int tid = threadIdx.x;
    const int tx = tid & 15, ty = tid >> 4;
    const int bx = blockIdx.x, by = blockIdx.y;

    const int a_r = tid >> 2;
    const int a_c = (tid & 3) << 2;
    const int b_r = tid >> 5;
    const int b_c = (tid & 31) << 2;

    const float* Ab = A + (size_t)by * 128 * K;

    float acc[8][8];
    #pragma unroll
    for (int i = 0; i < 8; i++)
        #pragma unroll
        for (int j = 0; j < 8; j++) acc[i][j] = 0.f;

    for (int k0 = 0; k0 < K; k0 += 16) {
        #pragma unroll
        for (int u = 0; u < 2; u++) {
            int r = a_r + u*64;
            float4 v = *(const float4*)(Ab + (size_t)r * K + (k0 + a_c));
            As[a_c+0][r] = v.x; As[a_c+1][r] = v.y;
            As[a_c+2][r] = v.z; As[a_c+3][r] = v.w;
        }
        #pragma unroll
        for (int u = 0; u < 2; u++) {
            int r = b_r + u*8;
            int col = bx*128 + b_c;
            float4 v = make_float4(0.f, 0.f, 0.f, 0.f);
            if (col < N) v = *(const float4*)(W + (size_t)(k0 + r) * N + col);
            *(float4*)&Bs[r][b_c] = v;
        }
        __syncthreads();
        #pragma unroll
        for (int k = 0; k < 16; k++) {
            float a[8], b[8];
            *(float4*)&a[0] = *(const float4*)&As[k][ty*8];
            *(float4*)&a[4] = *(const float4*)&As[k][ty*8+4];
            *(float4*)&b[0] = *(const float4*)&Bs[k][tx*8];
            *(float4*)&b[4] = *(const float4*)&Bs[k][tx*8+4];
            #pragma unroll
            for (int i = 0; i < 8; i++)
                #pragma unroll
                for (int j = 0; j < 8; j++)
                    acc[i][j] = fmaf(a[i], b[j], acc[i][j]);
        }
        __syncthreads();
    }

    const int row0 = by*128 + ty*8;
    const int col0 = bx*128 + tx*8;
    #pragma unroll
    for (int i = 0; i < 8; i++) {
        #pragma unroll
        for (int j = 0; j < 8; j += 4) {
            int col = col0 + j;
            if (col < N) {
                float4 v = make_float4(acc[i][j], acc[i][j+1], acc[i][j+2], acc[i][j+3]);
                *(float4*)(C + (size_t)(row0+i)*N + col) = v;
            }
        }
    }
}

// ---------------- RoPE LUT + merged pack ----------------
__global__ void rope_lut_kernel()
{
    int idx = blockIdx.x * blockDim.x + threadIdx.x;
    int pos = idx >> 5, fi = idx & 31;
    float inv = powf(10000.f, -(float)(2*fi) / 64.f);
    float ang = (float)pos * inv;
    float s, c;
    sincosf(ang, &s, &c);
    g_cs[idx] = c;
    g_sn[idx] = s;
}

__global__ void pack_qk_kernel()
{
    int gidx = blockIdx.x * blockDim.x + threadIdx.x;
    const int TOT = NM * NHID;
    bool isK = gidx >= TOT;
    int idx = isK ? (gidx - TOT) : gidx;
    int row = idx >> 11;
    int c   = idx & (NHID - 1);
    int h = c >> 7, d = c & 127;
    float out;
    if (!isK) {
        if (d < 64) {
            out = g_qcr[(size_t)row*2048 + h*64 + d];
        } else {
            int dd = d - 64;
            const float* qr = g_qcr + (size_t)row*2048 + 1024 + h*64;
            int pos = row & (NS - 1);
            float cs = g_cs[pos*32 + (dd & 31)], sn = g_sn[pos*32 + (dd & 31)];
            float v = qr[dd];
            float w = (dd < 32) ? -qr[dd + 32] : qr[dd - 32];
            out = v * cs + w * sn;
        }
        out *= 0.08838834764831845f;
        bf16 hi = __float2bfloat16(out);
        g_Qh[idx] = hi;
        g_Ql[idx] = __float2bfloat16(out - __bfloat162float(hi));
    } else {
        if (d < 64) {
            out = g_kc[(size_t)row*1024 + h*64 + d];
        } else {
            int dd = d - 64;
            const float* kr = g_krr + (size_t)row*NRD;
            int pos = row & (NS - 1);
            float cs = g_cs[pos*32 + (dd & 31)], sn = g_sn[pos*32 + (dd & 31)];
            float v = kr[dd];
            float w = (dd < 32) ? -kr[dd + 32] : kr[dd - 32];
            out = v * cs + w * sn;
        }
        bf16 hi = __float2bfloat16(out);
        g_Kh[idx] = hi;
        g_Kl[idx] = __float2bfloat16(out - __bfloat162float(hi));
    }
}

// ---------------- mma.sync split-bf16 flash attention (fp32 ctx out) ----------------
#define FS 136
#define FTILE_B (64*FS*2)

__global__ void __launch_bounds__(128)
flasht_kernel(const bf16* __restrict__ Qh, const bf16* __restrict__ Ql,
              const bf16* __restrict__ Kh, const bf16* __restrict__ Kl,
              const bf16* __restrict__ Vh, const bf16* __restrict__ Vl,
              float* __restrict__ O)
{
    extern __shared__ bf16 fsm[];
    const uint32_t sb = (uint32_t)__cvta_generic_to_shared(fsm);

    const int tid = threadIdx.x;
    const int lane = tid & 31;
    const int w = tid >> 5;
    const int lr = lane >> 2;
    const int lc = (lane & 3) * 2;
    const int h = blockIdx.y, b = blockIdx.z;
    const int q0 = blockIdx.x * 64;
    const size_t base = ((size_t)b * NS) * NHID + (size_t)h * NHD;

    for (int i = tid; i < 1024; i += 128) {
        int r = i >> 4, c = (i & 15) << 3;
        uint32_t so = (uint32_t)(r*FS + c) * 2;
        size_t go = base + (size_t)(q0 + r) * NHID + c;
        cp16(sb + 0*FTILE_B + so, Qh + go);
        cp16(sb + 1*FTILE_B + so, Ql + go);
    }
    asm volatile("cp.async.commit_group;");

    float m0 = -1e30f, m1 = -1e30f, l0 = 0.f, l1 = 0.f;
    float o[16][4];
    #pragma unroll
    for (int i = 0; i < 16; i++)
        #pragma unroll
        for (int j = 0; j < 4; j++) o[i][j] = 0.f;

    const int aRow = w*16 + (lane & 15);
    const int hi8  = 8 * (lane >> 4);
    const int ntiles = blockIdx.x + 1;

    for (int t = 0; t < ntiles; t++) {
        const int k0 = t * 64;
        if (t) __syncthreads();
        for (int i = tid; i < 1024; i += 128) {
            int r = i >> 4, c = (i & 15) << 3;
            uint32_t so = (uint32_t)(r*FS + c) * 2;
            size_t go = base + (size_t)(k0 + r) * NHID + c;
            cp16(sb + 2*FTILE_B + so, Kh + go);
            cp16(sb + 3*FTILE_B + so, Kl + go);
            cp16(sb + 4*FTILE_B + so, Vh + go);
            cp16(sb + 5*FTILE_B + so, Vl + go);
        }
        asm volatile("cp.async.commit_group;");
        asm volatile("cp.async.wait_group 0;");
        __syncthreads();

        float s[8][4];
        #pragma unroll
        for (int i = 0; i < 8; i++)
            #pragma unroll
            for (int j = 0; j < 4; j++) s[i][j] = 0.f;

        #pragma unroll
        for (int kc = 0; kc < 8; kc++) {
            uint32_t qh[4], ql[4];
            uint32_t qa = sb + (uint32_t)(aRow*FS + kc*16 + hi8)*2;
            LDM_X4(qh, qa);
            LDM_X4(ql, qa + FTILE_B);
            #pragma unroll
            for (int g = 0; g < 4; g++) {
                uint32_t kh[4], kl[4];
                uint32_t ka = sb + 2*FTILE_B + (uint32_t)((g*16 + (lane & 15))*FS + kc*16 + hi8)*2;
                LDM_X4(kh, ka);
                LDM_X4(kl, ka + FTILE_B);
                MMA16816(s[2*g],   qh, kh[0], kh[2]);
                MMA16816(s[2*g],   qh, kl[0], kl[2]);
                MMA16816(s[2*g],   ql, kh[0], kh[2]);
                MMA16816(s[2*g+1], qh, kh[1], kh[3]);
                MMA16816(s[2*g+1], qh, kl[1], kl[3]);
                MMA16816(s[2*g+1], ql, kh[1], kh[3]);
            }
        }

        if (t == blockIdx.x) {
            int r0 = q0 + w*16 + lr, r1 = r0 + 8;
            #pragma unroll
            for (int nt = 0; nt < 8; nt++) {
                int c = k0 + nt*8 + lc;
                if (c     > r0) s[nt][0] = -1e30f;
                if (c + 1 > r0) s[nt][1] = -1e30f;
                if (c     > r1) s[nt][2] = -1e30f;
                if (c + 1 > r1) s[nt][3] = -1e30f;
            }
        }

        float mt0 = -1e30f, mt1 = -1e30f;
        #pragma unroll
        for (int nt = 0; nt < 8; nt++) {
            mt0 = fmaxf(mt0, fmaxf(s[nt][0], s[nt][1]));
            mt1 = fmaxf(mt1, fmaxf(s[nt][2], s[nt][3]));
        }
        mt0 = fmaxf(mt0, __shfl_xor_sync(0xffffffffu, mt0, 1));
        mt0 = fmaxf(mt0, __shfl_xor_sync(0xffffffffu, mt0, 2));
        mt1 = fmaxf(mt1, __shfl_xor_sync(0xffffffffu, mt1, 1));
        mt1 = fmaxf(mt1, __shfl_xor_sync(0xffffffffu, mt1, 2));
        float n0 = fmaxf(m0, mt0), n1 = fmaxf(m1, mt1);
        float corr0 = __expf(m0 - n0), corr1 = __expf(m1 - n1);
        m0 = n0; m1 = n1;

        float ps0 = 0.f, ps1 = 0.f;
        #pragma unroll
        for (int nt = 0; nt < 8; nt++) {
            s[nt][0] = __expf(s[nt][0] - n0);
            s[nt][1] = __expf(s[nt][1] - n0);
            s[nt][2] = __expf(s[nt][2] - n1);
            s[nt][3] = __expf(s[nt][3] - n1);
            ps0 += s[nt][0] + s[nt][1];
            ps1 += s[nt][2] + s[nt][3];
        }
        l0 = l0 * corr0 + ps0;
        l1 = l1 * corr1 + ps1;
        #pragma unroll
        for (int i = 0; i < 16; i++) {
            o[i][0] *= corr0; o[i][1] *= corr0;
            o[i][2] *= corr1; o[i][3] *= corr1;
        }

        #pragma unroll
        for (int kc = 0; kc < 4; kc++) {
            uint32_t ph[4], pl[4];
            {
                float p00 = s[2*kc][0],   p01 = s[2*kc][1];
                float p02 = s[2*kc][2],   p03 = s[2*kc][3];
                float p10 = s[2*kc+1][0], p11 = s[2*kc+1][1];
                float p12 = s[2*kc+1][2], p13 = s[2*kc+1][3];
                float h00 = rn_bf16(p00), h01 = rn_bf16(p01);
                float h02 = rn_bf16(p02), h03 = rn_bf16(p03);
                float h10 = rn_bf16(p10), h11 = rn_bf16(p11);
                float h12 = rn_bf16(p12), h13 = rn_bf16(p13);
                ph[0] = pack_bf16(h00, h01);
                ph[1] = pack_bf16(h02, h03);
                ph[2] = pack_bf16(h10, h11);
                ph[3] = pack_bf16(h12, h13);
                pl[0] = pack_bf16(p00 - h00, p01 - h01);
                pl[1] = pack_bf16(p02 - h02, p03 - h03);
                pl[2] = pack_bf16(p10 - h10, p11 - h11);
                pl[3] = pack_bf16(p12 - h12, p13 - h13);
            }
            #pragma unroll
            for (int np = 0; np < 8; np++) {
                uint32_t vh[4], vl[4];
                uint32_t va = sb + 4*FTILE_B +
                    (uint32_t)((kc*16 + (lane & 15))*FS + np*16 + hi8)*2;
                LDM_X4_T(vh, va);
                LDM_X4_T(vl, va + FTILE_B);
                MMA16816(o[2*np],   ph, vh[0], vh[1]);
                MMA16816(o[2*np],   ph, vl[0], vl[1]);
                MMA16816(o[2*np],   pl, vh[0], vh[1]);
                MMA16816(o[2*np+1], ph, vh[2], vh[3]);
                MMA16816(o[2*np+1], ph, vl[2], vl[3]);
                MMA16816(o[2*np+1], pl, vh[2], vh[3]);
            }
        }
    }

    float t0 = l0, t1 = l1;
    t0 += __shfl_xor_sync(0xffffffffu, t0, 1);
    t0 += __shfl_xor_sync(0xffffffffu, t0, 2);
    t1 += __shfl_xor_sync(0xffffffffu, t1, 1);
    t1 += __shfl_xor_sync(0xffffffffu, t1, 2);
    float inv0 = 1.f / t0, inv1 = 1.f / t1;
    int r0 = q0 + w*16 + lr;
    #pragma unroll
    for (int nt = 0; nt < 16; nt++) {
        int c = nt*8 + lc;
        *(float2*)(O + base + (size_t)r0 * NHID + c) =
            make_float2(o[nt][0]*inv0, o[nt][1]*inv0);
        *(float2*)(O + base + (size_t)(r0+8) * NHID + c) =
            make_float2(o[nt][2]*inv1, o[nt][3]*inv1);
    }
}

// ---------------- host launcher ----------------
extern "C" void kernel_launch(void* const* d_in, const int* in_sizes, int n_in,
                              void* d_out, int out_size)
{
    const float* x        = (const float*)d_in[0];
    const float* wq_down  = (const float*)d_in[1];
    const float* wq_up    = (const float*)d_in[2];
    const float* wq_rope  = (const float*)d_in[3];
    const float* wk_rope  = (const float*)d_in[4];
    const float* wkv_down = (const float*)d_in[5];
    const float* wk_up    = (const float*)d_in[6];
    const float* wv_up    = (const float*)d_in[7];
    const float* wo       = (const float*)d_in[8];
    const float* bo       = (const float*)d_in[9];
    float* out = (float*)d_out;

    float *krr, *qcr, *kc, *ctx, *woT, *wosc, *csc;
    cudaGetSymbolAddress((void**)&krr,  g_krr);
    cudaGetSymbolAddress((void**)&qcr,  g_qcr);
    cudaGetSymbolAddress((void**)&kc,   g_kc);
    cudaGetSymbolAddress((void**)&ctx,  g_ctx);
    cudaGetSymbolAddress((void**)&woT,  g_woT);
    cudaGetSymbolAddress((void**)&wosc, g_wosc);
    cudaGetSymbolAddress((void**)&csc,  g_csc);

    int8_t *woq1, *woq2, *cq1, *cq2;
    cudaGetSymbolAddress((void**)&woq1, g_woq1);
    cudaGetSymbolAddress((void**)&woq2, g_woq2);
    cudaGetSymbolAddress((void**)&cq1,  g_cq1);
    cudaGetSymbolAddress((void**)&cq2,  g_cq2);

    bf16 *xs, *wd, *wuq, *wukv, *lat;
    bf16 *Qh, *Ql, *Kh, *Kl, *Vh, *Vl;
    cudaGetSymbolAddress((void**)&xs,   g_xs);
    cudaGetSymbolAddress((void**)&wd,   g_wd_f);
    cudaGetSymbolAddress((void**)&wuq,  g_wuq_f);
    cudaGetSymbolAddress((void**)&wukv, g_wukv_f);
    cudaGetSymbolAddress((void**)&lat,  g_lat_s);
    cudaGetSymbolAddress((void**)&Qh,   g_Qh);
    cudaGetSymbolAddress((void**)&Ql,   g_Ql);
    cudaGetSymbolAddress((void**)&Kh,   g_Kh);
    cudaGetSymbolAddress((void**)&Kl,   g_Kl);
    cudaGetSymbolAddress((void**)&Vh,   g_Vh);
    cudaGetSymbolAddress((void**)&Vl,   g_Vl);

    const size_t XN    = (size_t)NM*NHID;
    const size_t WDF   = (size_t)1024*2048;
    const size_t WUQF  = (size_t)2048*512;
    const size_t WUKVF = (size_t)3072*512;
    const size_t LATN  = (size_t)NM*1024;

    cudaFuncSetAttribute(bgemm_kernel<0>, cudaFuncAttributeMaxDynamicSharedMemorySize, BG_SMEM);
    cudaFuncSetAttribute(bgemm_kernel<2>, cudaFuncAttributeMaxDynamicSharedMemorySize, BG_SMEM);
    cudaFuncSetAttribute(bgemm_kernel<3>, cudaFuncAttributeMaxDynamicSharedMemorySize, BG_SMEM);
    cudaFuncSetAttribute(bgemm_i8_kernel, cudaFuncAttributeMaxDynamicSharedMemorySize, I8_SMEM);
    cudaFuncSetAttribute(flasht_kernel,   cudaFuncAttributeMaxDynamicSharedMemorySize, 6*FTILE_B);

    dim3 thr(256);
    dim3 gthr(128);

    // (1) RoPE LUT
    rope_lut_kernel<<<256, 256>>>();

    // (2) x split (single launch)
    split4_kernel<<<(unsigned)(XN/1024), 256>>>((const float4*)x, (uint32_t*)xs, (uint32_t*)(xs + XN));

    // (3) batched weight transpose-split (6 bf16 weights)
    {
        TAll ta;
        const float* srcs[6] = { wq_down, wkv_down, wq_up, wq_rope, wk_up, wv_up };
        bf16* his[6] = { wd,           wd + 512*2048,
                         wuq,          wuq + 1024*512,
                         wukv,         wukv + 1024*512 };
        bf16* los[6] = { wd + WDF,         wd + WDF + 512*2048,
                         wuq + WUQF,       wuq + WUQF + 1024*512,
                         wukv + WUKVF,     wukv + WUKVF + 1024*512 };
        int Ks[6] = { 2048, 2048, 512, 512, 512, 512 };
        int Ns[6] = { 512, 512, 1024, 1024, 1024, 2048 };
        int total = 0;
        for (int i = 0; i < 6; i++) {
            ta.src[i] = srcs[i]; ta.hi[i] = his[i]; ta.lo[i] = los[i];
            ta.K[i] = Ks[i]; ta.N[i] = Ns[i];
            ta.start[i] = total;
            total += (Ns[i]/32) * (Ks[i]/32);
        }
        ta.start[6] = total;
        tsplit_all_kernel<<<total, dim3(32, 8)>>>(ta);
    }

    // (4) fused down projection -> split bf16 latents
    bgemm_kernel<2><<<dim3(8, 64), gthr, BG_SMEM>>>(
        xs, xs + XN, wd, wd + WDF,
        nullptr, lat, lat + LATN,
        2048, 2048, 0, 1024, 0);

    // (5) wo transpose fp32, (6) wo two-level int8 quant
    ftrans_kernel<<<dim3(64, 64), dim3(32, 8)>>>(wo, woT, 2048, 2048);
    quant_rows2048_kernel<<<2048, 256>>>(woT, woq1, woq2, wosc);

    // (7) tiny rope-key projection
    sgemm_kernel<<<dim3(1, 64), thr>>>(x, wk_rope, krr, 64, 2048);

    // (8) fused up-q: [qc | qr] fp32
    bgemm_kernel<0><<<dim3(16, 64), gthr, BG_SMEM>>>(
        lat, lat + LATN, wuq, wuq + WUQF,
        qcr, nullptr, nullptr,
        1024, 512, 2048, 0, 0);

    // (9) fused up-kv: [kc fp32 | V split bf16]
    bgemm_kernel<3><<<dim3(24, 64), gthr, BG_SMEM>>>(
        lat + 512, lat + LATN + 512, wukv, wukv + WUKVF,
        kc, Vh, Vl,
        1024, 512, 1024, 2048, 1024);

    // (10) merged RoPE + pack Q/K
    pack_qk_kernel<<<(2*NM*NHID)/256, thr>>>();

    // (11) flash attention -> fp32 ctx
    flasht_kernel<<<dim3(NS/64, NH, NB), 128, 6*FTILE_B>>>(Qh, Ql, Kh, Kl, Vh, Vl, ctx);

    // (12) ctx two-level int8 quant
    quant_rows2048_kernel<<<NM, 256>>>(ctx, cq1, cq2, csc);

    // (13) int8 output projection + bias
    bgemm_i8_kernel<<<dim3(16, 64), thr, I8_SMEM>>>(
        cq1, cq2, woq1, woq2, csc, wosc, out, bo, 2048, 2048);
}

// round 11
// speedup vs baseline: 1.4503x; 1.4503x over previous
#include <cuda_runtime.h>
#include <cuda_bf16.h>
#include <cuda_fp16.h>
#include <math.h>
#include <stdint.h>

using bf16 = __nv_bfloat16;

#define NB   4
#define NS   2048
#define NH   16
#define NHD  128
#define NRD  64
#define NLAT 512
#define NHID 2048
#define NM   (NB*NS)

// ---------------- device scratch ----------------
__device__ float g_krr [(size_t)NM*NRD];
__device__ float g_qcr [(size_t)NM*2048];
__device__ float g_kc  [(size_t)NM*1024];
__device__ float g_cs  [NS*32];
__device__ float g_sn  [NS*32];

// bf16 split weights (6) + latents
__device__ bf16 g_xs    [2][(size_t)NM*NHID];
__device__ bf16 g_wd_f  [2][(size_t)1024*2048];
__device__ bf16 g_wuq_f [2][(size_t)2048*512];
__device__ bf16 g_wukv_f[2][(size_t)3072*512];
__device__ bf16 g_lat_s [2][(size_t)NM*1024];

__device__ bf16 g_Qh[(size_t)NM*NHID];
__device__ bf16 g_Ql[(size_t)NM*NHID];
__device__ bf16 g_Kh[(size_t)NM*NHID];
__device__ bf16 g_Kl[(size_t)NM*NHID];
__device__ bf16 g_Vh[(size_t)NM*NHID];
__device__ bf16 g_Vl[(size_t)NM*NHID];

// fp16 out-projection path
__device__ __half g_woh[(size_t)2048*2048];    // wo transposed [N,K] fp16
__device__ __half g_ch [(size_t)NM*NHID];      // ctx hi fp16
__device__ __half g_cl [(size_t)NM*NHID];      // ctx lo fp16

// ---------------- PTX helpers ----------------
__device__ __forceinline__ void cp16(uint32_t s, const void* g) {
    asm volatile("cp.async.cg.shared.global [%0], [%1], 16;\n" :: "r"(s), "l"(g));
}

#define LDM_X4(R, addr) \
    asm volatile("ldmatrix.sync.aligned.m8n8.x4.shared.b16 {%0,%1,%2,%3}, [%4];" \
        : "=r"(R[0]), "=r"(R[1]), "=r"(R[2]), "=r"(R[3]) : "r"(addr))
#define LDM_X4_T(R, addr) \
    asm volatile("ldmatrix.sync.aligned.m8n8.x4.trans.shared.b16 {%0,%1,%2,%3}, [%4];" \
        : "=r"(R[0]), "=r"(R[1]), "=r"(R[2]), "=r"(R[3]) : "r"(addr))
#define MMA16816(D, A, B0, B1) \
    asm volatile("mma.sync.aligned.m16n8k16.row.col.f32.bf16.bf16.f32 " \
        "{%0,%1,%2,%3}, {%4,%5,%6,%7}, {%8,%9}, {%0,%1,%2,%3};" \
        : "+f"(D[0]), "+f"(D[1]), "+f"(D[2]), "+f"(D[3]) \
        : "r"(A[0]), "r"(A[1]), "r"(A[2]), "r"(A[3]), "r"(B0), "r"(B1))
#define MMAH16816(D, A, B0, B1) \
    asm volatile("mma.sync.aligned.m16n8k16.row.col.f32.f16.f16.f32 " \
        "{%0,%1,%2,%3}, {%4,%5,%6,%7}, {%8,%9}, {%0,%1,%2,%3};" \
        : "+f"(D[0]), "+f"(D[1]), "+f"(D[2]), "+f"(D[3]) \
        : "r"(A[0]), "r"(A[1]), "r"(A[2]), "r"(A[3]), "r"(B0), "r"(B1))

__device__ __forceinline__ uint32_t pack_bf16(float a, float b) {
    uint32_t r;
    asm("cvt.rn.bf16x2.f32 %0, %1, %2;" : "=r"(r) : "f"(b), "f"(a));
    return r;
}
__device__ __forceinline__ float rn_bf16(float f) {
    return __bfloat162float(__float2bfloat16(f));
}
__device__ __forceinline__ uint32_t pack_f16(float a, float b) {   // lo=h(a), hi=h(b)
    uint32_t r;
    asm("cvt.rn.f16x2.f32 %0, %1, %2;" : "=r"(r) : "f"(b), "f"(a));
    return r;
}
__device__ __forceinline__ float rn_f16(float f) {
    return __half2float(__float2half_rn(f));
}

// ---------------- splits ----------------
__global__ void split4_kernel(const float4* __restrict__ in,
                              uint32_t* __restrict__ hi, uint32_t* __restrict__ lo)
{
    size_t i = (size_t)blockIdx.x * blockDim.x + threadIdx.x;
    float4 f = in[i];
    float hx = rn_bf16(f.x), hy = rn_bf16(f.y), hz = rn_bf16(f.z), hw = rn_bf16(f.w);
    hi[2*i]   = pack_bf16(hx, hy);
    hi[2*i+1] = pack_bf16(hz, hw);
    lo[2*i]   = pack_bf16(f.x - hx, f.y - hy);
    lo[2*i+1] = pack_bf16(f.z - hz, f.w - hw);
}

// batched transpose + split for 6 bf16 weights
struct TAll {
    const float* src[6];
    bf16* hi[6];
    bf16* lo[6];
    int   K[6];
    int   N[6];
    int   start[7];
};

__global__ void tsplit_all_kernel(TAll ta)
{
    __shared__ float t[32][33];
    int bid = blockIdx.x;
    int i = 0;
    #pragma unroll
    for (int j = 1; j < 6; j++) if (bid >= ta.start[j]) i = j;
    int lb = bid - ta.start[i];
    int K = ta.K[i], N = ta.N[i];
    int nbx = N >> 5;
    int n0 = (lb % nbx) * 32, k0 = (lb / nbx) * 32;
    const float* src = ta.src[i];
    bf16* hi = ta.hi[i];
    bf16* lo = ta.lo[i];

    int tx = threadIdx.x, ty = threadIdx.y;
    #pragma unroll
    for (int j = 0; j < 4; j++)
        t[ty + j*8][tx] = src[(size_t)(k0 + ty + j*8) * N + n0 + tx];
    __syncthreads();
    #pragma unroll
    for (int j = 0; j < 4; j++) {
        float f = t[tx][ty + j*8];
        bf16 h = __float2bfloat16(f);
        size_t o = (size_t)(n0 + ty + j*8) * K + k0 + tx;
        hi[o] = h;
        lo[o] = __float2bfloat16(f - __bfloat162float(h));
    }
}

// wo transpose fp32 -> fp16 [N,K]
__global__ void wtrans_h_kernel(const float* __restrict__ in, __half* __restrict__ out,
                                int K, int N)
{
    __shared__ float t[32][33];
    int n0 = blockIdx.x * 32, k0 = blockIdx.y * 32;
    int tx = threadIdx.x, ty = threadIdx.y;
    #pragma unroll
    for (int j = 0; j < 4; j++)
        t[ty + j*8][tx] = in[(size_t)(k0 + ty + j*8) * N + n0 + tx];
    __syncthreads();
    #pragma unroll
    for (int j = 0; j < 4; j++)
        out[(size_t)(n0 + ty + j*8) * K + k0 + tx] = __float2half_rn(t[tx][ty + j*8]);
}

// ---------------- mma.sync split-bf16 GEMM ----------------
#define SA_ELEMS (128*40)
#define BG_SMEM ((8*SA_ELEMS)*2)

__device__ __forceinline__ void bgemm_fill(
    uint32_t smem_base, int buf,
    const bf16* __restrict__ Ah, const bf16* __restrict__ Al,
    const bf16* __restrict__ Bh, const bf16* __restrict__ Bl,
    int tid, int row0, int col0, int k0, int lda, int ldb)
{
    #pragma unroll
    for (int j = 0; j < 4; j++) {
        int chunk = tid + 128*j;
        int r = chunk >> 2, cc = chunk & 3;
        size_t ga = (size_t)(row0 + r) * lda + k0 + cc*8;
        size_t gb = (size_t)(col0 + r) * ldb + k0 + cc*8;
        uint32_t off = (uint32_t)(r*40 + cc*8)*2;
        cp16(smem_base + (buf*2+0)*SA_ELEMS*2 + off, Ah + ga);
        cp16(smem_base + (buf*2+1)*SA_ELEMS*2 + off, Al + ga);
        cp16(smem_base + (4 + buf*2+0)*SA_ELEMS*2 + off, Bh + gb);
        cp16(smem_base + (4 + buf*2+1)*SA_ELEMS*2 + off, Bl + gb);
    }
    asm volatile("cp.async.commit_group;");
}

// EPI 0: fp32 (stride Nc). 2: bf16 hi/lo (stride Ns). 3: mixed at boundary.
template<int EPI>
__global__ void __launch_bounds__(128)
bgemm_kernel(const bf16* __restrict__ Ah, const bf16* __restrict__ Al,
             const bf16* __restrict__ Bh, const bf16* __restrict__ Bl,
             float* __restrict__ C, bf16* __restrict__ Chi, bf16* __restrict__ Clo,
             int lda, int K, int Nc, int Ns, int boundary)
{
    extern __shared__ bf16 smem_dyn[];
    const uint32_t smem_base = (uint32_t)__cvta_generic_to_shared(smem_dyn);

    const int tid  = threadIdx.x;
    const int lane = tid & 31;
    const int wid  = tid >> 5;
    const int m0w  = (wid >> 1) * 64;
    const int n0w  = (wid & 1) * 64;
    const int row0 = blockIdx.y * 128;
    const int col0 = blockIdx.x * 128;

    float acc[4][8][4];
    #pragma unroll
    for (int i = 0; i < 4; i++)
        #pragma unroll
        for (int j = 0; j < 8; j++)
            #pragma unroll
            for (int k = 0; k < 4; k++) acc[i][j][k] = 0.f;

    const int niter = K >> 5;
    bgemm_fill(smem_base, 0, Ah, Al, Bh, Bl, tid, row0, col0, 0, lda, K);

    const int aRow  = m0w + (lane & 15);
    const int aCol8 = 8 * (lane >> 4);
    const int bRow  = n0w + (lane & 15);

    for (int it = 0; it < niter; ++it) {
        const int buf = it & 1;
        if (it + 1 < niter) {
            bgemm_fill(smem_base, buf ^ 1, Ah, Al, Bh, Bl, tid, row0, col0, (it+1)*32, lda, K);
            asm volatile("cp.async.wait_group 1;");
        } else {
            asm volatile("cp.async.wait_group 0;");
        }
        __syncthreads();

        #pragma unroll
        for (int sub = 0; sub < 32; sub += 16) {
            uint32_t ah[4][4], al[4][4];
            #pragma unroll
            for (int mt = 0; mt < 4; mt++) {
                uint32_t addr = smem_base +
                    (uint32_t)((buf*2)*SA_ELEMS + (aRow + mt*16)*40 + sub + aCol8)*2;
                LDM_X4(ah[mt], addr);
                LDM_X4(al[mt], addr + SA_ELEMS*2);
            }
            #pragma unroll
            for (int ng = 0; ng < 4; ng++) {
                uint32_t bh[4], bl[4];
                uint32_t addr = smem_base +
                    (uint32_t)((4 + buf*2)*SA_ELEMS + (bRow + ng*16)*40 + sub + aCol8)*2;
                LDM_X4(bh, addr);
                LDM_X4(bl, addr + SA_ELEMS*2);
                #pragma unroll
                for (int half = 0; half < 2; half++) {
                    uint32_t b0h = bh[half], b1h = bh[half+2];
                    uint32_t b0l = bl[half], b1l = bl[half+2];
                    int nt = ng*2 + half;
                    #pragma unroll
                    for (int mt = 0; mt < 4; mt++) {
                        MMA16816(acc[mt][nt], ah[mt], b0h, b1h);
                        MMA16816(acc[mt][nt], ah[mt], b0l, b1l);
                        MMA16816(acc[mt][nt], al[mt], b0h, b1h);
                    }
                }
            }
        }
        __syncthreads();
    }

    const bool fp32_mode = (EPI == 0) || (EPI == 3 && col0 < boundary);
    #pragma unroll
    for (int mt = 0; mt < 4; mt++) {
        #pragma unroll
        for (int nt = 0; nt < 8; nt++) {
            int r  = row0 + m0w + mt*16 + (lane >> 2);
            int cc = col0 + n0w + nt*8 + (lane & 3)*2;
            float a0 = acc[mt][nt][0], a1 = acc[mt][nt][1];
            float a2 = acc[mt][nt][2], a3 = acc[mt][nt][3];
            if (fp32_mode) {
                *(float2*)(C + (size_t)r     * Nc + cc) = make_float2(a0, a1);
                *(float2*)(C + (size_t)(r+8) * Nc + cc) = make_float2(a2, a3);
            } else {
                int cs = (EPI == 3) ? (cc - boundary) : cc;
                float h0 = rn_bf16(a0), h1 = rn_bf16(a1);
                float h2 = rn_bf16(a2), h3 = rn_bf16(a3);
                *(uint32_t*)(Chi + (size_t)r     * Ns + cs) = pack_bf16(h0, h1);
                *(uint32_t*)(Clo + (size_t)r     * Ns + cs) = pack_bf16(a0 - h0, a1 - h1);
                *(uint32_t*)(Chi + (size_t)(r+8) * Ns + cs) = pack_bf16(h2, h3);
                *(uint32_t*)(Clo + (size_t)(r+8) * Ns + cs) = pack_bf16(a2 - h2, a3 - h3);
            }
        }
    }
}

// ---------------- asym fp16 GEMM (out projection): A hi/lo fp16, B single fp16 ----------------
// C[M,N] = A@Bt^T + bias. 2 MMAs per k16. 3 tiles per buffer.
#define HG_SMEM (6*SA_ELEMS*2)   // 61440 B

__device__ __forceinline__ void hgemm_fill(
    uint32_t sb, int buf,
    const __half* __restrict__ Ah, const __half* __restrict__ Al,
    const __half* __restrict__ B,
    int tid, int row0, int col0, int k0, int K)
{
    #pragma unroll
    for (int j = 0; j < 4; j++) {
        int chunk = tid + 128*j;
        int r = chunk >> 2, cc = chunk & 3;
        size_t ga = (size_t)(row0 + r) * K + k0 + cc*8;
        size_t gb = (size_t)(col0 + r) * K + k0 + cc*8;
        uint32_t off = (uint32_t)(r*40 + cc*8)*2;
        cp16(sb + (buf*3+0)*SA_ELEMS*2 + off, Ah + ga);
        cp16(sb + (buf*3+1)*SA_ELEMS*2 + off, Al + ga);
        cp16(sb + (buf*3+2)*SA_ELEMS*2 + off, B + gb);
    }
    asm volatile("cp.async.commit_group;");
}

__global__ void __launch_bounds__(128)
hgemm2_kernel(const __half* __restrict__ Ah, const __half* __restrict__ Al,
              const __half* __restrict__ B,
              float* __restrict__ C, const float* __restrict__ bias,
              int K, int N)
{
    extern __shared__ __half hsm[];
    const uint32_t sb = (uint32_t)__cvta_generic_to_shared(hsm);

    const int tid  = threadIdx.x;
    const int lane = tid & 31;
    const int wid  = tid >> 5;
    const int m0w  = (wid >> 1) * 64;
    const int n0w  = (wid & 1) * 64;
    const int row0 = blockIdx.y * 128;
    const int col0 = blockIdx.x * 128;

    float acc[4][8][4];
    #pragma unroll
    for (int i = 0; i < 4; i++)
        #pragma unroll
        for (int j = 0; j < 8; j++)
            #pragma unroll
            for (int k = 0; k < 4; k++) acc[i][j][k] = 0.f;

    const int niter = K >> 5;
    hgemm_fill(sb, 0, Ah, Al, B, tid, row0, col0, 0, K);

    const int aRow  = m0w + (lane & 15);
    const int aCol8 = 8 * (lane >> 4);
    const int bRow  = n0w + (lane & 15);

    for (int it = 0; it < niter; ++it) {
        const int buf = it & 1;
        if (it + 1 < niter) {
            hgemm_fill(sb, buf ^ 1, Ah, Al, B, tid, row0, col0, (it+1)*32, K);
            asm volatile("cp.async.wait_group 1;");
        } else {
            asm volatile("cp.async.wait_group 0;");
        }
        __syncthreads();

        #pragma unroll
        for (int sub = 0; sub < 32; sub += 16) {
            uint32_t ah[4][4], al[4][4];
            #pragma unroll
            for (int mt = 0; mt < 4; mt++) {
                uint32_t addr = sb +
                    (uint32_t)((buf*3)*SA_ELEMS + (aRow + mt*16)*40 + sub + aCol8)*2;
                LDM_X4(ah[mt], addr);
                LDM_X4(al[mt], addr + SA_ELEMS*2);
            }
            #pragma unroll
            for (int ng = 0; ng < 4; ng++) {
                uint32_t bb[4];
                uint32_t addr = sb +
                    (uint32_t)((buf*3+2)*SA_ELEMS + (bRow + ng*16)*40 + sub + aCol8)*2;
                LDM_X4(bb, addr);
                #pragma unroll
                for (int half = 0; half < 2; half++) {
                    uint32_t b0 = bb[half], b1 = bb[half+2];
                    int nt = ng*2 + half;
                    #pragma unroll
                    for (int mt = 0; mt < 4; mt++) {
                        MMAH16816(acc[mt][nt], ah[mt], b0, b1);
                        MMAH16816(acc[mt][nt], al[mt], b0, b1);
                    }
                }
            }
        }
        __syncthreads();
    }

    #pragma unroll
    for (int mt = 0; mt < 4; mt++) {
        #pragma unroll
        for (int nt = 0; nt < 8; nt++) {
            int r  = row0 + m0w + mt*16 + (lane >> 2);
            int cc = col0 + n0w + nt*8 + (lane & 3)*2;
            float b0 = bias[cc], b1 = bias[cc+1];
            *(float2*)(C + (size_t)r     * N + cc) =
                make_float2(acc[mt][nt][0] + b0, acc[mt][nt][1] + b1);
            *(float2*)(C + (size_t)(r+8) * N + cc) =
                make_float2(acc[mt][nt][2] + b0, acc[mt][nt][3] + b1);
        }
    }
}

// ---------------- fp32 SGEMM (tiny wk_rope, N=64) ----------------
__global__ void __launch_bounds__(256)
sgemm_kernel(const float* __restrict__ A, const float* __restrict__ W,
             float* __restrict__ C, int N, int K)
{
    __shared__ float As[16][132];
    __shared__ float Bs[16][128];

    const int tid = threadIdx.x;
    const int tx = tid & 15, ty = tid >> 4;
    const int bx = blockIdx.x, by = blockIdx.y;

    const int a_r = tid >> 2;
    const int a_c = (tid & 3) << 2;
    const int b_r = tid >> 5;
    const int b_c = (tid & 31) << 2;

    const float* Ab = A + (size_t)by * 128 * K;

    float acc[8][8];
    #pragma unroll
    for (int i = 0; i < 8; i++)
        #pragma unroll
        for (int j = 0; j < 8; j++) acc[i][j] = 0.f;

    for (int k0 = 0; k0 < K; k0 += 16) {
        #pragma unroll
        for (int u = 0; u < 2; u++) {
            int r = a_r + u*64;
            float4 v = *(const float4*)(Ab + (size_t)r * K + (k0 + a_c));
            As[a_c+0][r] = v.x; As[a_c+1][r] = v.y;
            As[a_c+2][r] = v.z; As[a_c+3][r] = v.w;
        }
        #pragma unroll
        for (int u = 0; u < 2; u++) {
            int r = b_r + u*8;
            int col = bx*128 + b_c;
            float4 v = make_float4(0.f, 0.f, 0.f, 0.f);
            if (col < N) v = *(const float4*)(W + (size_t)(k0 + r) * N + col);
            *(float4*)&Bs[r][b_c] = v;
        }
        __syncthreads();
        #pragma unroll
        for (int k = 0; k < 16; k++) {
            float a[8], b[8];
            *(float4*)&a[0] = *(const float4*)&As[k][ty*8];
            *(float4*)&a[4] = *(const float4*)&As[k][ty*8+4];
            *(float4*)&b[0] = *(const float4*)&Bs[k][tx*8];
            *(float4*)&b[4] = *(const float4*)&Bs[k][tx*8+4];
            #pragma unroll
            for (int i = 0; i < 8; i++)
                #pragma unroll
                for (int j = 0; j < 8; j++)
                    acc[i][j] = fmaf(a[i], b[j], acc[i][j]);
        }
        __syncthreads();
    }

    const int row0 = by*128 + ty*8;
    const int col0 = bx*128 + tx*8;
    #pragma unroll
    for (int i = 0; i < 8; i++) {
        #pragma unroll
        for (int j = 0; j < 8; j += 4) {
            int col = col0 + j;
            if (col < N) {
                float4 v = make_float4(acc[i][j], acc[i][j+1], acc[i][j+2], acc[i][j+3]);
                *(float4*)(C + (size_t)(row0+i)*N + col) = v;
            }
        }
    }
}

// ---------------- RoPE LUT + merged pack ----------------
__global__ void rope_lut_kernel()
{
    int idx = blockIdx.x * blockDim.x + threadIdx.x;
    int pos = idx >> 5, fi = idx & 31;
    float inv = powf(10000.f, -(float)(2*fi) / 64.f);
    float ang = (float)pos * inv;
    float s, c;
    sincosf(ang, &s, &c);
    g_cs[idx] = c;
    g_sn[idx] = s;
}

__global__ void pack_qk_kernel()
{
    int gidx = blockIdx.x * blockDim.x + threadIdx.x;
    const int TOT = NM * NHID;
    bool isK = gidx >= TOT;
    int idx = isK ? (gidx - TOT) : gidx;
    int row = idx >> 11;
    int c   = idx & (NHID - 1);
    int h = c >> 7, d = c & 127;
    float out;
    if (!isK) {
        if (d < 64) {
            out = g_qcr[(size_t)row*2048 + h*64 + d];
        } else {
            int dd = d - 64;
            const float* qr = g_qcr + (size_t)row*2048 + 1024 + h*64;
            int pos = row & (NS - 1);
            float cs = g_cs[pos*32 + (dd & 31)], sn = g_sn[pos*32 + (dd & 31)];
            float v = qr[dd];
            float w = (dd < 32) ? -qr[dd + 32] : qr[dd - 32];
            out = v * cs + w * sn;
        }
        out *= 0.08838834764831845f;
        bf16 hi = __float2bfloat16(out);
        g_Qh[idx] = hi;
        g_Ql[idx] = __float2bfloat16(out - __bfloat162float(hi));
    } else {
        if (d < 64) {
            out = g_kc[(size_t)row*1024 + h*64 + d];
        } else {
            int dd = d - 64;
            const float* kr = g_krr + (size_t)row*NRD;
            int pos = row & (NS - 1);
            float cs = g_cs[pos*32 + (dd & 31)], sn = g_sn[pos*32 + (dd & 31)];
            float v = kr[dd];
            float w = (dd < 32) ? -kr[dd + 32] : kr[dd - 32];
            out = v * cs + w * sn;
        }
        bf16 hi = __float2bfloat16(out);
        g_Kh[idx] = hi;
        g_Kl[idx] = __float2bfloat16(out - __bfloat162float(hi));
    }
}

// ---------------- mma.sync split-bf16 flash attention (fp16 hi/lo ctx out) ----------------
#define FS 136
#define FTILE_B (64*FS*2)

__global__ void __launch_bounds__(128)
flasht_kernel(const bf16* __restrict__ Qh, const bf16* __restrict__ Ql,
              const bf16* __restrict__ Kh, const bf16* __restrict__ Kl,
              const bf16* __restrict__ Vh, const bf16* __restrict__ Vl,
              __half* __restrict__ Ohi, __half* __restrict__ Olo)
{
    extern __shared__ bf16 fsm[];
    const uint32_t sb = (uint32_t)__cvta_generic_to_shared(fsm);

    const int tid = threadIdx.x;
    const int lane = tid & 31;
    const int w = tid >> 5;
    const int lr = lane >> 2;
    const int lc = (lane & 3) * 2;
    const int h = blockIdx.y, b = blockIdx.z;
    const int q0 = blockIdx.x * 64;
    const size_t base = ((size_t)b * NS) * NHID + (size_t)h * NHD;

    for (int i = tid; i < 1024; i += 128) {
        int r = i >> 4, c = (i & 15) << 3;
        uint32_t so = (uint32_t)(r*FS + c) * 2;
        size_t go = base + (size_t)(q0 + r) * NHID + c;
        cp16(sb + 0*FTILE_B + so, Qh + go);
        cp16(sb + 1*FTILE_B + so, Ql + go);
    }
    asm volatile("cp.async.commit_group;");

    float m0 = -1e30f, m1 = -1e30f, l0 = 0.f, l1 = 0.f;
    float o[16][4];
    #pragma unroll
    for (int i = 0; i < 16; i++)
        #pragma unroll
        for (int j = 0; j < 4; j++) o[i][j] = 0.f;

    const int aRow = w*16 + (lane & 15);
    const int hi8  = 8 * (lane >> 4);
    const int ntiles = blockIdx.x + 1;

    for (int t = 0; t < ntiles; t++) {
        const int k0 = t * 64;
        if (t) __syncthreads();
        for (int i = tid; i < 1024; i += 128) {
            int r = i >> 4, c = (i & 15) << 3;
            uint32_t so = (uint32_t)(r*FS + c) * 2;
            size_t go = base + (size_t)(k0 + r) * NHID + c;
            cp16(sb + 2*FTILE_B + so, Kh + go);
            cp16(sb + 3*FTILE_B + so, Kl + go);
            cp16(sb + 4*FTILE_B + so, Vh + go);
            cp16(sb + 5*FTILE_B + so, Vl + go);
        }
        asm volatile("cp.async.commit_group;");
        asm volatile("cp.async.wait_group 0;");
        __syncthreads();

        float s[8][4];
        #pragma unroll
        for (int i = 0; i < 8; i++)
            #pragma unroll
            for (int j = 0; j < 4; j++) s[i][j] = 0.f;

        #pragma unroll
        for (int kc = 0; kc < 8; kc++) {
            uint32_t qh[4], ql[4];
            uint32_t qa = sb + (uint32_t)(aRow*FS + kc*16 + hi8)*2;
            LDM_X4(qh, qa);
            LDM_X4(ql, qa + FTILE_B);
            #pragma unroll
            for (int g = 0; g < 4; g++) {
                uint32_t kh[4], kl[4];
                uint32_t ka = sb + 2*FTILE_B + (uint32_t)((g*16 + (lane & 15))*FS + kc*16 + hi8)*2;
                LDM_X4(kh, ka);
                LDM_X4(kl, ka + FTILE_B);
                MMA16816(s[2*g],   qh, kh[0], kh[2]);
                MMA16816(s[2*g],   qh, kl[0], kl[2]);
                MMA16816(s[2*g],   ql, kh[0], kh[2]);
                MMA16816(s[2*g+1], qh, kh[1], kh[3]);
                MMA16816(s[2*g+1], qh, kl[1], kl[3]);
                MMA16816(s[2*g+1], ql, kh[1], kh[3]);
            }
        }

        if (t == blockIdx.x) {
            int r0 = q0 + w*16 + lr, r1 = r0 + 8;
            #pragma unroll
            for (int nt = 0; nt < 8; nt++) {
                int c = k0 + nt*8 + lc;
                if (c     > r0) s[nt][0] = -1e30f;
                if (c + 1 > r0) s[nt][1] = -1e30f;
                if (c     > r1) s[nt][2] = -1e30f;
                if (c + 1 > r1) s[nt][3] = -1e30f;
            }
        }

        float mt0 = -1e30f, mt1 = -1e30f;
        #pragma unroll
        for (int nt = 0; nt < 8; nt++) {
            mt0 = fmaxf(mt0, fmaxf(s[nt][0], s[nt][1]));
            mt1 = fmaxf(mt1, fmaxf(s[nt][2], s[nt][3]));
        }
        mt0 = fmaxf(mt0, __shfl_xor_sync(0xffffffffu, mt0, 1));
        mt0 = fmaxf(mt0, __shfl_xor_sync(0xffffffffu, mt0, 2));
        mt1 = fmaxf(mt1, __shfl_xor_sync(0xffffffffu, mt1, 1));
        mt1 = fmaxf(mt1, __shfl_xor_sync(0xffffffffu, mt1, 2));
        float n0 = fmaxf(m0, mt0), n1 = fmaxf(m1, mt1);
        float corr0 = __expf(m0 - n0), corr1 = __expf(m1 - n1);
        m0 = n0; m1 = n1;

        float ps0 = 0.f, ps1 = 0.f;
        #pragma unroll
        for (int nt = 0; nt < 8; nt++) {
            s[nt][0] = __expf(s[nt][0] - n0);
            s[nt][1] = __expf(s[nt][1] - n0);
            s[nt][2] = __expf(s[nt][2] - n1);
            s[nt][3] = __expf(s[nt][3] - n1);
            ps0 += s[nt][0] + s[nt][1];
            ps1 += s[nt][2] + s[nt][3];
        }
        l0 = l0 * corr0 + ps0;
        l1 = l1 * corr1 + ps1;
        #pragma unroll
        for (int i = 0; i < 16; i++) {
            o[i][0] *= corr0; o[i][1] *= corr0;
            o[i][2] *= corr1; o[i][3] *= corr1;
        }

        #pragma unroll
        for (int kc = 0; kc < 4; kc++) {
            uint32_t ph[4], pl[4];
            {
                float p00 = s[2*kc][0],   p01 = s[2*kc][1];
                float p02 = s[2*kc][2],   p03 = s[2*kc][3];
                float p10 = s[2*kc+1][0], p11 = s[2*kc+1][1];
                float p12 = s[2*kc+1][2], p13 = s[2*kc+1][3];
                float h00 = rn_bf16(p00), h01 = rn_bf16(p01);
                float h02 = rn_bf16(p02), h03 = rn_bf16(p03);
                float h10 = rn_bf16(p10), h11 = rn_bf16(p11);
                float h12 = rn_bf16(p12), h13 = rn_bf16(p13);
                ph[0] = pack_bf16(h00, h01);
                ph[1] = pack_bf16(h02, h03);
                ph[2] = pack_bf16(h10, h11);
                ph[3] = pack_bf16(h12, h13);
                pl[0] = pack_bf16(p00 - h00, p01 - h01);
                pl[1] = pack_bf16(p02 - h02, p03 - h03);
                pl[2] = pack_bf16(p10 - h10, p11 - h11);
                pl[3] = pack_bf16(p12 - h12, p13 - h13);
            }
            #pragma unroll
            for (int np = 0; np < 8; np++) {
                uint32_t vh[4], vl[4];
                uint32_t va = sb + 4*FTILE_B +
                    (uint32_t)((kc*16 + (lane & 15))*FS + np*16 + hi8)*2;
                LDM_X4_T(vh, va);
                LDM_X4_T(vl, va + FTILE_B);
                MMA16816(o[2*np],   ph, vh[0], vh[1]);
                MMA16816(o[2*np],   ph, vl[0], vl[1]);
                MMA16816(o[2*np],   pl, vh[0], vh[1]);
                MMA16816(o[2*np+1], ph, vh[2], vh[3]);
                MMA16816(o[2*np+1], ph, vl[2], vl[3]);
                MMA16816(o[2*np+1], pl, vh[2], vh[3]);
            }
        }
    }

    float t0 = l0, t1 = l1;
    t0 += __shfl_xor_sync(0xffffffffu, t0, 1);
    t0 += __shfl_xor_sync(0xffffffffu, t0, 2);
    t1 += __shfl_xor_sync(0xffffffffu, t1, 1);
    t1 += __shfl_xor_sync(0xffffffffu, t1, 2);
    float inv0 = 1.f / t0, inv1 = 1.f / t1;
    int r0 = q0 + w*16 + lr;
    #pragma unroll
    for (int nt = 0; nt < 16; nt++) {
        int c = nt*8 + lc;
        float v0 = o[nt][0]*inv0, v1 = o[nt][1]*inv0;
        float v2 = o[nt][2]*inv1, v3 = o[nt][3]*inv1;
        float h0 = rn_f16(v0), h1 = rn_f16(v1);
        float h2 = rn_f16(v2), h3 = rn_f16(v3);
        size_t off0 = base + (size_t)r0 * NHID + c;
        size_t off1 = base + (size_t)(r0+8) * NHID + c;
        *(uint32_t*)(Ohi + off0) = pack_f16(h0, h1);
        *(uint32_t*)(Olo + off0) = pack_f16(v0 - h0, v1 - h1);
        *(uint32_t*)(Ohi + off1) = pack_f16(h2, h3);
        *(uint32_t*)(Olo + off1) = pack_f16(v2 - h2, v3 - h3);
    }
}

// ---------------- host launcher ----------------
extern "C" void kernel_launch(void* const* d_in, const int* in_sizes, int n_in,
                              void* d_out, int out_size)
{
    const float* x        = (const float*)d_in[0];
    const float* wq_down  = (const float*)d_in[1];
    const float* wq_up    = (const float*)d_in[2];
    const float* wq_rope  = (const float*)d_in[3];
    const float* wk_rope  = (const float*)d_in[4];
    const float* wkv_down = (const float*)d_in[5];
    const float* wk_up    = (const float*)d_in[6];
    const float* wv_up    = (const float*)d_in[7];
    const float* wo       = (const float*)d_in[8];
    const float* bo       = (const float*)d_in[9];
    float* out = (float*)d_out;

    float *krr, *qcr, *kc;
    cudaGetSymbolAddress((void**)&krr, g_krr);
    cudaGetSymbolAddress((void**)&qcr, g_qcr);
    cudaGetSymbolAddress((void**)&kc,  g_kc);

    bf16 *xs, *wd, *wuq, *wukv, *lat;
    bf16 *Qh, *Ql, *Kh, *Kl, *Vh, *Vl;
    cudaGetSymbolAddress((void**)&xs,   g_xs);
    cudaGetSymbolAddress((void**)&wd,   g_wd_f);
    cudaGetSymbolAddress((void**)&wuq,  g_wuq_f);
    cudaGetSymbolAddress((void**)&wukv, g_wukv_f);
    cudaGetSymbolAddress((void**)&lat,  g_lat_s);
    cudaGetSymbolAddress((void**)&Qh,   g_Qh);
    cudaGetSymbolAddress((void**)&Ql,   g_Ql);
    cudaGetSymbolAddress((void**)&Kh,   g_Kh);
    cudaGetSymbolAddress((void**)&Kl,   g_Kl);
    cudaGetSymbolAddress((void**)&Vh,   g_Vh);
    cudaGetSymbolAddress((void**)&Vl,   g_Vl);

    __half *woh, *ch, *cl;
    cudaGetSymbolAddress((void**)&woh, g_woh);
    cudaGetSymbolAddress((void**)&ch,  g_ch);
    cudaGetSymbolAddress((void**)&cl,  g_cl);

    const size_t XN    = (size_t)NM*NHID;
    const size_t WDF   = (size_t)1024*2048;
    const size_t WUQF  = (size_t)2048*512;
    const size_t WUKVF = (size_t)3072*512;
    const size_t LATN  = (size_t)NM*1024;

    cudaFuncSetAttribute(bgemm_kernel<0>, cudaFuncAttributeMaxDynamicSharedMemorySize, BG_SMEM);
    cudaFuncSetAttribute(bgemm_kernel<2>, cudaFuncAttributeMaxDynamicSharedMemorySize, BG_SMEM);
    cudaFuncSetAttribute(bgemm_kernel<3>, cudaFuncAttributeMaxDynamicSharedMemorySize, BG_SMEM);
    cudaFuncSetAttribute(hgemm2_kernel,   cudaFuncAttributeMaxDynamicSharedMemorySize, HG_SMEM);
    cudaFuncSetAttribute(flasht_kernel,   cudaFuncAttributeMaxDynamicSharedMemorySize, 6*FTILE_B);

    dim3 thr(256);
    dim3 gthr(128);

    // (1) RoPE LUT
    rope_lut_kernel<<<256, 256>>>();

    // (2) x split
    split4_kernel<<<(unsigned)(XN/1024), 256>>>((const float4*)x, (uint32_t*)xs, (uint32_t*)(xs + XN));

    // (3) batched weight transpose-split (6 bf16 weights)
    {
        TAll ta;
        const float* srcs[6] = { wq_down, wkv_down, wq_up, wq_rope, wk_up, wv_up };
        bf16* his[6] = { wd,           wd + 512*2048,
                         wuq,          wuq + 1024*512,
                         wukv,         wukv + 1024*512 };
        bf16* los[6] = { wd + WDF,         wd + WDF + 512*2048,
                         wuq + WUQF,       wuq + WUQF + 1024*512,
                         wukv + WUKVF,     wukv + WUKVF + 1024*512 };
        int Ks[6] = { 2048, 2048, 512, 512, 512, 512 };
        int Ns[6] = { 512, 512, 1024, 1024, 1024, 2048 };
        int total = 0;
        for (int i = 0; i < 6; i++) {
            ta.src[i] = srcs[i]; ta.hi[i] = his[i]; ta.lo[i] = los[i];
            ta.K[i] = Ks[i]; ta.N[i] = Ns[i];
            ta.start[i] = total;
            total += (Ns[i]/32) * (Ks[i]/32);
        }
        ta.start[6] = total;
        tsplit_all_kernel<<<total, dim3(32, 8)>>>(ta);
    }

    // (4) wo transpose -> fp16 [N,K]
    wtrans_h_kernel<<<dim3(64, 64), dim3(32, 8)>>>(wo, woh, 2048, 2048);

    // (5) tiny rope-key projection
    sgemm_kernel<<<dim3(1, 64), thr>>>(x, wk_rope, krr, 64, 2048);

    // (6) fused down projection -> split bf16 latents
    bgemm_kernel<2><<<dim3(8, 64), gthr, BG_SMEM>>>(
        xs, xs + XN, wd, wd + WDF,
        nullptr, lat, lat + LATN,
        2048, 2048, 0, 1024, 0);

    // (7) fused up-q: [qc | qr] fp32
    bgemm_kernel<0><<<dim3(16, 64), gthr, BG_SMEM>>>(
        lat, lat + LATN, wuq, wuq + WUQF,
        qcr, nullptr, nullptr,
        1024, 512, 2048, 0, 0);

    // (8) fused up-kv: [kc fp32 | V split bf16]
    bgemm_kernel<3><<<dim3(24, 64), gthr, BG_SMEM>>>(
        lat + 512, lat + LATN + 512, wukv, wukv + WUKVF,
        kc, Vh, Vl,
        1024, 512, 1024, 2048, 1024);

    // (9) merged RoPE + pack Q/K
    pack_qk_kernel<<<(2*NM*NHID)/256, thr>>>();

    // (10) flash attention -> ctx fp16 hi/lo
    flasht_kernel<<<dim3(NS/64, NH, NB), 128, 6*FTILE_B>>>(Qh, Ql, Kh, Kl, Vh, Vl, ch, cl);

    // (11) asym fp16 output projection + bias
    hgemm2_kernel<<<dim3(16, 64), gthr, HG_SMEM>>>(ch, cl, woh, out, bo, 2048, 2048);
}

// round 12
// speedup vs baseline: 1.6714x; 1.1524x over previous
#include <cuda_runtime.h>
#include <cuda_bf16.h>
#include <cuda_fp16.h>
#include <math.h>
#include <stdint.h>

using bf16 = __nv_bfloat16;

#define NB   4
#define NS   2048
#define NH   16
#define NHD  128
#define NRD  64
#define NLAT 512
#define NHID 2048
#define NM   (NB*NS)

// ---------------- device scratch ----------------
__device__ float g_krr [(size_t)NM*NRD];
__device__ float g_qcr [(size_t)NM*2048];
__device__ float g_kc  [(size_t)NM*1024];
__device__ float g_cs  [NS*32];
__device__ float g_sn  [NS*32];

// fp16 operands
__device__ __half g_xs  [2][(size_t)NM*NHID];    // x hi/lo
__device__ __half g_wd  [(size_t)1024*2048];     // [wq_down|wkv_down] T fp16
__device__ __half g_wuq [(size_t)2048*512];      // [wq_up|wq_rope] T fp16
__device__ __half g_wukv[(size_t)3072*512];      // [wk_up|wv_up] T fp16
__device__ __half g_woh [(size_t)2048*2048];     // wo T fp16
__device__ __half g_lat [2][(size_t)NM*1024];    // latents hi/lo fp16
__device__ __half g_V   [(size_t)NM*NHID];       // V single fp16
__device__ __half g_ch  [(size_t)NM*NHID];       // ctx hi fp16
__device__ __half g_cl  [(size_t)NM*NHID];       // ctx lo fp16

// bf16 attention Q/K (score path stays high precision)
__device__ bf16 g_Qh[(size_t)NM*NHID];
__device__ bf16 g_Ql[(size_t)NM*NHID];
__device__ bf16 g_Kh[(size_t)NM*NHID];
__device__ bf16 g_Kl[(size_t)NM*NHID];

// ---------------- PTX helpers ----------------
__device__ __forceinline__ void cp16(uint32_t s, const void* g) {
    asm volatile("cp.async.cg.shared.global [%0], [%1], 16;\n" :: "r"(s), "l"(g));
}

#define LDM_X4(R, addr) \
    asm volatile("ldmatrix.sync.aligned.m8n8.x4.shared.b16 {%0,%1,%2,%3}, [%4];" \
        : "=r"(R[0]), "=r"(R[1]), "=r"(R[2]), "=r"(R[3]) : "r"(addr))
#define LDM_X4_T(R, addr) \
    asm volatile("ldmatrix.sync.aligned.m8n8.x4.trans.shared.b16 {%0,%1,%2,%3}, [%4];" \
        : "=r"(R[0]), "=r"(R[1]), "=r"(R[2]), "=r"(R[3]) : "r"(addr))
#define MMA16816(D, A, B0, B1) \
    asm volatile("mma.sync.aligned.m16n8k16.row.col.f32.bf16.bf16.f32 " \
        "{%0,%1,%2,%3}, {%4,%5,%6,%7}, {%8,%9}, {%0,%1,%2,%3};" \
        : "+f"(D[0]), "+f"(D[1]), "+f"(D[2]), "+f"(D[3]) \
        : "r"(A[0]), "r"(A[1]), "r"(A[2]), "r"(A[3]), "r"(B0), "r"(B1))
#define MMAH16816(D, A, B0, B1) \
    asm volatile("mma.sync.aligned.m16n8k16.row.col.f32.f16.f16.f32 " \
        "{%0,%1,%2,%3}, {%4,%5,%6,%7}, {%8,%9}, {%0,%1,%2,%3};" \
        : "+f"(D[0]), "+f"(D[1]), "+f"(D[2]), "+f"(D[3]) \
        : "r"(A[0]), "r"(A[1]), "r"(A[2]), "r"(A[3]), "r"(B0), "r"(B1))

__device__ __forceinline__ uint32_t pack_bf16(float a, float b) {
    uint32_t r;
    asm("cvt.rn.bf16x2.f32 %0, %1, %2;" : "=r"(r) : "f"(b), "f"(a));
    return r;
}
__device__ __forceinline__ float rn_bf16(float f) {
    return __bfloat162float(__float2bfloat16(f));
}
__device__ __forceinline__ uint32_t pack_f16(float a, float b) {
    uint32_t r;
    asm("cvt.rn.f16x2.f32 %0, %1, %2;" : "=r"(r) : "f"(b), "f"(a));
    return r;
}
__device__ __forceinline__ float rn_f16(float f) {
    return __half2float(__float2half_rn(f));
}

// ---------------- x split fp32 -> fp16 hi/lo ----------------
__global__ void split4h_kernel(const float4* __restrict__ in,
                               uint32_t* __restrict__ hi, uint32_t* __restrict__ lo)
{
    size_t i = (size_t)blockIdx.x * blockDim.x + threadIdx.x;
    float4 f = in[i];
    float hx = rn_f16(f.x), hy = rn_f16(f.y), hz = rn_f16(f.z), hw = rn_f16(f.w);
    hi[2*i]   = pack_f16(hx, hy);
    hi[2*i+1] = pack_f16(hz, hw);
    lo[2*i]   = pack_f16(f.x - hx, f.y - hy);
    lo[2*i+1] = pack_f16(f.z - hz, f.w - hw);
}

// batched transpose fp32 [K,N] -> fp16 [N,K], 7 weights in one launch
struct TAll {
    const float* src[7];
    __half* dst[7];
    int K[7];
    int N[7];
    int start[8];
};

__global__ void wtrans_all_kernel(TAll ta)
{
    __shared__ float t[32][33];
    int bid = blockIdx.x;
    int i = 0;
    #pragma unroll
    for (int j = 1; j < 7; j++) if (bid >= ta.start[j]) i = j;
    int lb = bid - ta.start[i];
    int K = ta.K[i], N = ta.N[i];
    int nbx = N >> 5;
    int n0 = (lb % nbx) * 32, k0 = (lb / nbx) * 32;
    const float* src = ta.src[i];
    __half* dst = ta.dst[i];

    int tx = threadIdx.x, ty = threadIdx.y;
    #pragma unroll
    for (int j = 0; j < 4; j++)
        t[ty + j*8][tx] = src[(size_t)(k0 + ty + j*8) * N + n0 + tx];
    __syncthreads();
    #pragma unroll
    for (int j = 0; j < 4; j++)
        dst[(size_t)(n0 + ty + j*8) * K + k0 + tx] = __float2half_rn(t[tx][ty + j*8]);
}

// ---------------- asym fp16 GEMM: A hi/lo fp16, B single fp16 ----------------
// C[M,N] = A[M,K(lda)] @ Bt[N,K]^T. 2 MMAs per k16. 3 tiles/buffer, 61440 B.
// EPI 0: fp32 (Nc). 1: fp32+bias. 2: fp16 hi/lo (Ns). 3: mixed (fp32 < boundary, fp16 single >=).
#define SA_ELEMS (128*40)
#define HG_SMEM (6*SA_ELEMS*2)

__device__ __forceinline__ void hgemm_fill(
    uint32_t sb, int buf,
    const __half* __restrict__ Ah, const __half* __restrict__ Al,
    const __half* __restrict__ B,
    int tid, int row0, int col0, int k0, int lda, int ldb)
{
    #pragma unroll
    for (int j = 0; j < 4; j++) {
        int chunk = tid + 128*j;
        int r = chunk >> 2, cc = chunk & 3;
        size_t ga = (size_t)(row0 + r) * lda + k0 + cc*8;
        size_t gb = (size_t)(col0 + r) * ldb + k0 + cc*8;
        uint32_t off = (uint32_t)(r*40 + cc*8)*2;
        cp16(sb + (buf*3+0)*SA_ELEMS*2 + off, Ah + ga);
        cp16(sb + (buf*3+1)*SA_ELEMS*2 + off, Al + ga);
        cp16(sb + (buf*3+2)*SA_ELEMS*2 + off, B + gb);
    }
    asm volatile("cp.async.commit_group;");
}

template<int EPI>
__global__ void __launch_bounds__(128)
hgemm_kernel(const __half* __restrict__ Ah, const __half* __restrict__ Al,
             const __half* __restrict__ B,
             float* __restrict__ C, __half* __restrict__ Chi, __half* __restrict__ Clo,
             const float* __restrict__ bias,
             int lda, int K, int Nc, int Ns, int boundary)
{
    extern __shared__ __half hsm[];
    const uint32_t sb = (uint32_t)__cvta_generic_to_shared(hsm);

    const int tid  = threadIdx.x;
    const int lane = tid & 31;
    const int wid  = tid >> 5;
    const int m0w  = (wid >> 1) * 64;
    const int n0w  = (wid & 1) * 64;
    const int row0 = blockIdx.y * 128;
    const int col0 = blockIdx.x * 128;

    float acc[4][8][4];
    #pragma unroll
    for (int i = 0; i < 4; i++)
        #pragma unroll
        for (int j = 0; j < 8; j++)
            #pragma unroll
            for (int k = 0; k < 4; k++) acc[i][j][k] = 0.f;

    const int niter = K >> 5;
    hgemm_fill(sb, 0, Ah, Al, B, tid, row0, col0, 0, lda, K);

    const int aRow  = m0w + (lane & 15);
    const int aCol8 = 8 * (lane >> 4);
    const int bRow  = n0w + (lane & 15);

    for (int it = 0; it < niter; ++it) {
        const int buf = it & 1;
        if (it + 1 < niter) {
            hgemm_fill(sb, buf ^ 1, Ah, Al, B, tid, row0, col0, (it+1)*32, lda, K);
            asm volatile("cp.async.wait_group 1;");
        } else {
            asm volatile("cp.async.wait_group 0;");
        }
        __syncthreads();

        #pragma unroll
        for (int sub = 0; sub < 32; sub += 16) {
            uint32_t ah[4][4], al[4][4];
            #pragma unroll
            for (int mt = 0; mt < 4; mt++) {
                uint32_t addr = sb +
                    (uint32_t)((buf*3)*SA_ELEMS + (aRow + mt*16)*40 + sub + aCol8)*2;
                LDM_X4(ah[mt], addr);
                LDM_X4(al[mt], addr + SA_ELEMS*2);
            }
            // B non-trans ldmatrix on K-major: pairs n0-7 -> (r0,r2); n8-15 -> (r1,r3)
            #pragma unroll
            for (int ng = 0; ng < 4; ng++) {
                uint32_t bb[4];
                uint32_t addr = sb +
                    (uint32_t)((buf*3+2)*SA_ELEMS + (bRow + ng*16)*40 + sub + aCol8)*2;
                LDM_X4(bb, addr);
                #pragma unroll
                for (int half = 0; half < 2; half++) {
                    uint32_t b0 = bb[half], b1 = bb[half+2];
                    int nt = ng*2 + half;
                    #pragma unroll
                    for (int mt = 0; mt < 4; mt++) {
                        MMAH16816(acc[mt][nt], ah[mt], b0, b1);
                        MMAH16816(acc[mt][nt], al[mt], b0, b1);
                    }
                }
            }
        }
        __syncthreads();
    }

    const bool fp32_mode = (EPI == 0) || (EPI == 1) || (EPI == 3 && col0 < boundary);
    #pragma unroll
    for (int mt = 0; mt < 4; mt++) {
        #pragma unroll
        for (int nt = 0; nt < 8; nt++) {
            int r  = row0 + m0w + mt*16 + (lane >> 2);
            int cc = col0 + n0w + nt*8 + (lane & 3)*2;
            float a0 = acc[mt][nt][0], a1 = acc[mt][nt][1];
            float a2 = acc[mt][nt][2], a3 = acc[mt][nt][3];
            if (fp32_mode) {
                float b0 = 0.f, b1 = 0.f;
                if (EPI == 1) { b0 = bias[cc]; b1 = bias[cc+1]; }
                *(float2*)(C + (size_t)r     * Nc + cc) = make_float2(a0 + b0, a1 + b1);
                *(float2*)(C + (size_t)(r+8) * Nc + cc) = make_float2(a2 + b0, a3 + b1);
            } else if (EPI == 2) {
                float h0 = rn_f16(a0), h1 = rn_f16(a1);
                float h2 = rn_f16(a2), h3 = rn_f16(a3);
                *(uint32_t*)(Chi + (size_t)r     * Ns + cc) = pack_f16(h0, h1);
                *(uint32_t*)(Clo + (size_t)r     * Ns + cc) = pack_f16(a0 - h0, a1 - h1);
                *(uint32_t*)(Chi + (size_t)(r+8) * Ns + cc) = pack_f16(h2, h3);
                *(uint32_t*)(Clo + (size_t)(r+8) * Ns + cc) = pack_f16(a2 - h2, a3 - h3);
            } else {   // EPI == 3, fp16 single (V)
                int cs = cc - boundary;
                *(uint32_t*)(Chi + (size_t)r     * Ns + cs) = pack_f16(a0, a1);
                *(uint32_t*)(Chi + (size_t)(r+8) * Ns + cs) = pack_f16(a2, a3);
            }
        }
    }
}

// ---------------- fp32 SGEMM (tiny wk_rope, N=64) ----------------
__global__ void __launch_bounds__(256)
sgemm_kernel(const float* __restrict__ A, const float* __restrict__ W,
             float* __restrict__ C, int N, int K)
{
    __shared__ float As[16][132];
    __shared__ float Bs[16][128];

    const int tid = threadIdx.x;
    const int tx = tid & 15, ty = tid >> 4;
    const int bx = blockIdx.x, by = blockIdx.y;

    const int a_r = tid >> 2;
    const int a_c = (tid & 3) << 2;
    const int b_r = tid >> 5;
    const int b_c = (tid & 31) << 2;

    const float* Ab = A + (size_t)by * 128 * K;

    float acc[8][8];
    #pragma unroll
    for (int i = 0; i < 8; i++)
        #pragma unroll
        for (int j = 0; j < 8; j++) acc[i][j] = 0.f;

    for (int k0 = 0; k0 < K; k0 += 16) {
        #pragma unroll
        for (int u = 0; u < 2; u++) {
            int r = a_r + u*64;
            float4 v = *(const float4*)(Ab + (size_t)r * K + (k0 + a_c));
            As[a_c+0][r] = v.x; As[a_c+1][r] = v.y;
            As[a_c+2][r] = v.z; As[a_c+3][r] = v.w;
        }
        #pragma unroll
        for (int u = 0; u < 2; u++) {
            int r = b_r + u*8;
            int col = bx*128 + b_c;
            float4 v = make_float4(0.f, 0.f, 0.f, 0.f);
            if (col < N) v = *(const float4*)(W + (size_t)(k0 + r) * N + col);
            *(float4*)&Bs[r][b_c] = v;
        }
        __syncthreads();
        #pragma unroll
        for (int k = 0; k < 16; k++) {
            float a[8], b[8];
            *(float4*)&a[0] = *(const float4*)&As[k][ty*8];
            *(float4*)&a[4] = *(const float4*)&As[k][ty*8+4];
            *(float4*)&b[0] = *(const float4*)&Bs[k][tx*8];
            *(float4*)&b[4] = *(const float4*)&Bs[k][tx*8+4];
            #pragma unroll
            for (int i = 0; i < 8; i++)
                #pragma unroll
                for (int j = 0; j < 8; j++)
                    acc[i][j] = fmaf(a[i], b[j], acc[i][j]);
        }
        __syncthreads();
    }

    const int row0 = by*128 + ty*8;
    const int col0 = bx*128 + tx*8;
    #pragma unroll
    for (int i = 0; i < 8; i++) {
        #pragma unroll
        for (int j = 0; j < 8; j += 4) {
            int col = col0 + j;
            if (col < N) {
                float4 v = make_float4(acc[i][j], acc[i][j+1], acc[i][j+2], acc[i][j+3]);
                *(float4*)(C + (size_t)(row0+i)*N + col) = v;
            }
        }
    }
}

// ---------------- RoPE LUT + merged pack ----------------
__global__ void rope_lut_kernel()
{
    int idx = blockIdx.x * blockDim.x + threadIdx.x;
    int pos = idx >> 5, fi = idx & 31;
    float inv = powf(10000.f, -(float)(2*fi) / 64.f);
    float ang = (float)pos * inv;
    float s, c;
    sincosf(ang, &s, &c);
    g_cs[idx] = c;
    g_sn[idx] = s;
}

__global__ void pack_qk_kernel()
{
    int gidx = blockIdx.x * blockDim.x + threadIdx.x;
    const int TOT = NM * NHID;
    bool isK = gidx >= TOT;
    int idx = isK ? (gidx - TOT) : gidx;
    int row = idx >> 11;
    int c   = idx & (NHID - 1);
    int h = c >> 7, d = c & 127;
    float out;
    if (!isK) {
        if (d < 64) {
            out = g_qcr[(size_t)row*2048 + h*64 + d];
        } else {
            int dd = d - 64;
            const float* qr = g_qcr + (size_t)row*2048 + 1024 + h*64;
            int pos = row & (NS - 1);
            float cs = g_cs[pos*32 + (dd & 31)], sn = g_sn[pos*32 + (dd & 31)];
            float v = qr[dd];
            float w = (dd < 32) ? -qr[dd + 32] : qr[dd - 32];
            out = v * cs + w * sn;
        }
        out *= 0.08838834764831845f;
        bf16 hi = __float2bfloat16(out);
        g_Qh[idx] = hi;
        g_Ql[idx] = __float2bfloat16(out - __bfloat162float(hi));
    } else {
        if (d < 64) {
            out = g_kc[(size_t)row*1024 + h*64 + d];
        } else {
            int dd = d - 64;
            const float* kr = g_krr + (size_t)row*NRD;
            int pos = row & (NS - 1);
            float cs = g_cs[pos*32 + (dd & 31)], sn = g_sn[pos*32 + (dd & 31)];
            float v = kr[dd];
            float w = (dd < 32) ? -kr[dd + 32] : kr[dd - 32];
            out = v * cs + w * sn;
        }
        bf16 hi = __float2bfloat16(out);
        g_Kh[idx] = hi;
        g_Kl[idx] = __float2bfloat16(out - __bfloat162float(hi));
    }
}

// ---------------- flash attention: QK bf16-split, PV fp16 (P hi/lo x V single) ----------------
#define FS 136
#define FTILE_B (64*FS*2)
#define FL_SMEM (5*FTILE_B)   // Qh,Ql,Kh,Kl (bf16) + V (fp16)

__global__ void __launch_bounds__(128)
flasht_kernel(const bf16* __restrict__ Qh, const bf16* __restrict__ Ql,
              const bf16* __restrict__ Kh, const bf16* __restrict__ Kl,
              const __half* __restrict__ V,
              __half* __restrict__ Ohi, __half* __restrict__ Olo)
{
    extern __shared__ bf16 fsm[];
    const uint32_t sb = (uint32_t)__cvta_generic_to_shared(fsm);

    const int tid = threadIdx.x;
    const int lane = tid & 31;
    const int w = tid >> 5;
    const int lr = lane >> 2;
    const int lc = (lane & 3) * 2;
    const int h = blockIdx.y, b = blockIdx.z;
    const int q0 = blockIdx.x * 64;
    const size_t base = ((size_t)b * NS) * NHID + (size_t)h * NHD;

    for (int i = tid; i < 1024; i += 128) {
        int r = i >> 4, c = (i & 15) << 3;
        uint32_t so = (uint32_t)(r*FS + c) * 2;
        size_t go = base + (size_t)(q0 + r) * NHID + c;
        cp16(sb + 0*FTILE_B + so, Qh + go);
        cp16(sb + 1*FTILE_B + so, Ql + go);
    }
    asm volatile("cp.async.commit_group;");

    float m0 = -1e30f, m1 = -1e30f, l0 = 0.f, l1 = 0.f;
    float o[16][4];
    #pragma unroll
    for (int i = 0; i < 16; i++)
        #pragma unroll
        for (int j = 0; j < 4; j++) o[i][j] = 0.f;

    const int aRow = w*16 + (lane & 15);
    const int hi8  = 8 * (lane >> 4);
    const int ntiles = blockIdx.x + 1;

    for (int t = 0; t < ntiles; t++) {
        const int k0 = t * 64;
        if (t) __syncthreads();
        for (int i = tid; i < 1024; i += 128) {
            int r = i >> 4, c = (i & 15) << 3;
            uint32_t so = (uint32_t)(r*FS + c) * 2;
            size_t go = base + (size_t)(k0 + r) * NHID + c;
            cp16(sb + 2*FTILE_B + so, Kh + go);
            cp16(sb + 3*FTILE_B + so, Kl + go);
            cp16(sb + 4*FTILE_B + so, V + go);
        }
        asm volatile("cp.async.commit_group;");
        asm volatile("cp.async.wait_group 0;");
        __syncthreads();

        float s[8][4];
        #pragma unroll
        for (int i = 0; i < 8; i++)
            #pragma unroll
            for (int j = 0; j < 4; j++) s[i][j] = 0.f;

        #pragma unroll
        for (int kc = 0; kc < 8; kc++) {
            uint32_t qh[4], ql[4];
            uint32_t qa = sb + (uint32_t)(aRow*FS + kc*16 + hi8)*2;
            LDM_X4(qh, qa);
            LDM_X4(ql, qa + FTILE_B);
            #pragma unroll
            for (int g = 0; g < 4; g++) {
                uint32_t kh[4], kl[4];
                uint32_t ka = sb + 2*FTILE_B + (uint32_t)((g*16 + (lane & 15))*FS + kc*16 + hi8)*2;
                LDM_X4(kh, ka);
                LDM_X4(kl, ka + FTILE_B);
                MMA16816(s[2*g],   qh, kh[0], kh[2]);
                MMA16816(s[2*g],   qh, kl[0], kl[2]);
                MMA16816(s[2*g],   ql, kh[0], kh[2]);
                MMA16816(s[2*g+1], qh, kh[1], kh[3]);
                MMA16816(s[2*g+1], qh, kl[1], kl[3]);
                MMA16816(s[2*g+1], ql, kh[1], kh[3]);
            }
        }

        if (t == blockIdx.x) {
            int r0 = q0 + w*16 + lr, r1 = r0 + 8;
            #pragma unroll
            for (int nt = 0; nt < 8; nt++) {
                int c = k0 + nt*8 + lc;
                if (c     > r0) s[nt][0] = -1e30f;
                if (c + 1 > r0) s[nt][1] = -1e30f;
                if (c     > r1) s[nt][2] = -1e30f;
                if (c + 1 > r1) s[nt][3] = -1e30f;
            }
        }

        float mt0 = -1e30f, mt1 = -1e30f;
        #pragma unroll
        for (int nt = 0; nt < 8; nt++) {
            mt0 = fmaxf(mt0, fmaxf(s[nt][0], s[nt][1]));
            mt1 = fmaxf(mt1, fmaxf(s[nt][2], s[nt][3]));
        }
        mt0 = fmaxf(mt0, __shfl_xor_sync(0xffffffffu, mt0, 1));
        mt0 = fmaxf(mt0, __shfl_xor_sync(0xffffffffu, mt0, 2));
        mt1 = fmaxf(mt1, __shfl_xor_sync(0xffffffffu, mt1, 1));
        mt1 = fmaxf(mt1, __shfl_xor_sync(0xffffffffu, mt1, 2));
        float n0 = fmaxf(m0, mt0), n1 = fmaxf(m1, mt1);
        float corr0 = __expf(m0 - n0), corr1 = __expf(m1 - n1);
        m0 = n0; m1 = n1;

        float ps0 = 0.f, ps1 = 0.f;
        #pragma unroll
        for (int nt = 0; nt < 8; nt++) {
            s[nt][0] = __expf(s[nt][0] - n0);
            s[nt][1] = __expf(s[nt][1] - n0);
            s[nt][2] = __expf(s[nt][2] - n1);
            s[nt][3] = __expf(s[nt][3] - n1);
            ps0 += s[nt][0] + s[nt][1];
            ps1 += s[nt][2] + s[nt][3];
        }
        l0 = l0 * corr0 + ps0;
        l1 = l1 * corr1 + ps1;
        #pragma unroll
        for (int i = 0; i < 16; i++) {
            o[i][0] *= corr0; o[i][1] *= corr0;
            o[i][2] *= corr1; o[i][3] *= corr1;
        }

        // ---- O += P V : P hi/lo fp16, V single fp16 -> 2 MMAs ----
        #pragma unroll
        for (int kc = 0; kc < 4; kc++) {
            uint32_t ph[4], pl[4];
            {
                float p00 = s[2*kc][0],   p01 = s[2*kc][1];
                float p02 = s[2*kc][2],   p03 = s[2*kc][3];
                float p10 = s[2*kc+1][0], p11 = s[2*kc+1][1];
                float p12 = s[2*kc+1][2], p13 = s[2*kc+1][3];
                float h00 = rn_f16(p00), h01 = rn_f16(p01);
                float h02 = rn_f16(p02), h03 = rn_f16(p03);
                float h10 = rn_f16(p10), h11 = rn_f16(p11);
                float h12 = rn_f16(p12), h13 = rn_f16(p13);
                ph[0] = pack_f16(h00, h01);
                ph[1] = pack_f16(h02, h03);
                ph[2] = pack_f16(h10, h11);
                ph[3] = pack_f16(h12, h13);
                pl[0] = pack_f16(p00 - h00, p01 - h01);
                pl[1] = pack_f16(p02 - h02, p03 - h03);
                pl[2] = pack_f16(p10 - h10, p11 - h11);
                pl[3] = pack_f16(p12 - h12, p13 - h13);
            }
            #pragma unroll
            for (int np = 0; np < 8; np++) {
                uint32_t vv[4];
                uint32_t va = sb + 4*FTILE_B +
                    (uint32_t)((kc*16 + (lane & 15))*FS + np*16 + hi8)*2;
                LDM_X4_T(vv, va);
                MMAH16816(o[2*np],   ph, vv[0], vv[1]);
                MMAH16816(o[2*np],   pl, vv[0], vv[1]);
                MMAH16816(o[2*np+1], ph, vv[2], vv[3]);
                MMAH16816(o[2*np+1], pl, vv[2], vv[3]);
            }
        }
    }

    float t0 = l0, t1 = l1;
    t0 += __shfl_xor_sync(0xffffffffu, t0, 1);
    t0 += __shfl_xor_sync(0xffffffffu, t0, 2);
    t1 += __shfl_xor_sync(0xffffffffu, t1, 1);
    t1 += __shfl_xor_sync(0xffffffffu, t1, 2);
    float inv0 = 1.f / t0, inv1 = 1.f / t1;
    int r0 = q0 + w*16 + lr;
    #pragma unroll
    for (int nt = 0; nt < 16; nt++) {
        int c = nt*8 + lc;
        float v0 = o[nt][0]*inv0, v1 = o[nt][1]*inv0;
        float v2 = o[nt][2]*inv1, v3 = o[nt][3]*inv1;
        float h0 = rn_f16(v0), h1 = rn_f16(v1);
        float h2 = rn_f16(v2), h3 = rn_f16(v3);
        size_t off0 = base + (size_t)r0 * NHID + c;
        size_t off1 = base + (size_t)(r0+8) * NHID + c;
        *(uint32_t*)(Ohi + off0) = pack_f16(h0, h1);
        *(uint32_t*)(Olo + off0) = pack_f16(v0 - h0, v1 - h1);
        *(uint32_t*)(Ohi + off1) = pack_f16(h2, h3);
        *(uint32_t*)(Olo + off1) = pack_f16(v2 - h2, v3 - h3);
    }
}

// ---------------- host launcher ----------------
extern "C" void kernel_launch(void* const* d_in, const int* in_sizes, int n_in,
                              void* d_out, int out_size)
{
    const float* x        = (const float*)d_in[0];
    const float* wq_down  = (const float*)d_in[1];
    const float* wq_up    = (const float*)d_in[2];
    const float* wq_rope  = (const float*)d_in[3];
    const float* wk_rope  = (const float*)d_in[4];
    const float* wkv_down = (const float*)d_in[5];
    const float* wk_up    = (const float*)d_in[6];
    const float* wv_up    = (const float*)d_in[7];
    const float* wo       = (const float*)d_in[8];
    const float* bo       = (const float*)d_in[9];
    float* out = (float*)d_out;

    float *krr, *qcr, *kc;
    cudaGetSymbolAddress((void**)&krr, g_krr);
    cudaGetSymbolAddress((void**)&qcr, g_qcr);
    cudaGetSymbolAddress((void**)&kc,  g_kc);

    __half *xs, *wd, *wuq, *wukv, *woh, *lat, *V, *ch, *cl;
    cudaGetSymbolAddress((void**)&xs,   g_xs);
    cudaGetSymbolAddress((void**)&wd,   g_wd);
    cudaGetSymbolAddress((void**)&wuq,  g_wuq);
    cudaGetSymbolAddress((void**)&wukv, g_wukv);
    cudaGetSymbolAddress((void**)&woh,  g_woh);
    cudaGetSymbolAddress((void**)&lat,  g_lat);
    cudaGetSymbolAddress((void**)&V,    g_V);
    cudaGetSymbolAddress((void**)&ch,   g_ch);
    cudaGetSymbolAddress((void**)&cl,   g_cl);

    bf16 *Qh, *Ql, *Kh, *Kl;
    cudaGetSymbolAddress((void**)&Qh, g_Qh);
    cudaGetSymbolAddress((void**)&Ql, g_Ql);
    cudaGetSymbolAddress((void**)&Kh, g_Kh);
    cudaGetSymbolAddress((void**)&Kl, g_Kl);

    const size_t XN   = (size_t)NM*NHID;
    const size_t LATN = (size_t)NM*1024;

    cudaFuncSetAttribute(hgemm_kernel<0>, cudaFuncAttributeMaxDynamicSharedMemorySize, HG_SMEM);
    cudaFuncSetAttribute(hgemm_kernel<1>, cudaFuncAttributeMaxDynamicSharedMemorySize, HG_SMEM);
    cudaFuncSetAttribute(hgemm_kernel<2>, cudaFuncAttributeMaxDynamicSharedMemorySize, HG_SMEM);
    cudaFuncSetAttribute(hgemm_kernel<3>, cudaFuncAttributeMaxDynamicSharedMemorySize, HG_SMEM);
    cudaFuncSetAttribute(flasht_kernel,   cudaFuncAttributeMaxDynamicSharedMemorySize, FL_SMEM);

    dim3 thr(256);
    dim3 gthr(128);

    // (1) RoPE LUT
    rope_lut_kernel<<<256, 256>>>();

    // (2) x split -> fp16 hi/lo
    split4h_kernel<<<(unsigned)(XN/1024), 256>>>((const float4*)x, (uint32_t*)xs, (uint32_t*)(xs + XN));

    // (3) batched weight transpose -> fp16 (all 7 weights)
    {
        TAll ta;
        const float* srcs[7] = { wq_down, wkv_down, wq_up, wq_rope, wk_up, wv_up, wo };
        __half* dsts[7] = { wd,            wd + (size_t)512*2048,
                            wuq,           wuq + (size_t)1024*512,
                            wukv,          wukv + (size_t)1024*512,
                            woh };
        int Ks[7] = { 2048, 2048, 512, 512, 512, 512, 2048 };
        int Ns[7] = { 512, 512, 1024, 1024, 1024, 2048, 2048 };
        int total = 0;
        for (int i = 0; i < 7; i++) {
            ta.src[i] = srcs[i]; ta.dst[i] = dsts[i];
            ta.K[i] = Ks[i]; ta.N[i] = Ns[i];
            ta.start[i] = total;
            total += (Ns[i]/32) * (Ks[i]/32);
        }
        ta.start[7] = total;
        wtrans_all_kernel<<<total, dim3(32, 8)>>>(ta);
    }

    // (4) tiny rope-key projection
    sgemm_kernel<<<dim3(1, 64), thr>>>(x, wk_rope, krr, 64, 2048);

    // (5) fused down projection -> fp16 hi/lo latents (EPI=2)
    hgemm_kernel<2><<<dim3(8, 64), gthr, HG_SMEM>>>(
        xs, xs + XN, wd,
        nullptr, lat, lat + LATN, nullptr,
        2048, 2048, 0, 1024, 0);

    // (6) fused up-q: [qc | qr] fp32 (EPI=0)
    hgemm_kernel<0><<<dim3(16, 64), gthr, HG_SMEM>>>(
        lat, lat + LATN, wuq,
        qcr, nullptr, nullptr, nullptr,
        1024, 512, 2048, 0, 0);

    // (7) fused up-kv: [kc fp32 | V fp16 single] (EPI=3)
    hgemm_kernel<3><<<dim3(24, 64), gthr, HG_SMEM>>>(
        lat + 512, lat + LATN + 512, wukv,
        kc, V, nullptr, nullptr,
        1024, 512, 1024, 2048, 1024);

    // (8) merged RoPE + pack Q/K (bf16 hi/lo)
    pack_qk_kernel<<<(2*NM*NHID)/256, thr>>>();

    // (9) flash attention -> ctx fp16 hi/lo
    flasht_kernel<<<dim3(NS/64, NH, NB), 128, FL_SMEM>>>(Qh, Ql, Kh, Kl, V, ch, cl);

    // (10) asym fp16 output projection + bias (EPI=1)
    hgemm_kernel<1><<<dim3(16, 64), gthr, HG_SMEM>>>(
        ch, cl, woh,
        out, nullptr, nullptr, bo,
        2048, 2048, 2048, 0, 0);
}

// round 13
// speedup vs baseline: 1.9336x; 1.1569x over previous
#include <cuda_runtime.h>
#include <cuda_bf16.h>
#include <cuda_fp16.h>
#include <math.h>
#include <stdint.h>

using bf16 = __nv_bfloat16;

#define NB   4
#define NS   2048
#define NH   16
#define NHD  128
#define NRD  64
#define NLAT 512
#define NHID 2048
#define NM   (NB*NS)

// ---------------- device scratch ----------------
__device__ float g_krr [(size_t)NM*NRD];
__device__ float g_qcr [(size_t)NM*2048];
__device__ float g_kc  [(size_t)NM*1024];
__device__ float g_cs  [NS*32];
__device__ float g_sn  [NS*32];

// fp16 operands
__device__ __half g_xs  [2][(size_t)NM*NHID];    // x hi/lo
__device__ __half g_wd  [(size_t)1152*2048];     // [wq_down|wkv_down|wk_rope|pad] T fp16
__device__ __half g_wuq [(size_t)2048*512];      // [wq_up|wq_rope] T fp16
__device__ __half g_wukv[(size_t)3072*512];      // [wk_up|wv_up] T fp16
__device__ __half g_woh [(size_t)2048*2048];     // wo T fp16
__device__ __half g_lat [2][(size_t)NM*1024];    // latents hi/lo fp16
__device__ __half g_V   [(size_t)NM*NHID];       // V single fp16
__device__ __half g_ch  [(size_t)NM*NHID];       // ctx hi fp16
__device__ __half g_cl  [(size_t)NM*NHID];       // ctx lo fp16

// bf16 attention Q/K (score path stays high precision)
__device__ bf16 g_Qh[(size_t)NM*NHID];
__device__ bf16 g_Ql[(size_t)NM*NHID];
__device__ bf16 g_Kh[(size_t)NM*NHID];
__device__ bf16 g_Kl[(size_t)NM*NHID];

// ---------------- PTX helpers ----------------
__device__ __forceinline__ void cp16(uint32_t s, const void* g) {
    asm volatile("cp.async.cg.shared.global [%0], [%1], 16;\n" :: "r"(s), "l"(g));
}

#define LDM_X4(R, addr) \
    asm volatile("ldmatrix.sync.aligned.m8n8.x4.shared.b16 {%0,%1,%2,%3}, [%4];" \
        : "=r"(R[0]), "=r"(R[1]), "=r"(R[2]), "=r"(R[3]) : "r"(addr))
#define LDM_X4_T(R, addr) \
    asm volatile("ldmatrix.sync.aligned.m8n8.x4.trans.shared.b16 {%0,%1,%2,%3}, [%4];" \
        : "=r"(R[0]), "=r"(R[1]), "=r"(R[2]), "=r"(R[3]) : "r"(addr))
#define MMA16816(D, A, B0, B1) \
    asm volatile("mma.sync.aligned.m16n8k16.row.col.f32.bf16.bf16.f32 " \
        "{%0,%1,%2,%3}, {%4,%5,%6,%7}, {%8,%9}, {%0,%1,%2,%3};" \
        : "+f"(D[0]), "+f"(D[1]), "+f"(D[2]), "+f"(D[3]) \
        : "r"(A[0]), "r"(A[1]), "r"(A[2]), "r"(A[3]), "r"(B0), "r"(B1))
#define MMAH16816(D, A, B0, B1) \
    asm volatile("mma.sync.aligned.m16n8k16.row.col.f32.f16.f16.f32 " \
        "{%0,%1,%2,%3}, {%4,%5,%6,%7}, {%8,%9}, {%0,%1,%2,%3};" \
        : "+f"(D[0]), "+f"(D[1]), "+f"(D[2]), "+f"(D[3]) \
        : "r"(A[0]), "r"(A[1]), "r"(A[2]), "r"(A[3]), "r"(B0), "r"(B1))

__device__ __forceinline__ uint32_t pack_bf16(float a, float b) {
    uint32_t r;
    asm("cvt.rn.bf16x2.f32 %0, %1, %2;" : "=r"(r) : "f"(b), "f"(a));
    return r;
}
__device__ __forceinline__ float rn_bf16(float f) {
    return __bfloat162float(__float2bfloat16(f));
}
__device__ __forceinline__ uint32_t pack_f16(float a, float b) {
    uint32_t r;
    asm("cvt.rn.f16x2.f32 %0, %1, %2;" : "=r"(r) : "f"(b), "f"(a));
    return r;
}
__device__ __forceinline__ float rn_f16(float f) {
    return __half2float(__float2half_rn(f));
}

// ---------------- x split fp32 -> fp16 hi/lo ----------------
__global__ void split4h_kernel(const float4* __restrict__ in,
                               uint32_t* __restrict__ hi, uint32_t* __restrict__ lo)
{
    size_t i = (size_t)blockIdx.x * blockDim.x + threadIdx.x;
    float4 f = in[i];
    float hx = rn_f16(f.x), hy = rn_f16(f.y), hz = rn_f16(f.z), hw = rn_f16(f.w);
    hi[2*i]   = pack_f16(hx, hy);
    hi[2*i+1] = pack_f16(hz, hw);
    lo[2*i]   = pack_f16(f.x - hx, f.y - hy);
    lo[2*i+1] = pack_f16(f.z - hz, f.w - hw);
}

// batched transpose fp32 [K,N] -> fp16 [N,K], 8 weights in one launch
struct TAll {
    const float* src[8];
    __half* dst[8];
    int K[8];
    int N[8];
    int start[9];
};

__global__ void wtrans_all_kernel(TAll ta)
{
    __shared__ float t[32][33];
    int bid = blockIdx.x;
    int i = 0;
    #pragma unroll
    for (int j = 1; j < 8; j++) if (bid >= ta.start[j]) i = j;
    int lb = bid - ta.start[i];
    int K = ta.K[i], N = ta.N[i];
    int nbx = N >> 5;
    int n0 = (lb % nbx) * 32, k0 = (lb / nbx) * 32;
    const float* src = ta.src[i];
    __half* dst = ta.dst[i];

    int tx = threadIdx.x, ty = threadIdx.y;
    #pragma unroll
    for (int j = 0; j < 4; j++)
        t[ty + j*8][tx] = src[(size_t)(k0 + ty + j*8) * N + n0 + tx];
    __syncthreads();
    #pragma unroll
    for (int j = 0; j < 4; j++)
        dst[(size_t)(n0 + ty + j*8) * K + k0 + tx] = __float2half_rn(t[tx][ty + j*8]);
}

// ---------------- asym fp16 GEMM: A hi/lo fp16, B single fp16 ----------------
// C[M,N] = A[M,K(lda)] @ Bt[N,K]^T. 2 MMAs per k16. 3 tiles/buffer, 61440 B.
// EPI 0: fp32 (Nc). 1: fp32+bias. 2: fp16 hi/lo (Ns).
// EPI 3: mixed (fp32 C < boundary, fp16 single Chi >=).
// EPI 4: mixed (fp16 hi/lo < boundary; fp32 C at cs=cc-boundary if cs<Nc, else discard).
#define SA_ELEMS (128*40)
#define HG_SMEM (6*SA_ELEMS*2)

__device__ __forceinline__ void hgemm_fill(
    uint32_t sb, int buf,
    const __half* __restrict__ Ah, const __half* __restrict__ Al,
    const __half* __restrict__ B,
    int tid, int row0, int col0, int k0, int lda, int ldb)
{
    #pragma unroll
    for (int j = 0; j < 4; j++) {
        int chunk = tid + 128*j;
        int r = chunk >> 2, cc = chunk & 3;
        size_t ga = (size_t)(row0 + r) * lda + k0 + cc*8;
        size_t gb = (size_t)(col0 + r) * ldb + k0 + cc*8;
        uint32_t off = (uint32_t)(r*40 + cc*8)*2;
        cp16(sb + (buf*3+0)*SA_ELEMS*2 + off, Ah + ga);
        cp16(sb + (buf*3+1)*SA_ELEMS*2 + off, Al + ga);
        cp16(sb + (buf*3+2)*SA_ELEMS*2 + off, B + gb);
    }
    asm volatile("cp.async.commit_group;");
}

template<int EPI>
__global__ void __launch_bounds__(128)
hgemm_kernel(const __half* __restrict__ Ah, const __half* __restrict__ Al,
             const __half* __restrict__ B,
             float* __restrict__ C, __half* __restrict__ Chi, __half* __restrict__ Clo,
             const float* __restrict__ bias,
             int lda, int K, int Nc, int Ns, int boundary)
{
    extern __shared__ __half hsm[];
    const uint32_t sb = (uint32_t)__cvta_generic_to_shared(hsm);

    const int tid  = threadIdx.x;
    const int lane = tid & 31;
    const int wid  = tid >> 5;
    const int m0w  = (wid >> 1) * 64;
    const int n0w  = (wid & 1) * 64;
    const int row0 = blockIdx.y * 128;
    const int col0 = blockIdx.x * 128;

    float acc[4][8][4];
    #pragma unroll
    for (int i = 0; i < 4; i++)
        #pragma unroll
        for (int j = 0; j < 8; j++)
            #pragma unroll
            for (int k = 0; k < 4; k++) acc[i][j][k] = 0.f;

    const int niter = K >> 5;
    hgemm_fill(sb, 0, Ah, Al, B, tid, row0, col0, 0, lda, K);

    const int aRow  = m0w + (lane & 15);
    const int aCol8 = 8 * (lane >> 4);
    const int bRow  = n0w + (lane & 15);

    for (int it = 0; it < niter; ++it) {
        const int buf = it & 1;
        if (it + 1 < niter) {
            hgemm_fill(sb, buf ^ 1, Ah, Al, B, tid, row0, col0, (it+1)*32, lda, K);
            asm volatile("cp.async.wait_group 1;");
        } else {
            asm volatile("cp.async.wait_group 0;");
        }
        __syncthreads();

        #pragma unroll
        for (int sub = 0; sub < 32; sub += 16) {
            uint32_t ah[4][4], al[4][4];
            #pragma unroll
            for (int mt = 0; mt < 4; mt++) {
                uint32_t addr = sb +
                    (uint32_t)((buf*3)*SA_ELEMS + (aRow + mt*16)*40 + sub + aCol8)*2;
                LDM_X4(ah[mt], addr);
                LDM_X4(al[mt], addr + SA_ELEMS*2);
            }
            // B non-trans ldmatrix on K-major: pairs n0-7 -> (r0,r2); n8-15 -> (r1,r3)
            #pragma unroll
            for (int ng = 0; ng < 4; ng++) {
                uint32_t bb[4];
                uint32_t addr = sb +
                    (uint32_t)((buf*3+2)*SA_ELEMS + (bRow + ng*16)*40 + sub + aCol8)*2;
                LDM_X4(bb, addr);
                #pragma unroll
                for (int half = 0; half < 2; half++) {
                    uint32_t b0 = bb[half], b1 = bb[half+2];
                    int nt = ng*2 + half;
                    #pragma unroll
                    for (int mt = 0; mt < 4; mt++) {
                        MMAH16816(acc[mt][nt], ah[mt], b0, b1);
                        MMAH16816(acc[mt][nt], al[mt], b0, b1);
                    }
                }
            }
        }
        __syncthreads();
    }

    const bool fp32_mode = (EPI == 0) || (EPI == 1) || (EPI == 3 && col0 < boundary);
    const bool hilo_mode = (EPI == 2) || (EPI == 4 && col0 < boundary);
    #pragma unroll
    for (int mt = 0; mt < 4; mt++) {
        #pragma unroll
        for (int nt = 0; nt < 8; nt++) {
            int r  = row0 + m0w + mt*16 + (lane >> 2);
            int cc = col0 + n0w + nt*8 + (lane & 3)*2;
            float a0 = acc[mt][nt][0], a1 = acc[mt][nt][1];
            float a2 = acc[mt][nt][2], a3 = acc[mt][nt][3];
            if (fp32_mode) {
                float b0 = 0.f, b1 = 0.f;
                if (EPI == 1) { b0 = bias[cc]; b1 = bias[cc+1]; }
                *(float2*)(C + (size_t)r     * Nc + cc) = make_float2(a0 + b0, a1 + b1);
                *(float2*)(C + (size_t)(r+8) * Nc + cc) = make_float2(a2 + b0, a3 + b1);
            } else if (hilo_mode) {
                float h0 = rn_f16(a0), h1 = rn_f16(a1);
                float h2 = rn_f16(a2), h3 = rn_f16(a3);
                *(uint32_t*)(Chi + (size_t)r     * Ns + cc) = pack_f16(h0, h1);
                *(uint32_t*)(Clo + (size_t)r     * Ns + cc) = pack_f16(a0 - h0, a1 - h1);
                *(uint32_t*)(Chi + (size_t)(r+8) * Ns + cc) = pack_f16(h2, h3);
                *(uint32_t*)(Clo + (size_t)(r+8) * Ns + cc) = pack_f16(a2 - h2, a3 - h3);
            } else if (EPI == 3) {   // fp16 single (V)
                int cs = cc - boundary;
                *(uint32_t*)(Chi + (size_t)r     * Ns + cs) = pack_f16(a0, a1);
                *(uint32_t*)(Chi + (size_t)(r+8) * Ns + cs) = pack_f16(a2, a3);
            } else {                 // EPI == 4, high cols: fp32 krr with bound, pad discarded
                int cs = cc - boundary;
                if (cs < Nc) {
                    *(float2*)(C + (size_t)r     * Nc + cs) = make_float2(a0, a1);
                    *(float2*)(C + (size_t)(r+8) * Nc + cs) = make_float2(a2, a3);
                }
            }
        }
    }
}

// ---------------- RoPE LUT + merged pack ----------------
__global__ void rope_lut_kernel()
{
    int idx = blockIdx.x * blockDim.x + threadIdx.x;
    int pos = idx >> 5, fi = idx & 31;
    float inv = powf(10000.f, -(float)(2*fi) / 64.f);
    float ang = (float)pos * inv;
    float s, c;
    sincosf(ang, &s, &c);
    g_cs[idx] = c;
    g_sn[idx] = s;
}

__global__ void pack_qk_kernel()
{
    int gidx = blockIdx.x * blockDim.x + threadIdx.x;
    const int TOT = NM * NHID;
    bool isK = gidx >= TOT;
    int idx = isK ? (gidx - TOT) : gidx;
    int row = idx >> 11;
    int c   = idx & (NHID - 1);
    int h = c >> 7, d = c & 127;
    float out;
    if (!isK) {
        if (d < 64) {
            out = g_qcr[(size_t)row*2048 + h*64 + d];
        } else {
            int dd = d - 64;
            const float* qr = g_qcr + (size_t)row*2048 + 1024 + h*64;
            int pos = row & (NS - 1);
            float cs = g_cs[pos*32 + (dd & 31)], sn = g_sn[pos*32 + (dd & 31)];
            float v = qr[dd];
            float w = (dd < 32) ? -qr[dd + 32] : qr[dd - 32];
            out = v * cs + w * sn;
        }
        out *= 0.08838834764831845f;
        bf16 hi = __float2bfloat16(out);
        g_Qh[idx] = hi;
        g_Ql[idx] = __float2bfloat16(out - __bfloat162float(hi));
    } else {
        if (d < 64) {
            out = g_kc[(size_t)row*1024 + h*64 + d];
        } else {
            int dd = d - 64;
            const float* kr = g_krr + (size_t)row*NRD;
            int pos = row & (NS - 1);
            float cs = g_cs[pos*32 + (dd & 31)], sn = g_sn[pos*32 + (dd & 31)];
            float v = kr[dd];
            float w = (dd < 32) ? -kr[dd + 32] : kr[dd - 32];
            out = v * cs + w * sn;
        }
        bf16 hi = __float2bfloat16(out);
        g_Kh[idx] = hi;
        g_Kl[idx] = __float2bfloat16(out - __bfloat162float(hi));
    }
}

// ---------------- flash attention: QK bf16-split, PV fp16 (P hi/lo x V single) ----------------
#define FS 136
#define FTILE_B (64*FS*2)
#define FL_SMEM (5*FTILE_B)

__global__ void __launch_bounds__(128)
flasht_kernel(const bf16* __restrict__ Qh, const bf16* __restrict__ Ql,
              const bf16* __restrict__ Kh, const bf16* __restrict__ Kl,
              const __half* __restrict__ V,
              __half* __restrict__ Ohi, __half* __restrict__ Olo)
{
    extern __shared__ bf16 fsm[];
    const uint32_t sb = (uint32_t)__cvta_generic_to_shared(fsm);

    const int tid = threadIdx.x;
    const int lane = tid & 31;
    const int w = tid >> 5;
    const int lr = lane >> 2;
    const int lc = (lane & 3) * 2;
    const int h = blockIdx.y, b = blockIdx.z;
    const int q0 = blockIdx.x * 64;
    const size_t base = ((size_t)b * NS) * NHID + (size_t)h * NHD;

    for (int i = tid; i < 1024; i += 128) {
        int r = i >> 4, c = (i & 15) << 3;
        uint32_t so = (uint32_t)(r*FS + c) * 2;
        size_t go = base + (size_t)(q0 + r) * NHID + c;
        cp16(sb + 0*FTILE_B + so, Qh + go);
        cp16(sb + 1*FTILE_B + so, Ql + go);
    }
    asm volatile("cp.async.commit_group;");

    float m0 = -1e30f, m1 = -1e30f, l0 = 0.f, l1 = 0.f;
    float o[16][4];
    #pragma unroll
    for (int i = 0; i < 16; i++)
        #pragma unroll
        for (int j = 0; j < 4; j++) o[i][j] = 0.f;

    const int aRow = w*16 + (lane & 15);
    const int hi8  = 8 * (lane >> 4);
    const int ntiles = blockIdx.x + 1;

    for (int t = 0; t < ntiles; t++) {
        const int k0 = t * 64;
        if (t) __syncthreads();
        for (int i = tid; i < 1024; i += 128) {
            int r = i >> 4, c = (i & 15) << 3;
            uint32_t so = (uint32_t)(r*FS + c) * 2;
            size_t go = base + (size_t)(k0 + r) * NHID + c;
            cp16(sb + 2*FTILE_B + so, Kh + go);
            cp16(sb + 3*FTILE_B + so, Kl + go);
            cp16(sb + 4*FTILE_B + so, V + go);
        }
        asm volatile("cp.async.commit_group;");
        asm volatile("cp.async.wait_group 0;");
        __syncthreads();

        float s[8][4];
        #pragma unroll
        for (int i = 0; i < 8; i++)
            #pragma unroll
            for (int j = 0; j < 4; j++) s[i][j] = 0.f;

        #pragma unroll
        for (int kc = 0; kc < 8; kc++) {
            uint32_t qh[4], ql[4];
            uint32_t qa = sb + (uint32_t)(aRow*FS + kc*16 + hi8)*2;
            LDM_X4(qh, qa);
            LDM_X4(ql, qa + FTILE_B);
            #pragma unroll
            for (int g = 0; g < 4; g++) {
                uint32_t kh[4], kl[4];
                uint32_t ka = sb + 2*FTILE_B + (uint32_t)((g*16 + (lane & 15))*FS + kc*16 + hi8)*2;
                LDM_X4(kh, ka);
                LDM_X4(kl, ka + FTILE_B);
                MMA16816(s[2*g],   qh, kh[0], kh[2]);
                MMA16816(s[2*g],   qh, kl[0], kl[2]);
                MMA16816(s[2*g],   ql, kh[0], kh[2]);
                MMA16816(s[2*g+1], qh, kh[1], kh[3]);
                MMA16816(s[2*g+1], qh, kl[1], kl[3]);
                MMA16816(s[2*g+1], ql, kh[1], kh[3]);
            }
        }

        if (t == blockIdx.x) {
            int r0 = q0 + w*16 + lr, r1 = r0 + 8;
            #pragma unroll
            for (int nt = 0; nt < 8; nt++) {
                int c = k0 + nt*8 + lc;
                if (c     > r0) s[nt][0] = -1e30f;
                if (c + 1 > r0) s[nt][1] = -1e30f;
                if (c     > r1) s[nt][2] = -1e30f;
                if (c + 1 > r1) s[nt][3] = -1e30f;
            }
        }

        float mt0 = -1e30f, mt1 = -1e30f;
        #pragma unroll
        for (int nt = 0; nt < 8; nt++) {
            mt0 = fmaxf(mt0, fmaxf(s[nt][0], s[nt][1]));
            mt1 = fmaxf(mt1, fmaxf(s[nt][2], s[nt][3]));
        }
        mt0 = fmaxf(mt0, __shfl_xor_sync(0xffffffffu, mt0, 1));
        mt0 = fmaxf(mt0, __shfl_xor_sync(0xffffffffu, mt0, 2));
        mt1 = fmaxf(mt1, __shfl_xor_sync(0xffffffffu, mt1, 1));
        mt1 = fmaxf(mt1, __shfl_xor_sync(0xffffffffu, mt1, 2));
        float n0 = fmaxf(m0, mt0), n1 = fmaxf(m1, mt1);
        float corr0 = __expf(m0 - n0), corr1 = __expf(m1 - n1);
        m0 = n0; m1 = n1;

        float ps0 = 0.f, ps1 = 0.f;
        #pragma unroll
        for (int nt = 0; nt < 8; nt++) {
            s[nt][0] = __expf(s[nt][0] - n0);
            s[nt][1] = __expf(s[nt][1] - n0);
            s[nt][2] = __expf(s[nt][2] - n1);
            s[nt][3] = __expf(s[nt][3] - n1);
            ps0 += s[nt][0] + s[nt][1];
            ps1 += s[nt][2] + s[nt][3];
        }
        l0 = l0 * corr0 + ps0;
        l1 = l1 * corr1 + ps1;
        #pragma unroll
        for (int i = 0; i < 16; i++) {
            o[i][0] *= corr0; o[i][1] *= corr0;
            o[i][2] *= corr1; o[i][3] *= corr1;
        }

        #pragma unroll
        for (int kc = 0; kc < 4; kc++) {
            uint32_t ph[4], pl[4];
            {
                float p00 = s[2*kc][0],   p01 = s[2*kc][1];
                float p02 = s[2*kc][2],   p03 = s[2*kc][3];
                float p10 = s[2*kc+1][0], p11 = s[2*kc+1][1];
                float p12 = s[2*kc+1][2], p13 = s[2*kc+1][3];
                float h00 = rn_f16(p00), h01 = rn_f16(p01);
                float h02 = rn_f16(p02), h03 = rn_f16(p03);
                float h10 = rn_f16(p10), h11 = rn_f16(p11);
                float h12 = rn_f16(p12), h13 = rn_f16(p13);
                ph[0] = pack_f16(h00, h01);
                ph[1] = pack_f16(h02, h03);
                ph[2] = pack_f16(h10, h11);
                ph[3] = pack_f16(h12, h13);
                pl[0] = pack_f16(p00 - h00, p01 - h01);
                pl[1] = pack_f16(p02 - h02, p03 - h03);
                pl[2] = pack_f16(p10 - h10, p11 - h11);
                pl[3] = pack_f16(p12 - h12, p13 - h13);
            }
            #pragma unroll
            for (int np = 0; np < 8; np++) {
                uint32_t vv[4];
                uint32_t va = sb + 4*FTILE_B +
                    (uint32_t)((kc*16 + (lane & 15))*FS + np*16 + hi8)*2;
                LDM_X4_T(vv, va);
                MMAH16816(o[2*np],   ph, vv[0], vv[1]);
                MMAH16816(o[2*np],   pl, vv[0], vv[1]);
                MMAH16816(o[2*np+1], ph, vv[2], vv[3]);
                MMAH16816(o[2*np+1], pl, vv[2], vv[3]);
            }
        }
    }

    float t0 = l0, t1 = l1;
    t0 += __shfl_xor_sync(0xffffffffu, t0, 1);
    t0 += __shfl_xor_sync(0xffffffffu, t0, 2);
    t1 += __shfl_xor_sync(0xffffffffu, t1, 1);
    t1 += __shfl_xor_sync(0xffffffffu, t1, 2);
    float inv0 = 1.f / t0, inv1 = 1.f / t1;
    int r0 = q0 + w*16 + lr;
    #pragma unroll
    for (int nt = 0; nt < 16; nt++) {
        int c = nt*8 + lc;
        float v0 = o[nt][0]*inv0, v1 = o[nt][1]*inv0;
        float v2 = o[nt][2]*inv1, v3 = o[nt][3]*inv1;
        float h0 = rn_f16(v0), h1 = rn_f16(v1);
        float h2 = rn_f16(v2), h3 = rn_f16(v3);
        size_t off0 = base + (size_t)r0 * NHID + c;
        size_t off1 = base + (size_t)(r0+8) * NHID + c;
        *(uint32_t*)(Ohi + off0) = pack_f16(h0, h1);
        *(uint32_t*)(Olo + off0) = pack_f16(v0 - h0, v1 - h1);
        *(uint32_t*)(Ohi + off1) = pack_f16(h2, h3);
        *(uint32_t*)(Olo + off1) = pack_f16(v2 - h2, v3 - h3);
    }
}

// ---------------- host launcher ----------------
extern "C" void kernel_launch(void* const* d_in, const int* in_sizes, int n_in,
                              void* d_out, int out_size)
{
    const float* x        = (const float*)d_in[0];
    const float* wq_down  = (const float*)d_in[1];
    const float* wq_up    = (const float*)d_in[2];
    const float* wq_rope  = (const float*)d_in[3];
    const float* wk_rope  = (const float*)d_in[4];
    const float* wkv_down = (const float*)d_in[5];
    const float* wk_up    = (const float*)d_in[6];
    const float* wv_up    = (const float*)d_in[7];
    const float* wo       = (const float*)d_in[8];
    const float* bo       = (const float*)d_in[9];
    float* out = (float*)d_out;

    float *krr, *qcr, *kc;
    cudaGetSymbolAddress((void**)&krr, g_krr);
    cudaGetSymbolAddress((void**)&qcr, g_qcr);
    cudaGetSymbolAddress((void**)&kc,  g_kc);

    __half *xs, *wd, *wuq, *wukv, *woh, *lat, *V, *ch, *cl;
    cudaGetSymbolAddress((void**)&xs,   g_xs);
    cudaGetSymbolAddress((void**)&wd,   g_wd);
    cudaGetSymbolAddress((void**)&wuq,  g_wuq);
    cudaGetSymbolAddress((void**)&wukv, g_wukv);
    cudaGetSymbolAddress((void**)&woh,  g_woh);
    cudaGetSymbolAddress((void**)&lat,  g_lat);
    cudaGetSymbolAddress((void**)&V,    g_V);
    cudaGetSymbolAddress((void**)&ch,   g_ch);
    cudaGetSymbolAddress((void**)&cl,   g_cl);

    bf16 *Qh, *Ql, *Kh, *Kl;
    cudaGetSymbolAddress((void**)&Qh, g_Qh);
    cudaGetSymbolAddress((void**)&Ql, g_Ql);
    cudaGetSymbolAddress((void**)&Kh, g_Kh);
    cudaGetSymbolAddress((void**)&Kl, g_Kl);

    const size_t XN   = (size_t)NM*NHID;
    const size_t LATN = (size_t)NM*1024;

    cudaFuncSetAttribute(hgemm_kernel<0>, cudaFuncAttributeMaxDynamicSharedMemorySize, HG_SMEM);
    cudaFuncSetAttribute(hgemm_kernel<1>, cudaFuncAttributeMaxDynamicSharedMemorySize, HG_SMEM);
    cudaFuncSetAttribute(hgemm_kernel<3>, cudaFuncAttributeMaxDynamicSharedMemorySize, HG_SMEM);
    cudaFuncSetAttribute(hgemm_kernel<4>, cudaFuncAttributeMaxDynamicSharedMemorySize, HG_SMEM);
    cudaFuncSetAttribute(flasht_kernel,   cudaFuncAttributeMaxDynamicSharedMemorySize, FL_SMEM);

    dim3 thr(256);
    dim3 gthr(128);

    // (1) RoPE LUT
    rope_lut_kernel<<<256, 256>>>();

    // (2) x split -> fp16 hi/lo
    split4h_kernel<<<(unsigned)(XN/1024), 256>>>((const float4*)x, (uint32_t*)xs, (uint32_t*)(xs + XN));

    // (3) batched weight transpose -> fp16 (all 8 weights incl wk_rope)
    {
        TAll ta;
        const float* srcs[8] = { wq_down, wkv_down, wk_rope, wq_up, wq_rope, wk_up, wv_up, wo };
        __half* dsts[8] = { wd,            wd + (size_t)512*2048,  wd + (size_t)1024*2048,
                            wuq,           wuq + (size_t)1024*512,
                            wukv,          wukv + (size_t)1024*512,
                            woh };
        int Ks[8] = { 2048, 2048, 2048, 512, 512, 512, 512, 2048 };
        int Ns[8] = { 512, 512, 64, 1024, 1024, 1024, 2048, 2048 };
        int total = 0;
        for (int i = 0; i < 8; i++) {
            ta.src[i] = srcs[i]; ta.dst[i] = dsts[i];
            ta.K[i] = Ks[i]; ta.N[i] = Ns[i];
            ta.start[i] = total;
            total += (Ns[i]/32) * (Ks[i]/32);
        }
        ta.start[8] = total;
        wtrans_all_kernel<<<total, dim3(32, 8)>>>(ta);
    }

    // (4) fused down projection + wk_rope: N=1152 (EPI=4)
    //     cols 0-1023 -> fp16 hi/lo latents; cols 1024-1087 -> fp32 krr; rest pad.
    hgemm_kernel<4><<<dim3(9, 64), gthr, HG_SMEM>>>(
        xs, xs + XN, wd,
        krr, lat, lat + LATN, nullptr,
        2048, 2048, 64, 1024, 1024);

    // (5) fused up-q: [qc | qr] fp32 (EPI=0)
    hgemm_kernel<0><<<dim3(16, 64), gthr, HG_SMEM>>>(
        lat, lat + LATN, wuq,
        qcr, nullptr, nullptr, nullptr,
        1024, 512, 2048, 0, 0);

    // (6) fused up-kv: [kc fp32 | V fp16 single] (EPI=3)
    hgemm_kernel<3><<<dim3(24, 64), gthr, HG_SMEM>>>(
        lat + 512, lat + LATN + 512, wukv,
        kc, V, nullptr, nullptr,
        1024, 512, 1024, 2048, 1024);

    // (7) merged RoPE + pack Q/K (bf16 hi/lo)
    pack_qk_kernel<<<(2*NM*NHID)/256, thr>>>();

    // (8) flash attention -> ctx fp16 hi/lo
    flasht_kernel<<<dim3(NS/64, NH, NB), 128, FL_SMEM>>>(Qh, Ql, Kh, Kl, V, ch, cl);

    // (9) asym fp16 output projection + bias (EPI=1)
    hgemm_kernel<1><<<dim3(16, 64), gthr, HG_SMEM>>>(
        ch, cl, woh,
        out, nullptr, nullptr, bo,
        2048, 2048, 2048, 0, 0);
}

// round 14
// speedup vs baseline: 2.2238x; 1.1501x over previous
#include <cuda_runtime.h>
#include <cuda_fp16.h>
#include <math.h>
#include <stdint.h>

#define NB   4
#define NS   2048
#define NH   16
#define NHD  128
#define NRD  64
#define NLAT 512
#define NHID 2048
#define NM   (NB*NS)

// ---------------- device scratch ----------------
__device__ float g_krr [(size_t)NM*NRD];
__device__ float g_qcr [(size_t)NM*2048];
__device__ float g_kc  [(size_t)NM*1024];
__device__ float g_cs  [NS*32];
__device__ float g_sn  [NS*32];

// fp16 operands
__device__ __half g_xs  [2][(size_t)NM*NHID];    // x hi/lo
__device__ __half g_wd  [(size_t)1152*2048];     // [wq_down|wkv_down|wk_rope|pad] T fp16
__device__ __half g_wuq [(size_t)2048*512];      // [wq_up|wq_rope] T fp16
__device__ __half g_wukv[(size_t)3072*512];      // [wk_up|wv_up] T fp16
__device__ __half g_woh [(size_t)2048*2048];     // wo T fp16
__device__ __half g_lat [2][(size_t)NM*1024];    // latents hi/lo fp16
__device__ __half g_V   [(size_t)NM*NHID];       // V single fp16
__device__ __half g_Qs  [(size_t)NM*NHID];       // Q single fp16 (pre-scaled)
__device__ __half g_Ks  [(size_t)NM*NHID];       // K single fp16
__device__ __half g_ch  [(size_t)NM*NHID];       // ctx hi fp16
__device__ __half g_cl  [(size_t)NM*NHID];       // ctx lo fp16

// ---------------- PTX helpers ----------------
__device__ __forceinline__ void cp16(uint32_t s, const void* g) {
    asm volatile("cp.async.cg.shared.global [%0], [%1], 16;\n" :: "r"(s), "l"(g));
}

#define LDM_X4(R, addr) \
    asm volatile("ldmatrix.sync.aligned.m8n8.x4.shared.b16 {%0,%1,%2,%3}, [%4];" \
        : "=r"(R[0]), "=r"(R[1]), "=r"(R[2]), "=r"(R[3]) : "r"(addr))
#define LDM_X4_T(R, addr) \
    asm volatile("ldmatrix.sync.aligned.m8n8.x4.trans.shared.b16 {%0,%1,%2,%3}, [%4];" \
        : "=r"(R[0]), "=r"(R[1]), "=r"(R[2]), "=r"(R[3]) : "r"(addr))
#define MMAH16816(D, A, B0, B1) \
    asm volatile("mma.sync.aligned.m16n8k16.row.col.f32.f16.f16.f32 " \
        "{%0,%1,%2,%3}, {%4,%5,%6,%7}, {%8,%9}, {%0,%1,%2,%3};" \
        : "+f"(D[0]), "+f"(D[1]), "+f"(D[2]), "+f"(D[3]) \
        : "r"(A[0]), "r"(A[1]), "r"(A[2]), "r"(A[3]), "r"(B0), "r"(B1))

__device__ __forceinline__ uint32_t pack_f16(float a, float b) {   // lo=h(a), hi=h(b)
    uint32_t r;
    asm("cvt.rn.f16x2.f32 %0, %1, %2;" : "=r"(r) : "f"(b), "f"(a));
    return r;
}
__device__ __forceinline__ float rn_f16(float f) {
    return __half2float(__float2half_rn(f));
}

// ---------------- x split fp32 -> fp16 hi/lo ----------------
__global__ void split4h_kernel(const float4* __restrict__ in,
                               uint32_t* __restrict__ hi, uint32_t* __restrict__ lo)
{
    size_t i = (size_t)blockIdx.x * blockDim.x + threadIdx.x;
    float4 f = in[i];
    float hx = rn_f16(f.x), hy = rn_f16(f.y), hz = rn_f16(f.z), hw = rn_f16(f.w);
    hi[2*i]   = pack_f16(hx, hy);
    hi[2*i+1] = pack_f16(hz, hw);
    lo[2*i]   = pack_f16(f.x - hx, f.y - hy);
    lo[2*i+1] = pack_f16(f.z - hz, f.w - hw);
}

// batched transpose fp32 [K,N] -> fp16 [N,K], 8 weights in one launch
struct TAll {
    const float* src[8];
    __half* dst[8];
    int K[8];
    int N[8];
    int start[9];
};

__global__ void wtrans_all_kernel(TAll ta)
{
    __shared__ float t[32][33];
    int bid = blockIdx.x;
    int i = 0;
    #pragma unroll
    for (int j = 1; j < 8; j++) if (bid >= ta.start[j]) i = j;
    int lb = bid - ta.start[i];
    int K = ta.K[i], N = ta.N[i];
    int nbx = N >> 5;
    int n0 = (lb % nbx) * 32, k0 = (lb / nbx) * 32;
    const float* src = ta.src[i];
    __half* dst = ta.dst[i];

    int tx = threadIdx.x, ty = threadIdx.y;
    #pragma unroll
    for (int j = 0; j < 4; j++)
        t[ty + j*8][tx] = src[(size_t)(k0 + ty + j*8) * N + n0 + tx];
    __syncthreads();
    #pragma unroll
    for (int j = 0; j < 4; j++)
        dst[(size_t)(n0 + ty + j*8) * K + k0 + tx] = __float2half_rn(t[tx][ty + j*8]);
}

// ---------------- asym fp16 GEMM: A hi/lo fp16, B single fp16 ----------------
// EPI 0: fp32 (Nc). 1: fp32+bias. 2: fp16 hi/lo (Ns).
// EPI 3: mixed (fp32 C < boundary, fp16 single Chi >=).
// EPI 4: mixed (fp16 hi/lo < boundary; fp32 C at cs=cc-boundary if cs<Nc, else discard).
#define SA_ELEMS (128*40)
#define HG_SMEM (6*SA_ELEMS*2)

__device__ __forceinline__ void hgemm_fill(
    uint32_t sb, int buf,
    const __half* __restrict__ Ah, const __half* __restrict__ Al,
    const __half* __restrict__ B,
    int tid, int row0, int col0, int k0, int lda, int ldb)
{
    #pragma unroll
    for (int j = 0; j < 4; j++) {
        int chunk = tid + 128*j;
        int r = chunk >> 2, cc = chunk & 3;
        size_t ga = (size_t)(row0 + r) * lda + k0 + cc*8;
        size_t gb = (size_t)(col0 + r) * ldb + k0 + cc*8;
        uint32_t off = (uint32_t)(r*40 + cc*8)*2;
        cp16(sb + (buf*3+0)*SA_ELEMS*2 + off, Ah + ga);
        cp16(sb + (buf*3+1)*SA_ELEMS*2 + off, Al + ga);
        cp16(sb + (buf*3+2)*SA_ELEMS*2 + off, B + gb);
    }
    asm volatile("cp.async.commit_group;");
}

template<int EPI>
__global__ void __launch_bounds__(128)
hgemm_kernel(const __half* __restrict__ Ah, const __half* __restrict__ Al,
             const __half* __restrict__ B,
             float* __restrict__ C, __half* __restrict__ Chi, __half* __restrict__ Clo,
             const float* __restrict__ bias,
             int lda, int K, int Nc, int Ns, int boundary)
{
    extern __shared__ __half hsm[];
    const uint32_t sb = (uint32_t)__cvta_generic_to_shared(hsm);

    const int tid  = threadIdx.x;
    const int lane = tid & 31;
    const int wid  = tid >> 5;
    const int m0w  = (wid >> 1) * 64;
    const int n0w  = (wid & 1) * 64;
    const int row0 = blockIdx.y * 128;
    const int col0 = blockIdx.x * 128;

    float acc[4][8][4];
    #pragma unroll
    for (int i = 0; i < 4; i++)
        #pragma unroll
        for (int j = 0; j < 8; j++)
            #pragma unroll
            for (int k = 0; k < 4; k++) acc[i][j][k] = 0.f;

    const int niter = K >> 5;
    hgemm_fill(sb, 0, Ah, Al, B, tid, row0, col0, 0, lda, K);

    const int aRow  = m0w + (lane & 15);
    const int aCol8 = 8 * (lane >> 4);
    const int bRow  = n0w + (lane & 15);

    for (int it = 0; it < niter; ++it) {
        const int buf = it & 1;
        if (it + 1 < niter) {
            hgemm_fill(sb, buf ^ 1, Ah, Al, B, tid, row0, col0, (it+1)*32, lda, K);
            asm volatile("cp.async.wait_group 1;");
        } else {
            asm volatile("cp.async.wait_group 0;");
        }
        __syncthreads();

        #pragma unroll
        for (int sub = 0; sub < 32; sub += 16) {
            uint32_t ah[4][4], al[4][4];
            #pragma unroll
            for (int mt = 0; mt < 4; mt++) {
                uint32_t addr = sb +
                    (uint32_t)((buf*3)*SA_ELEMS + (aRow + mt*16)*40 + sub + aCol8)*2;
                LDM_X4(ah[mt], addr);
                LDM_X4(al[mt], addr + SA_ELEMS*2);
            }
            #pragma unroll
            for (int ng = 0; ng < 4; ng++) {
                uint32_t bb[4];
                uint32_t addr = sb +
                    (uint32_t)((buf*3+2)*SA_ELEMS + (bRow + ng*16)*40 + sub + aCol8)*2;
                LDM_X4(bb, addr);
                #pragma unroll
                for (int half = 0; half < 2; half++) {
                    uint32_t b0 = bb[half], b1 = bb[half+2];
                    int nt = ng*2 + half;
                    #pragma unroll
                    for (int mt = 0; mt < 4; mt++) {
                        MMAH16816(acc[mt][nt], ah[mt], b0, b1);
                        MMAH16816(acc[mt][nt], al[mt], b0, b1);
                    }
                }
            }
        }
        __syncthreads();
    }

    const bool fp32_mode = (EPI == 0) || (EPI == 1) || (EPI == 3 && col0 < boundary);
    const bool hilo_mode = (EPI == 2) || (EPI == 4 && col0 < boundary);
    #pragma unroll
    for (int mt = 0; mt < 4; mt++) {
        #pragma unroll
        for (int nt = 0; nt < 8; nt++) {
            int r  = row0 + m0w + mt*16 + (lane >> 2);
            int cc = col0 + n0w + nt*8 + (lane & 3)*2;
            float a0 = acc[mt][nt][0], a1 = acc[mt][nt][1];
            float a2 = acc[mt][nt][2], a3 = acc[mt][nt][3];
            if (fp32_mode) {
                float b0 = 0.f, b1 = 0.f;
                if (EPI == 1) { b0 = bias[cc]; b1 = bias[cc+1]; }
                *(float2*)(C + (size_t)r     * Nc + cc) = make_float2(a0 + b0, a1 + b1);
                *(float2*)(C + (size_t)(r+8) * Nc + cc) = make_float2(a2 + b0, a3 + b1);
            } else if (hilo_mode) {
                float h0 = rn_f16(a0), h1 = rn_f16(a1);
                float h2 = rn_f16(a2), h3 = rn_f16(a3);
                *(uint32_t*)(Chi + (size_t)r     * Ns + cc) = pack_f16(h0, h1);
                *(uint32_t*)(Clo + (size_t)r     * Ns + cc) = pack_f16(a0 - h0, a1 - h1);
                *(uint32_t*)(Chi + (size_t)(r+8) * Ns + cc) = pack_f16(h2, h3);
                *(uint32_t*)(Clo + (size_t)(r+8) * Ns + cc) = pack_f16(a2 - h2, a3 - h3);
            } else if (EPI == 3) {   // fp16 single (V)
                int cs = cc - boundary;
                *(uint32_t*)(Chi + (size_t)r     * Ns + cs) = pack_f16(a0, a1);
                *(uint32_t*)(Chi + (size_t)(r+8) * Ns + cs) = pack_f16(a2, a3);
            } else {                 // EPI == 4, high cols: fp32 krr, pad discarded
                int cs = cc - boundary;
                if (cs < Nc) {
                    *(float2*)(C + (size_t)r     * Nc + cs) = make_float2(a0, a1);
                    *(float2*)(C + (size_t)(r+8) * Nc + cs) = make_float2(a2, a3);
                }
            }
        }
    }
}

// ---------------- RoPE LUT + merged pack (Q/K single fp16) ----------------
__global__ void rope_lut_kernel()
{
    int idx = blockIdx.x * blockDim.x + threadIdx.x;
    int pos = idx >> 5, fi = idx & 31;
    float inv = powf(10000.f, -(float)(2*fi) / 64.f);
    float ang = (float)pos * inv;
    float s, c;
    sincosf(ang, &s, &c);
    g_cs[idx] = c;
    g_sn[idx] = s;
}

__global__ void pack_qk_kernel()
{
    int gidx = blockIdx.x * blockDim.x + threadIdx.x;
    const int TOT = NM * NHID;
    bool isK = gidx >= TOT;
    int idx = isK ? (gidx - TOT) : gidx;
    int row = idx >> 11;
    int c   = idx & (NHID - 1);
    int h = c >> 7, d = c & 127;
    float out;
    if (!isK) {
        if (d < 64) {
            out = g_qcr[(size_t)row*2048 + h*64 + d];
        } else {
            int dd = d - 64;
            const float* qr = g_qcr + (size_t)row*2048 + 1024 + h*64;
            int pos = row & (NS - 1);
            float cs = g_cs[pos*32 + (dd & 31)], sn = g_sn[pos*32 + (dd & 31)];
            float v = qr[dd];
            float w = (dd < 32) ? -qr[dd + 32] : qr[dd - 32];
            out = v * cs + w * sn;
        }
        out *= 0.08838834764831845f;
        g_Qs[idx] = __float2half_rn(out);
    } else {
        if (d < 64) {
            out = g_kc[(size_t)row*1024 + h*64 + d];
        } else {
            int dd = d - 64;
            const float* kr = g_krr + (size_t)row*NRD;
            int pos = row & (NS - 1);
            float cs = g_cs[pos*32 + (dd & 31)], sn = g_sn[pos*32 + (dd & 31)];
            float v = kr[dd];
            float w = (dd < 32) ? -kr[dd + 32] : kr[dd - 32];
            out = v * cs + w * sn;
        }
        g_Ks[idx] = __float2half_rn(out);
    }
}

// ---------------- flash attention: all-single-fp16 (Q,K,V,P) ----------------
#define FS 136
#define FTILE_B (64*FS*2)
#define FL_SMEM (3*FTILE_B)   // Q, K, V single fp16 tiles

__global__ void __launch_bounds__(128)
flasht_kernel(const __half* __restrict__ Q, const __half* __restrict__ K,
              const __half* __restrict__ V,
              __half* __restrict__ Ohi, __half* __restrict__ Olo)
{
    extern __shared__ __half fsm[];
    const uint32_t sb = (uint32_t)__cvta_generic_to_shared(fsm);

    const int tid = threadIdx.x;
    const int lane = tid & 31;
    const int w = tid >> 5;
    const int lr = lane >> 2;
    const int lc = (lane & 3) * 2;
    const int h = blockIdx.y, b = blockIdx.z;
    const int q0 = blockIdx.x * 64;
    const size_t base = ((size_t)b * NS) * NHID + (size_t)h * NHD;

    for (int i = tid; i < 1024; i += 128) {
        int r = i >> 4, c = (i & 15) << 3;
        uint32_t so = (uint32_t)(r*FS + c) * 2;
        cp16(sb + so, Q + base + (size_t)(q0 + r) * NHID + c);
    }
    asm volatile("cp.async.commit_group;");

    float m0 = -1e30f, m1 = -1e30f, l0 = 0.f, l1 = 0.f;
    float o[16][4];
    #pragma unroll
    for (int i = 0; i < 16; i++)
        #pragma unroll
        for (int j = 0; j < 4; j++) o[i][j] = 0.f;

    const int aRow = w*16 + (lane & 15);
    const int hi8  = 8 * (lane >> 4);
    const int ntiles = blockIdx.x + 1;

    for (int t = 0; t < ntiles; t++) {
        const int k0 = t * 64;
        if (t) __syncthreads();
        for (int i = tid; i < 1024; i += 128) {
            int r = i >> 4, c = (i & 15) << 3;
            uint32_t so = (uint32_t)(r*FS + c) * 2;
            size_t go = base + (size_t)(k0 + r) * NHID + c;
            cp16(sb + 1*FTILE_B + so, K + go);
            cp16(sb + 2*FTILE_B + so, V + go);
        }
        asm volatile("cp.async.commit_group;");
        asm volatile("cp.async.wait_group 0;");
        __syncthreads();

        float s[8][4];
        #pragma unroll
        for (int i = 0; i < 8; i++)
            #pragma unroll
            for (int j = 0; j < 4; j++) s[i][j] = 0.f;

        // ---- S = Q K^T, single fp16, 1 MMA per fragment ----
        #pragma unroll
        for (int kc = 0; kc < 8; kc++) {
            uint32_t qs[4];
            LDM_X4(qs, sb + (uint32_t)(aRow*FS + kc*16 + hi8)*2);
            #pragma unroll
            for (int g = 0; g < 4; g++) {
                uint32_t ks[4];
                LDM_X4(ks, sb + 1*FTILE_B + (uint32_t)((g*16 + (lane & 15))*FS + kc*16 + hi8)*2);
                MMAH16816(s[2*g],   qs, ks[0], ks[2]);
                MMAH16816(s[2*g+1], qs, ks[1], ks[3]);
            }
        }

        if (t == blockIdx.x) {
            int r0 = q0 + w*16 + lr, r1 = r0 + 8;
            #pragma unroll
            for (int nt = 0; nt < 8; nt++) {
                int c = k0 + nt*8 + lc;
                if (c     > r0) s[nt][0] = -1e30f;
                if (c + 1 > r0) s[nt][1] = -1e30f;
                if (c     > r1) s[nt][2] = -1e30f;
                if (c + 1 > r1) s[nt][3] = -1e30f;
            }
        }

        float mt0 = -1e30f, mt1 = -1e30f;
        #pragma unroll
        for (int nt = 0; nt < 8; nt++) {
            mt0 = fmaxf(mt0, fmaxf(s[nt][0], s[nt][1]));
            mt1 = fmaxf(mt1, fmaxf(s[nt][2], s[nt][3]));
        }
        mt0 = fmaxf(mt0, __shfl_xor_sync(0xffffffffu, mt0, 1));
        mt0 = fmaxf(mt0, __shfl_xor_sync(0xffffffffu, mt0, 2));
        mt1 = fmaxf(mt1, __shfl_xor_sync(0xffffffffu, mt1, 1));
        mt1 = fmaxf(mt1, __shfl_xor_sync(0xffffffffu, mt1, 2));
        float n0 = fmaxf(m0, mt0), n1 = fmaxf(m1, mt1);
        float corr0 = __expf(m0 - n0), corr1 = __expf(m1 - n1);
        m0 = n0; m1 = n1;

        float ps0 = 0.f, ps1 = 0.f;
        #pragma unroll
        for (int nt = 0; nt < 8; nt++) {
            s[nt][0] = __expf(s[nt][0] - n0);
            s[nt][1] = __expf(s[nt][1] - n0);
            s[nt][2] = __expf(s[nt][2] - n1);
            s[nt][3] = __expf(s[nt][3] - n1);
            ps0 += s[nt][0] + s[nt][1];
            ps1 += s[nt][2] + s[nt][3];
        }
        l0 = l0 * corr0 + ps0;
        l1 = l1 * corr1 + ps1;
        #pragma unroll
        for (int i = 0; i < 16; i++) {
            o[i][0] *= corr0; o[i][1] *= corr0;
            o[i][2] *= corr1; o[i][3] *= corr1;
        }

        // ---- O += P V : P single fp16, V single fp16, 1 MMA per fragment ----
        #pragma unroll
        for (int kc = 0; kc < 4; kc++) {
            uint32_t ph[4];
            ph[0] = pack_f16(s[2*kc][0],   s[2*kc][1]);
            ph[1] = pack_f16(s[2*kc][2],   s[2*kc][3]);
            ph[2] = pack_f16(s[2*kc+1][0], s[2*kc+1][1]);
            ph[3] = pack_f16(s[2*kc+1][2], s[2*kc+1][3]);
            #pragma unroll
            for (int np = 0; np < 8; np++) {
                uint32_t vv[4];
                LDM_X4_T(vv, sb + 2*FTILE_B +
                    (uint32_t)((kc*16 + (lane & 15))*FS + np*16 + hi8)*2);
                MMAH16816(o[2*np],   ph, vv[0], vv[1]);
                MMAH16816(o[2*np+1], ph, vv[2], vv[3]);
            }
        }
    }

    float t0 = l0, t1 = l1;
    t0 += __shfl_xor_sync(0xffffffffu, t0, 1);
    t0 += __shfl_xor_sync(0xffffffffu, t0, 2);
    t1 += __shfl_xor_sync(0xffffffffu, t1, 1);
    t1 += __shfl_xor_sync(0xffffffffu, t1, 2);
    float inv0 = 1.f / t0, inv1 = 1.f / t1;
    int r0 = q0 + w*16 + lr;
    #pragma unroll
    for (int nt = 0; nt < 16; nt++) {
        int c = nt*8 + lc;
        float v0 = o[nt][0]*inv0, v1 = o[nt][1]*inv0;
        float v2 = o[nt][2]*inv1, v3 = o[nt][3]*inv1;
        float h0 = rn_f16(v0), h1 = rn_f16(v1);
        float h2 = rn_f16(v2), h3 = rn_f16(v3);
        size_t off0 = base + (size_t)r0 * NHID + c;
        size_t off1 = base + (size_t)(r0+8) * NHID + c;
        *(uint32_t*)(Ohi + off0) = pack_f16(h0, h1);
        *(uint32_t*)(Olo + off0) = pack_f16(v0 - h0, v1 - h1);
        *(uint32_t*)(Ohi + off1) = pack_f16(h2, h3);
        *(uint32_t*)(Olo + off1) = pack_f16(v2 - h2, v3 - h3);
    }
}

// ---------------- host launcher ----------------
extern "C" void kernel_launch(void* const* d_in, const int* in_sizes, int n_in,
                              void* d_out, int out_size)
{
    const float* x        = (const float*)d_in[0];
    const float* wq_down  = (const float*)d_in[1];
    const float* wq_up    = (const float*)d_in[2];
    const float* wq_rope  = (const float*)d_in[3];
    const float* wk_rope  = (const float*)d_in[4];
    const float* wkv_down = (const float*)d_in[5];
    const float* wk_up    = (const float*)d_in[6];
    const float* wv_up    = (const float*)d_in[7];
    const float* wo       = (const float*)d_in[8];
    const float* bo       = (const float*)d_in[9];
    float* out = (float*)d_out;

    float *krr, *qcr, *kc;
    cudaGetSymbolAddress((void**)&krr, g_krr);
    cudaGetSymbolAddress((void**)&qcr, g_qcr);
    cudaGetSymbolAddress((void**)&kc,  g_kc);

    __half *xs, *wd, *wuq, *wukv, *woh, *lat, *V, *Qs, *Ks, *ch, *cl;
    cudaGetSymbolAddress((void**)&xs,   g_xs);
    cudaGetSymbolAddress((void**)&wd,   g_wd);
    cudaGetSymbolAddress((void**)&wuq,  g_wuq);
    cudaGetSymbolAddress((void**)&wukv, g_wukv);
    cudaGetSymbolAddress((void**)&woh,  g_woh);
    cudaGetSymbolAddress((void**)&lat,  g_lat);
    cudaGetSymbolAddress((void**)&V,    g_V);
    cudaGetSymbolAddress((void**)&Qs,   g_Qs);
    cudaGetSymbolAddress((void**)&Ks,   g_Ks);
    cudaGetSymbolAddress((void**)&ch,   g_ch);
    cudaGetSymbolAddress((void**)&cl,   g_cl);

    const size_t XN   = (size_t)NM*NHID;
    const size_t LATN = (size_t)NM*1024;

    cudaFuncSetAttribute(hgemm_kernel<0>, cudaFuncAttributeMaxDynamicSharedMemorySize, HG_SMEM);
    cudaFuncSetAttribute(hgemm_kernel<1>, cudaFuncAttributeMaxDynamicSharedMemorySize, HG_SMEM);
    cudaFuncSetAttribute(hgemm_kernel<3>, cudaFuncAttributeMaxDynamicSharedMemorySize, HG_SMEM);
    cudaFuncSetAttribute(hgemm_kernel<4>, cudaFuncAttributeMaxDynamicSharedMemorySize, HG_SMEM);
    cudaFuncSetAttribute(flasht_kernel,   cudaFuncAttributeMaxDynamicSharedMemorySize, FL_SMEM);

    dim3 thr(256);
    dim3 gthr(128);

    // (1) RoPE LUT
    rope_lut_kernel<<<256, 256>>>();

    // (2) x split -> fp16 hi/lo
    split4h_kernel<<<(unsigned)(XN/1024), 256>>>((const float4*)x, (uint32_t*)xs, (uint32_t*)(xs + XN));

    // (3) batched weight transpose -> fp16 (all 8 weights incl wk_rope)
    {
        TAll ta;
        const float* srcs[8] = { wq_down, wkv_down, wk_rope, wq_up, wq_rope, wk_up, wv_up, wo };
        __half* dsts[8] = { wd,            wd + (size_t)512*2048,  wd + (size_t)1024*2048,
                            wuq,           wuq + (size_t)1024*512,
                            wukv,          wukv + (size_t)1024*512,
                            woh };
        int Ks_[8] = { 2048, 2048, 2048, 512, 512, 512, 512, 2048 };
        int Ns_[8] = { 512, 512, 64, 1024, 1024, 1024, 2048, 2048 };
        int total = 0;
        for (int i = 0; i < 8; i++) {
            ta.src[i] = srcs[i]; ta.dst[i] = dsts[i];
            ta.K[i] = Ks_[i]; ta.N[i] = Ns_[i];
            ta.start[i] = total;
            total += (Ns_[i]/32) * (Ks_[i]/32);
        }
        ta.start[8] = total;
        wtrans_all_kernel<<<total, dim3(32, 8)>>>(ta);
    }

    // (4) fused down projection + wk_rope: N=1152 (EPI=4)
    hgemm_kernel<4><<<dim3(9, 64), gthr, HG_SMEM>>>(
        xs, xs + XN, wd,
        krr, lat, lat + LATN, nullptr,
        2048, 2048, 64, 1024, 1024);

    // (5) fused up-q: [qc | qr] fp32 (EPI=0)
    hgemm_kernel<0><<<dim3(16, 64), gthr, HG_SMEM>>>(
        lat, lat + LATN, wuq,
        qcr, nullptr, nullptr, nullptr,
        1024, 512, 2048, 0, 0);

    // (6) fused up-kv: [kc fp32 | V fp16 single] (EPI=3)
    hgemm_kernel<3><<<dim3(24, 64), gthr, HG_SMEM>>>(
        lat + 512, lat + LATN + 512, wukv,
        kc, V, nullptr, nullptr,
        1024, 512, 1024, 2048, 1024);

    // (7) merged RoPE + pack Q/K -> single fp16
    pack_qk_kernel<<<(2*NM*NHID)/256, thr>>>();

    // (8) flash attention (all-single fp16) -> ctx fp16 hi/lo
    flasht_kernel<<<dim3(NS/64, NH, NB), 128, FL_SMEM>>>(Qs, Ks, V, ch, cl);

    // (9) asym fp16 output projection + bias (EPI=1)
    hgemm_kernel<1><<<dim3(16, 64), gthr, HG_SMEM>>>(
        ch, cl, woh,
        out, nullptr, nullptr, bo,
        2048, 2048, 2048, 0, 0);
}

// round 15
// speedup vs baseline: 3.2596x; 1.4657x over previous
#include <cuda_runtime.h>
#include <cuda_fp16.h>
#include <math.h>
#include <stdint.h>

#define NB   4
#define NS   2048
#define NH   16
#define NHD  128
#define NRD  64
#define NLAT 512
#define NHID 2048
#define NM   (NB*NS)

// ---------------- device scratch ----------------
__device__ float g_krr [(size_t)NM*NRD];
__device__ float g_qcr [(size_t)NM*2048];
__device__ float g_kc  [(size_t)NM*1024];
__device__ float g_cs  [NS*32];
__device__ float g_sn  [NS*32];

// fp16 operands (all single precision fp16)
__device__ __half g_xs  [(size_t)NM*NHID];     // x fp16
__device__ __half g_wd  [(size_t)1152*2048];   // [wq_down|wkv_down|wk_rope|pad] T
__device__ __half g_wuq [(size_t)2048*512];    // [wq_up|wq_rope] T
__device__ __half g_wukv[(size_t)3072*512];    // [wk_up|wv_up] T
__device__ __half g_woh [(size_t)2048*2048];   // wo T
__device__ __half g_lat [(size_t)NM*1024];     // latents
__device__ __half g_V   [(size_t)NM*NHID];     // V
__device__ __half g_Qs  [(size_t)NM*NHID];     // Q (pre-scaled)
__device__ __half g_Ks  [(size_t)NM*NHID];     // K
__device__ __half g_ch  [(size_t)NM*NHID];     // ctx

// ---------------- PTX helpers ----------------
__device__ __forceinline__ void cp16(uint32_t s, const void* g) {
    asm volatile("cp.async.cg.shared.global [%0], [%1], 16;\n" :: "r"(s), "l"(g));
}

#define LDM_X4(R, addr) \
    asm volatile("ldmatrix.sync.aligned.m8n8.x4.shared.b16 {%0,%1,%2,%3}, [%4];" \
        : "=r"(R[0]), "=r"(R[1]), "=r"(R[2]), "=r"(R[3]) : "r"(addr))
#define LDM_X4_T(R, addr) \
    asm volatile("ldmatrix.sync.aligned.m8n8.x4.trans.shared.b16 {%0,%1,%2,%3}, [%4];" \
        : "=r"(R[0]), "=r"(R[1]), "=r"(R[2]), "=r"(R[3]) : "r"(addr))
#define MMAH16816(D, A, B0, B1) \
    asm volatile("mma.sync.aligned.m16n8k16.row.col.f32.f16.f16.f32 " \
        "{%0,%1,%2,%3}, {%4,%5,%6,%7}, {%8,%9}, {%0,%1,%2,%3};" \
        : "+f"(D[0]), "+f"(D[1]), "+f"(D[2]), "+f"(D[3]) \
        : "r"(A[0]), "r"(A[1]), "r"(A[2]), "r"(A[3]), "r"(B0), "r"(B1))

__device__ __forceinline__ uint32_t pack_f16(float a, float b) {   // lo=h(a), hi=h(b)
    uint32_t r;
    asm("cvt.rn.f16x2.f32 %0, %1, %2;" : "=r"(r) : "f"(b), "f"(a));
    return r;
}

// ---------------- x convert fp32 -> fp16 ----------------
__global__ void cvt4h_kernel(const float4* __restrict__ in, uint32_t* __restrict__ out)
{
    size_t i = (size_t)blockIdx.x * blockDim.x + threadIdx.x;
    float4 f = in[i];
    out[2*i]   = pack_f16(f.x, f.y);
    out[2*i+1] = pack_f16(f.z, f.w);
}

// batched transpose fp32 [K,N] -> fp16 [N,K], 8 weights in one launch
struct TAll {
    const float* src[8];
    __half* dst[8];
    int K[8];
    int N[8];
    int start[9];
};

__global__ void wtrans_all_kernel(TAll ta)
{
    __shared__ float t[32][33];
    int bid = blockIdx.x;
    int i = 0;
    #pragma unroll
    for (int j = 1; j < 8; j++) if (bid >= ta.start[j]) i = j;
    int lb = bid - ta.start[i];
    int K = ta.K[i], N = ta.N[i];
    int nbx = N >> 5;
    int n0 = (lb % nbx) * 32, k0 = (lb / nbx) * 32;
    const float* src = ta.src[i];
    __half* dst = ta.dst[i];

    int tx = threadIdx.x, ty = threadIdx.y;
    #pragma unroll
    for (int j = 0; j < 4; j++)
        t[ty + j*8][tx] = src[(size_t)(k0 + ty + j*8) * N + n0 + tx];
    __syncthreads();
    #pragma unroll
    for (int j = 0; j < 4; j++)
        dst[(size_t)(n0 + ty + j*8) * K + k0 + tx] = __float2half_rn(t[tx][ty + j*8]);
}

// ---------------- single-fp16 GEMM: A fp16, B fp16, 1 MMA per k16 ----------------
// C[M,N] = A[M,K(lda)] @ Bt[N,K]^T. Block 128x128, BK=32, 128 thr, warp 64x64.
// EPI 0: fp32 (Nc). 1: fp32+bias. 3: mixed (fp32 C < boundary; fp16 Ch at Ns >=).
// EPI 4: mixed (fp16 Ch at Ns < boundary; fp32 C at cs<Nc >=, else discard).
#define SA_ELEMS (128*40)
#define HG_SMEM (4*SA_ELEMS*2)   // 40960 B

__device__ __forceinline__ void hgemm_fill(
    uint32_t sb, int buf,
    const __half* __restrict__ A, const __half* __restrict__ B,
    int tid, int row0, int col0, int k0, int lda, int ldb)
{
    #pragma unroll
    for (int j = 0; j < 4; j++) {
        int chunk = tid + 128*j;
        int r = chunk >> 2, cc = chunk & 3;
        size_t ga = (size_t)(row0 + r) * lda + k0 + cc*8;
        size_t gb = (size_t)(col0 + r) * ldb + k0 + cc*8;
        uint32_t off = (uint32_t)(r*40 + cc*8)*2;
        cp16(sb + (buf*2+0)*SA_ELEMS*2 + off, A + ga);
        cp16(sb + (buf*2+1)*SA_ELEMS*2 + off, B + gb);
    }
    asm volatile("cp.async.commit_group;");
}

template<int EPI>
__global__ void __launch_bounds__(128)
hgemm_kernel(const __half* __restrict__ A, const __half* __restrict__ B,
             float* __restrict__ C, __half* __restrict__ Ch,
             const float* __restrict__ bias,
             int lda, int K, int Nc, int Ns, int boundary)
{
    extern __shared__ __half hsm[];
    const uint32_t sb = (uint32_t)__cvta_generic_to_shared(hsm);

    const int tid  = threadIdx.x;
    const int lane = tid & 31;
    const int wid  = tid >> 5;
    const int m0w  = (wid >> 1) * 64;
    const int n0w  = (wid & 1) * 64;
    const int row0 = blockIdx.y * 128;
    const int col0 = blockIdx.x * 128;

    float acc[4][8][4];
    #pragma unroll
    for (int i = 0; i < 4; i++)
        #pragma unroll
        for (int j = 0; j < 8; j++)
            #pragma unroll
            for (int k = 0; k < 4; k++) acc[i][j][k] = 0.f;

    const int niter = K >> 5;
    hgemm_fill(sb, 0, A, B, tid, row0, col0, 0, lda, K);

    const int aRow  = m0w + (lane & 15);
    const int aCol8 = 8 * (lane >> 4);
    const int bRow  = n0w + (lane & 15);

    for (int it = 0; it < niter; ++it) {
        const int buf = it & 1;
        if (it + 1 < niter) {
            hgemm_fill(sb, buf ^ 1, A, B, tid, row0, col0, (it+1)*32, lda, K);
            asm volatile("cp.async.wait_group 1;");
        } else {
            asm volatile("cp.async.wait_group 0;");
        }
        __syncthreads();

        #pragma unroll
        for (int sub = 0; sub < 32; sub += 16) {
            uint32_t ah[4][4];
            #pragma unroll
            for (int mt = 0; mt < 4; mt++) {
                LDM_X4(ah[mt], sb +
                    (uint32_t)((buf*2)*SA_ELEMS + (aRow + mt*16)*40 + sub + aCol8)*2);
            }
            // B non-trans ldmatrix on K-major: pairs n0-7 -> (r0,r2); n8-15 -> (r1,r3)
            #pragma unroll
            for (int ng = 0; ng < 4; ng++) {
                uint32_t bb[4];
                LDM_X4(bb, sb +
                    (uint32_t)((buf*2+1)*SA_ELEMS + (bRow + ng*16)*40 + sub + aCol8)*2);
                #pragma unroll
                for (int half = 0; half < 2; half++) {
                    uint32_t b0 = bb[half], b1 = bb[half+2];
                    int nt = ng*2 + half;
                    #pragma unroll
                    for (int mt = 0; mt < 4; mt++)
                        MMAH16816(acc[mt][nt], ah[mt], b0, b1);
                }
            }
        }
        __syncthreads();
    }

    const bool fp32_mode = (EPI == 0) || (EPI == 1) || (EPI == 3 && col0 < boundary);
    const bool f16_mode  = (EPI == 4 && col0 < boundary) || (EPI == 3 && col0 >= boundary);
    #pragma unroll
    for (int mt = 0; mt < 4; mt++) {
        #pragma unroll
        for (int nt = 0; nt < 8; nt++) {
            int r  = row0 + m0w + mt*16 + (lane >> 2);
            int cc = col0 + n0w + nt*8 + (lane & 3)*2;
            float a0 = acc[mt][nt][0], a1 = acc[mt][nt][1];
            float a2 = acc[mt][nt][2], a3 = acc[mt][nt][3];
            if (fp32_mode) {
                float b0 = 0.f, b1 = 0.f;
                if (EPI == 1) { b0 = bias[cc]; b1 = bias[cc+1]; }
                *(float2*)(C + (size_t)r     * Nc + cc) = make_float2(a0 + b0, a1 + b1);
                *(float2*)(C + (size_t)(r+8) * Nc + cc) = make_float2(a2 + b0, a3 + b1);
            } else if (f16_mode) {
                int cs = (EPI == 3) ? (cc - boundary) : cc;
                *(uint32_t*)(Ch + (size_t)r     * Ns + cs) = pack_f16(a0, a1);
                *(uint32_t*)(Ch + (size_t)(r+8) * Ns + cs) = pack_f16(a2, a3);
            } else {   // EPI == 4 high cols: fp32 krr, pad discarded
                int cs = cc - boundary;
                if (cs < Nc) {
                    *(float2*)(C + (size_t)r     * Nc + cs) = make_float2(a0, a1);
                    *(float2*)(C + (size_t)(r+8) * Nc + cs) = make_float2(a2, a3);
                }
            }
        }
    }
}

// ---------------- RoPE LUT + merged pack (Q/K single fp16) ----------------
__global__ void rope_lut_kernel()
{
    int idx = blockIdx.x * blockDim.x + threadIdx.x;
    int pos = idx >> 5, fi = idx & 31;
    float inv = powf(10000.f, -(float)(2*fi) / 64.f);
    float ang = (float)pos * inv;
    float s, c;
    sincosf(ang, &s, &c);
    g_cs[idx] = c;
    g_sn[idx] = s;
}

__global__ void pack_qk_kernel()
{
    int gidx = blockIdx.x * blockDim.x + threadIdx.x;
    const int TOT = NM * NHID;
    bool isK = gidx >= TOT;
    int idx = isK ? (gidx - TOT) : gidx;
    int row = idx >> 11;
    int c   = idx & (NHID - 1);
    int h = c >> 7, d = c & 127;
    float out;
    if (!isK) {
        if (d < 64) {
            out = g_qcr[(size_t)row*2048 + h*64 + d];
        } else {
            int dd = d - 64;
            const float* qr = g_qcr + (size_t)row*2048 + 1024 + h*64;
            int pos = row & (NS - 1);
            float cs = g_cs[pos*32 + (dd & 31)], sn = g_sn[pos*32 + (dd & 31)];
            float v = qr[dd];
            float w = (dd < 32) ? -qr[dd + 32] : qr[dd - 32];
            out = v * cs + w * sn;
        }
        out *= 0.08838834764831845f;
        g_Qs[idx] = __float2half_rn(out);
    } else {
        if (d < 64) {
            out = g_kc[(size_t)row*1024 + h*64 + d];
        } else {
            int dd = d - 64;
            const float* kr = g_krr + (size_t)row*NRD;
            int pos = row & (NS - 1);
            float cs = g_cs[pos*32 + (dd & 31)], sn = g_sn[pos*32 + (dd & 31)];
            float v = kr[dd];
            float w = (dd < 32) ? -kr[dd + 32] : kr[dd - 32];
            out = v * cs + w * sn;
        }
        g_Ks[idx] = __float2half_rn(out);
    }
}

// ---------------- flash attention: all-single-fp16, ctx single fp16 out ----------------
#define FS 136
#define FTILE_B (64*FS*2)
#define FL_SMEM (3*FTILE_B)

__global__ void __launch_bounds__(128)
flasht_kernel(const __half* __restrict__ Q, const __half* __restrict__ K,
              const __half* __restrict__ V, __half* __restrict__ O)
{
    extern __shared__ __half fsm[];
    const uint32_t sb = (uint32_t)__cvta_generic_to_shared(fsm);

    const int tid = threadIdx.x;
    const int lane = tid & 31;
    const int w = tid >> 5;
    const int lr = lane >> 2;
    const int lc = (lane & 3) * 2;
    const int h = blockIdx.y, b = blockIdx.z;
    const int q0 = blockIdx.x * 64;
    const size_t base = ((size_t)b * NS) * NHID + (size_t)h * NHD;

    for (int i = tid; i < 1024; i += 128) {
        int r = i >> 4, c = (i & 15) << 3;
        uint32_t so = (uint32_t)(r*FS + c) * 2;
        cp16(sb + so, Q + base + (size_t)(q0 + r) * NHID + c);
    }
    asm volatile("cp.async.commit_group;");

    float m0 = -1e30f, m1 = -1e30f, l0 = 0.f, l1 = 0.f;
    float o[16][4];
    #pragma unroll
    for (int i = 0; i < 16; i++)
        #pragma unroll
        for (int j = 0; j < 4; j++) o[i][j] = 0.f;

    const int aRow = w*16 + (lane & 15);
    const int hi8  = 8 * (lane >> 4);
    const int ntiles = blockIdx.x + 1;

    for (int t = 0; t < ntiles; t++) {
        const int k0 = t * 64;
        if (t) __syncthreads();
        for (int i = tid; i < 1024; i += 128) {
            int r = i >> 4, c = (i & 15) << 3;
            uint32_t so = (uint32_t)(r*FS + c) * 2;
            size_t go = base + (size_t)(k0 + r) * NHID + c;
            cp16(sb + 1*FTILE_B + so, K + go);
            cp16(sb + 2*FTILE_B + so, V + go);
        }
        asm volatile("cp.async.commit_group;");
        asm volatile("cp.async.wait_group 0;");
        __syncthreads();

        float s[8][4];
        #pragma unroll
        for (int i = 0; i < 8; i++)
            #pragma unroll
            for (int j = 0; j < 4; j++) s[i][j] = 0.f;

        #pragma unroll
        for (int kc = 0; kc < 8; kc++) {
            uint32_t qs[4];
            LDM_X4(qs, sb + (uint32_t)(aRow*FS + kc*16 + hi8)*2);
            #pragma unroll
            for (int g = 0; g < 4; g++) {
                uint32_t ks[4];
                LDM_X4(ks, sb + 1*FTILE_B + (uint32_t)((g*16 + (lane & 15))*FS + kc*16 + hi8)*2);
                MMAH16816(s[2*g],   qs, ks[0], ks[2]);
                MMAH16816(s[2*g+1], qs, ks[1], ks[3]);
            }
        }

        if (t == blockIdx.x) {
            int r0 = q0 + w*16 + lr, r1 = r0 + 8;
            #pragma unroll
            for (int nt = 0; nt < 8; nt++) {
                int c = k0 + nt*8 + lc;
                if (c     > r0) s[nt][0] = -1e30f;
                if (c + 1 > r0) s[nt][1] = -1e30f;
                if (c     > r1) s[nt][2] = -1e30f;
                if (c + 1 > r1) s[nt][3] = -1e30f;
            }
        }

        float mt0 = -1e30f, mt1 = -1e30f;
        #pragma unroll
        for (int nt = 0; nt < 8; nt++) {
            mt0 = fmaxf(mt0, fmaxf(s[nt][0], s[nt][1]));
            mt1 = fmaxf(mt1, fmaxf(s[nt][2], s[nt][3]));
        }
        mt0 = fmaxf(mt0, __shfl_xor_sync(0xffffffffu, mt0, 1));
        mt0 = fmaxf(mt0, __shfl_xor_sync(0xffffffffu, mt0, 2));
        mt1 = fmaxf(mt1, __shfl_xor_sync(0xffffffffu, mt1, 1));
        mt1 = fmaxf(mt1, __shfl_xor_sync(0xffffffffu, mt1, 2));
        float n0 = fmaxf(m0, mt0), n1 = fmaxf(m1, mt1);
        float corr0 = __expf(m0 - n0), corr1 = __expf(m1 - n1);
        m0 = n0; m1 = n1;

        float ps0 = 0.f, ps1 = 0.f;
        #pragma unroll
        for (int nt = 0; nt < 8; nt++) {
            s[nt][0] = __expf(s[nt][0] - n0);
            s[nt][1] = __expf(s[nt][1] - n0);
            s[nt][2] = __expf(s[nt][2] - n1);
            s[nt][3] = __expf(s[nt][3] - n1);
            ps0 += s[nt][0] + s[nt][1];
            ps1 += s[nt][2] + s[nt][3];
        }
        l0 = l0 * corr0 + ps0;
        l1 = l1 * corr1 + ps1;
        #pragma unroll
        for (int i = 0; i < 16; i++) {
            o[i][0] *= corr0; o[i][1] *= corr0;
            o[i][2] *= corr1; o[i][3] *= corr1;
        }

        #pragma unroll
        for (int kc = 0; kc < 4; kc++) {
            uint32_t ph[4];
            ph[0] = pack_f16(s[2*kc][0],   s[2*kc][1]);
            ph[1] = pack_f16(s[2*kc][2],   s[2*kc][3]);
            ph[2] = pack_f16(s[2*kc+1][0], s[2*kc+1][1]);
            ph[3] = pack_f16(s[2*kc+1][2], s[2*kc+1][3]);
            #pragma unroll
            for (int np = 0; np < 8; np++) {
                uint32_t vv[4];
                LDM_X4_T(vv, sb + 2*FTILE_B +
                    (uint32_t)((kc*16 + (lane & 15))*FS + np*16 + hi8)*2);
                MMAH16816(o[2*np],   ph, vv[0], vv[1]);
                MMAH16816(o[2*np+1], ph, vv[2], vv[3]);
            }
        }
    }

    float t0 = l0, t1 = l1;
    t0 += __shfl_xor_sync(0xffffffffu, t0, 1);
    t0 += __shfl_xor_sync(0xffffffffu, t0, 2);
    t1 += __shfl_xor_sync(0xffffffffu, t1, 1);
    t1 += __shfl_xor_sync(0xffffffffu, t1, 2);
    float inv0 = 1.f / t0, inv1 = 1.f / t1;
    int r0 = q0 + w*16 + lr;
    #pragma unroll
    for (int nt = 0; nt < 16; nt++) {
        int c = nt*8 + lc;
        size_t off0 = base + (size_t)r0 * NHID + c;
        size_t off1 = base + (size_t)(r0+8) * NHID + c;
        *(uint32_t*)(O + off0) = pack_f16(o[nt][0]*inv0, o[nt][1]*inv0);
        *(uint32_t*)(O + off1) = pack_f16(o[nt][2]*inv1, o[nt][3]*inv1);
    }
}

// ---------------- host launcher ----------------
extern "C" void kernel_launch(void* const* d_in, const int* in_sizes, int n_in,
                              void* d_out, int out_size)
{
    const float* x        = (const float*)d_in[0];
    const float* wq_down  = (const float*)d_in[1];
    const float* wq_up    = (const float*)d_in[2];
    const float* wq_rope  = (const float*)d_in[3];
    const float* wk_rope  = (const float*)d_in[4];
    const float* wkv_down = (const float*)d_in[5];
    const float* wk_up    = (const float*)d_in[6];
    const float* wv_up    = (const float*)d_in[7];
    const float* wo       = (const float*)d_in[8];
    const float* bo       = (const float*)d_in[9];
    float* out = (float*)d_out;

    float *krr, *qcr, *kc;
    cudaGetSymbolAddress((void**)&krr, g_krr);
    cudaGetSymbolAddress((void**)&qcr, g_qcr);
    cudaGetSymbolAddress((void**)&kc,  g_kc);

    __half *xs, *wd, *wuq, *wukv, *woh, *lat, *V, *Qs, *Ks, *ch;
    cudaGetSymbolAddress((void**)&xs,   g_xs);
    cudaGetSymbolAddress((void**)&wd,   g_wd);
    cudaGetSymbolAddress((void**)&wuq,  g_wuq);
    cudaGetSymbolAddress((void**)&wukv, g_wukv);
    cudaGetSymbolAddress((void**)&woh,  g_woh);
    cudaGetSymbolAddress((void**)&lat,  g_lat);
    cudaGetSymbolAddress((void**)&V,    g_V);
    cudaGetSymbolAddress((void**)&Qs,   g_Qs);
    cudaGetSymbolAddress((void**)&Ks,   g_Ks);
    cudaGetSymbolAddress((void**)&ch,   g_ch);

    const size_t XN = (size_t)NM*NHID;

    cudaFuncSetAttribute(hgemm_kernel<0>, cudaFuncAttributeMaxDynamicSharedMemorySize, HG_SMEM);
    cudaFuncSetAttribute(hgemm_kernel<1>, cudaFuncAttributeMaxDynamicSharedMemorySize, HG_SMEM);
    cudaFuncSetAttribute(hgemm_kernel<3>, cudaFuncAttributeMaxDynamicSharedMemorySize, HG_SMEM);
    cudaFuncSetAttribute(hgemm_kernel<4>, cudaFuncAttributeMaxDynamicSharedMemorySize, HG_SMEM);
    cudaFuncSetAttribute(flasht_kernel,   cudaFuncAttributeMaxDynamicSharedMemorySize, FL_SMEM);

    dim3 thr(256);
    dim3 gthr(128);

    // (1) RoPE LUT
    rope_lut_kernel<<<256, 256>>>();

    // (2) x -> fp16
    cvt4h_kernel<<<(unsigned)(XN/1024), 256>>>((const float4*)x, (uint32_t*)xs);

    // (3) batched weight transpose -> fp16 (8 weights)
    {
        TAll ta;
        const float* srcs[8] = { wq_down, wkv_down, wk_rope, wq_up, wq_rope, wk_up, wv_up, wo };
        __half* dsts[8] = { wd,            wd + (size_t)512*2048,  wd + (size_t)1024*2048,
                            wuq,           wuq + (size_t)1024*512,
                            wukv,          wukv + (size_t)1024*512,
                            woh };
        int Ks_[8] = { 2048, 2048, 2048, 512, 512, 512, 512, 2048 };
        int Ns_[8] = { 512, 512, 64, 1024, 1024, 1024, 2048, 2048 };
        int total = 0;
        for (int i = 0; i < 8; i++) {
            ta.src[i] = srcs[i]; ta.dst[i] = dsts[i];
            ta.K[i] = Ks_[i]; ta.N[i] = Ns_[i];
            ta.start[i] = total;
            total += (Ns_[i]/32) * (Ks_[i]/32);
        }
        ta.start[8] = total;
        wtrans_all_kernel<<<total, dim3(32, 8)>>>(ta);
    }

    // (4) fused down projection + wk_rope: N=1152 (EPI=4)
    //     cols 0-1023 -> fp16 latents; cols 1024-1087 -> fp32 krr; rest pad.
    hgemm_kernel<4><<<dim3(9, 64), gthr, HG_SMEM>>>(
        xs, wd, krr, lat, nullptr,
        2048, 2048, 64, 1024, 1024);

    // (5) fused up-q: [qc | qr] fp32 (EPI=0)
    hgemm_kernel<0><<<dim3(16, 64), gthr, HG_SMEM>>>(
        lat, wuq, qcr, nullptr, nullptr,
        1024, 512, 2048, 0, 0);

    // (6) fused up-kv: [kc fp32 | V fp16] (EPI=3)
    hgemm_kernel<3><<<dim3(24, 64), gthr, HG_SMEM>>>(
        lat + 512, wukv, kc, V, nullptr,
        1024, 512, 1024, 2048, 1024);

    // (7) merged RoPE + pack Q/K -> fp16
    pack_qk_kernel<<<(2*NM*NHID)/256, thr>>>();

    // (8) flash attention (all fp16) -> ctx fp16
    flasht_kernel<<<dim3(NS/64, NH, NB), 128, FL_SMEM>>>(Qs, Ks, V, ch);

    // (9) fp16 output projection + bias (EPI=1)
    hgemm_kernel<1><<<dim3(16, 64), gthr, HG_SMEM>>>(
        ch, woh, out, nullptr, bo,
        2048, 2048, 2048, 0, 0);
}

// round 16
// speedup vs baseline: 3.4628x; 1.0624x over previous
#include <cuda_runtime.h>
#include <cuda_fp16.h>
#include <math.h>
#include <stdint.h>

#define NB   4
#define NS   2048
#define NH   16
#define NHD  128
#define NRD  64
#define NLAT 512
#define NHID 2048
#define NM   (NB*NS)

// ---------------- device scratch ----------------
__device__ float g_krr [(size_t)NM*NRD];
__device__ float g_cs  [NS*32];
__device__ float g_sn  [NS*32];

// fp16 operands
__device__ __half g_xs  [(size_t)NM*NHID];     // x fp16
__device__ __half g_wd  [(size_t)1152*2048];   // [wq_down|wkv_down|wk_rope|pad] T
__device__ __half g_wuq [(size_t)2048*512];    // [wq_up|wq_rope] T
__device__ __half g_wukv[(size_t)3072*512];    // [wk_up|wv_up] T
__device__ __half g_woh [(size_t)2048*2048];   // wo T
__device__ __half g_lat [(size_t)NM*1024];     // latents
__device__ __half g_qrh [(size_t)NM*1024];     // q_rope pre-rotation fp16
__device__ __half g_V   [(size_t)NM*NHID];     // V
__device__ __half g_Qs  [(size_t)NM*NHID];     // Q (head-interleaved, pre-scaled)
__device__ __half g_Ks  [(size_t)NM*NHID];     // K (head-interleaved)
__device__ __half g_ch  [(size_t)NM*NHID];     // ctx

// ---------------- PTX helpers ----------------
__device__ __forceinline__ void cp16(uint32_t s, const void* g) {
    asm volatile("cp.async.cg.shared.global [%0], [%1], 16;\n" :: "r"(s), "l"(g));
}

#define LDM_X4(R, addr) \
    asm volatile("ldmatrix.sync.aligned.m8n8.x4.shared.b16 {%0,%1,%2,%3}, [%4];" \
        : "=r"(R[0]), "=r"(R[1]), "=r"(R[2]), "=r"(R[3]) : "r"(addr))
#define LDM_X4_T(R, addr) \
    asm volatile("ldmatrix.sync.aligned.m8n8.x4.trans.shared.b16 {%0,%1,%2,%3}, [%4];" \
        : "=r"(R[0]), "=r"(R[1]), "=r"(R[2]), "=r"(R[3]) : "r"(addr))
#define MMAH16816(D, A, B0, B1) \
    asm volatile("mma.sync.aligned.m16n8k16.row.col.f32.f16.f16.f32 " \
        "{%0,%1,%2,%3}, {%4,%5,%6,%7}, {%8,%9}, {%0,%1,%2,%3};" \
        : "+f"(D[0]), "+f"(D[1]), "+f"(D[2]), "+f"(D[3]) \
        : "r"(A[0]), "r"(A[1]), "r"(A[2]), "r"(A[3]), "r"(B0), "r"(B1))

__device__ __forceinline__ uint32_t pack_f16(float a, float b) {   // lo=h(a), hi=h(b)
    uint32_t r;
    asm("cvt.rn.f16x2.f32 %0, %1, %2;" : "=r"(r) : "f"(b), "f"(a));
    return r;
}

#define QSCALE 0.08838834764831845f

// ---------------- x convert fp32 -> fp16 ----------------
__global__ void cvt4h_kernel(const float4* __restrict__ in, uint32_t* __restrict__ out)
{
    size_t i = (size_t)blockIdx.x * blockDim.x + threadIdx.x;
    float4 f = in[i];
    out[2*i]   = pack_f16(f.x, f.y);
    out[2*i+1] = pack_f16(f.z, f.w);
}

// batched transpose fp32 [K,N] -> fp16 [N,K], 8 weights in one launch
struct TAll {
    const float* src[8];
    __half* dst[8];
    int K[8];
    int N[8];
    int start[9];
};

__global__ void wtrans_all_kernel(TAll ta)
{
    __shared__ float t[32][33];
    int bid = blockIdx.x;
    int i = 0;
    #pragma unroll
    for (int j = 1; j < 8; j++) if (bid >= ta.start[j]) i = j;
    int lb = bid - ta.start[i];
    int K = ta.K[i], N = ta.N[i];
    int nbx = N >> 5;
    int n0 = (lb % nbx) * 32, k0 = (lb / nbx) * 32;
    const float* src = ta.src[i];
    __half* dst = ta.dst[i];

    int tx = threadIdx.x, ty = threadIdx.y;
    #pragma unroll
    for (int j = 0; j < 4; j++)
        t[ty + j*8][tx] = src[(size_t)(k0 + ty + j*8) * N + n0 + tx];
    __syncthreads();
    #pragma unroll
    for (int j = 0; j < 4; j++)
        dst[(size_t)(n0 + ty + j*8) * K + k0 + tx] = __float2half_rn(t[tx][ty + j*8]);
}

// ---------------- single-fp16 GEMM ----------------
// C[M,N] = A[M,K(lda)] @ Bt[N,K]^T. Block 128x128, BK=32, 128 thr, warp 64x64.
// EPI 1: fp32 + bias (Nc).
// EPI 4: fp16 Ch (Ns) < boundary; fp32 C at cs<Nc >= boundary, else discard. (down+krr)
// EPI 5: cols<boundary: qc -> Ch head-remap (stride 2048, h=cc/64, d=cc%64, +scale);
//        cols>=: fp16 Ch2 temp (stride 1024). (up-q)
// EPI 6: cols<boundary: kc -> Ch head-remap (stride 2048); cols>=: fp16 Ch2 (stride Ns). (up-kv)
#define SA_ELEMS (128*40)
#define HG_SMEM (4*SA_ELEMS*2)   // 40960 B

__device__ __forceinline__ void hgemm_fill(
    uint32_t sb, int buf,
    const __half* __restrict__ A, const __half* __restrict__ B,
    int tid, int row0, int col0, int k0, int lda, int ldb)
{
    #pragma unroll
    for (int j = 0; j < 4; j++) {
        int chunk = tid + 128*j;
        int r = chunk >> 2, cc = chunk & 3;
        size_t ga = (size_t)(row0 + r) * lda + k0 + cc*8;
        size_t gb = (size_t)(col0 + r) * ldb + k0 + cc*8;
        uint32_t off = (uint32_t)(r*40 + cc*8)*2;
        cp16(sb + (buf*2+0)*SA_ELEMS*2 + off, A + ga);
        cp16(sb + (buf*2+1)*SA_ELEMS*2 + off, B + gb);
    }
    asm volatile("cp.async.commit_group;");
}

template<int EPI>
__global__ void __launch_bounds__(128)
hgemm_kernel(const __half* __restrict__ A, const __half* __restrict__ B,
             float* __restrict__ C, __half* __restrict__ Ch, __half* __restrict__ Ch2,
             const float* __restrict__ bias,
             int lda, int K, int Nc, int Ns, int boundary)
{
    extern __shared__ __half hsm[];
    const uint32_t sb = (uint32_t)__cvta_generic_to_shared(hsm);

    const int tid  = threadIdx.x;
    const int lane = tid & 31;
    const int wid  = tid >> 5;
    const int m0w  = (wid >> 1) * 64;
    const int n0w  = (wid & 1) * 64;
    const int row0 = blockIdx.y * 128;
    const int col0 = blockIdx.x * 128;

    float acc[4][8][4];
    #pragma unroll
    for (int i = 0; i < 4; i++)
        #pragma unroll
        for (int j = 0; j < 8; j++)
            #pragma unroll
            for (int k = 0; k < 4; k++) acc[i][j][k] = 0.f;

    const int niter = K >> 5;
    hgemm_fill(sb, 0, A, B, tid, row0, col0, 0, lda, K);

    const int aRow  = m0w + (lane & 15);
    const int aCol8 = 8 * (lane >> 4);
    const int bRow  = n0w + (lane & 15);

    for (int it = 0; it < niter; ++it) {
        const int buf = it & 1;
        if (it + 1 < niter) {
            hgemm_fill(sb, buf ^ 1, A, B, tid, row0, col0, (it+1)*32, lda, K);
            asm volatile("cp.async.wait_group 1;");
        } else {
            asm volatile("cp.async.wait_group 0;");
        }
        __syncthreads();

        #pragma unroll
        for (int sub = 0; sub < 32; sub += 16) {
            uint32_t ah[4][4];
            #pragma unroll
            for (int mt = 0; mt < 4; mt++) {
                LDM_X4(ah[mt], sb +
                    (uint32_t)((buf*2)*SA_ELEMS + (aRow + mt*16)*40 + sub + aCol8)*2);
            }
            // B non-trans ldmatrix on K-major: pairs n0-7 -> (r0,r2); n8-15 -> (r1,r3)
            #pragma unroll
            for (int ng = 0; ng < 4; ng++) {
                uint32_t bb[4];
                LDM_X4(bb, sb +
                    (uint32_t)((buf*2+1)*SA_ELEMS + (bRow + ng*16)*40 + sub + aCol8)*2);
                #pragma unroll
                for (int half = 0; half < 2; half++) {
                    uint32_t b0 = bb[half], b1 = bb[half+2];
                    int nt = ng*2 + half;
                    #pragma unroll
                    for (int mt = 0; mt < 4; mt++)
                        MMAH16816(acc[mt][nt], ah[mt], b0, b1);
                }
            }
        }
        __syncthreads();
    }

    #pragma unroll
    for (int mt = 0; mt < 4; mt++) {
        #pragma unroll
        for (int nt = 0; nt < 8; nt++) {
            int r  = row0 + m0w + mt*16 + (lane >> 2);
            int cc = col0 + n0w + nt*8 + (lane & 3)*2;
            float a0 = acc[mt][nt][0], a1 = acc[mt][nt][1];
            float a2 = acc[mt][nt][2], a3 = acc[mt][nt][3];
            if (EPI == 1) {
                float b0 = bias[cc], b1 = bias[cc+1];
                *(float2*)(C + (size_t)r     * Nc + cc) = make_float2(a0 + b0, a1 + b1);
                *(float2*)(C + (size_t)(r+8) * Nc + cc) = make_float2(a2 + b0, a3 + b1);
            } else if (EPI == 4) {
                if (col0 < boundary) {
                    *(uint32_t*)(Ch + (size_t)r     * Ns + cc) = pack_f16(a0, a1);
                    *(uint32_t*)(Ch + (size_t)(r+8) * Ns + cc) = pack_f16(a2, a3);
                } else {
                    int cs = cc - boundary;
                    if (cs < Nc) {
                        *(float2*)(C + (size_t)r     * Nc + cs) = make_float2(a0, a1);
                        *(float2*)(C + (size_t)(r+8) * Nc + cs) = make_float2(a2, a3);
                    }
                }
            } else if (EPI == 5) {
                if (cc < boundary) {
                    int h = cc >> 6, d = cc & 63;
                    size_t o = (size_t)h*128 + d;
                    *(uint32_t*)(Ch + (size_t)r     * 2048 + o) = pack_f16(a0*QSCALE, a1*QSCALE);
                    *(uint32_t*)(Ch + (size_t)(r+8) * 2048 + o) = pack_f16(a2*QSCALE, a3*QSCALE);
                } else {
                    int cq = cc - boundary;
                    *(uint32_t*)(Ch2 + (size_t)r     * 1024 + cq) = pack_f16(a0, a1);
                    *(uint32_t*)(Ch2 + (size_t)(r+8) * 1024 + cq) = pack_f16(a2, a3);
                }
            } else {   // EPI == 6
                if (cc < boundary) {
                    int h = cc >> 6, d = cc & 63;
                    size_t o = (size_t)h*128 + d;
                    *(uint32_t*)(Ch + (size_t)r     * 2048 + o) = pack_f16(a0, a1);
                    *(uint32_t*)(Ch + (size_t)(r+8) * 2048 + o) = pack_f16(a2, a3);
                } else {
                    int cs = cc - boundary;
                    *(uint32_t*)(Ch2 + (size_t)r     * Ns + cs) = pack_f16(a0, a1);
                    *(uint32_t*)(Ch2 + (size_t)(r+8) * Ns + cs) = pack_f16(a2, a3);
                }
            }
        }
    }
}

// ---------------- RoPE LUT + rope-only pack ----------------
__global__ void rope_lut_kernel()
{
    int idx = blockIdx.x * blockDim.x + threadIdx.x;
    int pos = idx >> 5, fi = idx & 31;
    float inv = powf(10000.f, -(float)(2*fi) / 64.f);
    float ang = (float)pos * inv;
    float s, c;
    sincosf(ang, &s, &c);
    g_cs[idx] = c;
    g_sn[idx] = s;
}

__global__ void pack_rope_kernel()
{
    int gidx = blockIdx.x * blockDim.x + threadIdx.x;
    const int TOT = NM * 1024;
    bool isK = gidx >= TOT;
    int idx = isK ? (gidx - TOT) : gidx;
    int row = idx >> 10;
    int c   = idx & 1023;
    int h = c >> 6, dd = c & 63;
    int pos = row & (NS - 1);
    float cs = g_cs[pos*32 + (dd & 31)], sn = g_sn[pos*32 + (dd & 31)];
    if (!isK) {
        const __half* qr = g_qrh + (size_t)row*1024 + h*64;
        float v = __half2float(qr[dd]);
        float w = (dd < 32) ? -__half2float(qr[dd + 32]) : __half2float(qr[dd - 32]);
        float out = (v * cs + w * sn) * QSCALE;
        g_Qs[(size_t)row*2048 + h*128 + 64 + dd] = __float2half_rn(out);
    } else {
        const float* kr = g_krr + (size_t)row*NRD;
        float v = kr[dd];
        float w = (dd < 32) ? -kr[dd + 32] : kr[dd - 32];
        float out = v * cs + w * sn;
        g_Ks[(size_t)row*2048 + h*128 + 64 + dd] = __float2half_rn(out);
    }
}

// ---------------- flash attention: all-single-fp16 ----------------
#define FS 136
#define FTILE_B (64*FS*2)
#define FL_SMEM (3*FTILE_B)

__global__ void __launch_bounds__(128)
flasht_kernel(const __half* __restrict__ Q, const __half* __restrict__ K,
              const __half* __restrict__ V, __half* __restrict__ O)
{
    extern __shared__ __half fsm[];
    const uint32_t sb = (uint32_t)__cvta_generic_to_shared(fsm);

    const int tid = threadIdx.x;
    const int lane = tid & 31;
    const int w = tid >> 5;
    const int lr = lane >> 2;
    const int lc = (lane & 3) * 2;
    const int h = blockIdx.y, b = blockIdx.z;
    const int q0 = blockIdx.x * 64;
    const size_t base = ((size_t)b * NS) * NHID + (size_t)h * NHD;

    for (int i = tid; i < 1024; i += 128) {
        int r = i >> 4, c = (i & 15) << 3;
        uint32_t so = (uint32_t)(r*FS + c) * 2;
        cp16(sb + so, Q + base + (size_t)(q0 + r) * NHID + c);
    }
    asm volatile("cp.async.commit_group;");

    float m0 = -1e30f, m1 = -1e30f, l0 = 0.f, l1 = 0.f;
    float o[16][4];
    #pragma unroll
    for (int i = 0; i < 16; i++)
        #pragma unroll
        for (int j = 0; j < 4; j++) o[i][j] = 0.f;

    const int aRow = w*16 + (lane & 15);
    const int hi8  = 8 * (lane >> 4);
    const int ntiles = blockIdx.x + 1;

    for (int t = 0; t < ntiles; t++) {
        const int k0 = t * 64;
        if (t) __syncthreads();
        for (int i = tid; i < 1024; i += 128) {
            int r = i >> 4, c = (i & 15) << 3;
            uint32_t so = (uint32_t)(r*FS + c) * 2;
            size_t go = base + (size_t)(k0 + r) * NHID + c;
            cp16(sb + 1*FTILE_B + so, K + go);
            cp16(sb + 2*FTILE_B + so, V + go);
        }
        asm volatile("cp.async.commit_group;");
        asm volatile("cp.async.wait_group 0;");
        __syncthreads();

        float s[8][4];
        #pragma unroll
        for (int i = 0; i < 8; i++)
            #pragma unroll
            for (int j = 0; j < 4; j++) s[i][j] = 0.f;

        #pragma unroll
        for (int kc = 0; kc < 8; kc++) {
            uint32_t qs[4];
            LDM_X4(qs, sb + (uint32_t)(aRow*FS + kc*16 + hi8)*2);
            #pragma unroll
            for (int g = 0; g < 4; g++) {
                uint32_t ks[4];
                LDM_X4(ks, sb + 1*FTILE_B + (uint32_t)((g*16 + (lane & 15))*FS + kc*16 + hi8)*2);
                MMAH16816(s[2*g],   qs, ks[0], ks[2]);
                MMAH16816(s[2*g+1], qs, ks[1], ks[3]);
            }
        }

        if (t == blockIdx.x) {
            int r0 = q0 + w*16 + lr, r1 = r0 + 8;
            #pragma unroll
            for (int nt = 0; nt < 8; nt++) {
                int c = k0 + nt*8 + lc;
                if (c     > r0) s[nt][0] = -1e30f;
                if (c + 1 > r0) s[nt][1] = -1e30f;
                if (c     > r1) s[nt][2] = -1e30f;
                if (c + 1 > r1) s[nt][3] = -1e30f;
            }
        }

        float mt0 = -1e30f, mt1 = -1e30f;
        #pragma unroll
        for (int nt = 0; nt < 8; nt++) {
            mt0 = fmaxf(mt0, fmaxf(s[nt][0], s[nt][1]));
            mt1 = fmaxf(mt1, fmaxf(s[nt][2], s[nt][3]));
        }
        mt0 = fmaxf(mt0, __shfl_xor_sync(0xffffffffu, mt0, 1));
        mt0 = fmaxf(mt0, __shfl_xor_sync(0xffffffffu, mt0, 2));
        mt1 = fmaxf(mt1, __shfl_xor_sync(0xffffffffu, mt1, 1));
        mt1 = fmaxf(mt1, __shfl_xor_sync(0xffffffffu, mt1, 2));
        float n0 = fmaxf(m0, mt0), n1 = fmaxf(m1, mt1);
        float corr0 = __expf(m0 - n0), corr1 = __expf(m1 - n1);
        m0 = n0; m1 = n1;

        float ps0 = 0.f, ps1 = 0.f;
        #pragma unroll
        for (int nt = 0; nt < 8; nt++) {
            s[nt][0] = __expf(s[nt][0] - n0);
            s[nt][1] = __expf(s[nt][1] - n0);
            s[nt][2] = __expf(s[nt][2] - n1);
            s[nt][3] = __expf(s[nt][3] - n1);
            ps0 += s[nt][0] + s[nt][1];
            ps1 += s[nt][2] + s[nt][3];
        }
        l0 = l0 * corr0 + ps0;
        l1 = l1 * corr1 + ps1;
        #pragma unroll
        for (int i = 0; i < 16; i++) {
            o[i][0] *= corr0; o[i][1] *= corr0;
            o[i][2] *= corr1; o[i][3] *= corr1;
        }

        #pragma unroll
        for (int kc = 0; kc < 4; kc++) {
            uint32_t ph[4];
            ph[0] = pack_f16(s[2*kc][0],   s[2*kc][1]);
            ph[1] = pack_f16(s[2*kc][2],   s[2*kc][3]);
            ph[2] = pack_f16(s[2*kc+1][0], s[2*kc+1][1]);
            ph[3] = pack_f16(s[2*kc+1][2], s[2*kc+1][3]);
            #pragma unroll
            for (int np = 0; np < 8; np++) {
                uint32_t vv[4];
                LDM_X4_T(vv, sb + 2*FTILE_B +
                    (uint32_t)((kc*16 + (lane & 15))*FS + np*16 + hi8)*2);
                MMAH16816(o[2*np],   ph, vv[0], vv[1]);
                MMAH16816(o[2*np+1], ph, vv[2], vv[3]);
            }
        }
    }

    float t0 = l0, t1 = l1;
    t0 += __shfl_xor_sync(0xffffffffu, t0, 1);
    t0 += __shfl_xor_sync(0xffffffffu, t0, 2);
    t1 += __shfl_xor_sync(0xffffffffu, t1, 1);
    t1 += __shfl_xor_sync(0xffffffffu, t1, 2);
    float inv0 = 1.f / t0, inv1 = 1.f / t1;
    int r0 = q0 + w*16 + lr;
    #pragma unroll
    for (int nt = 0; nt < 16; nt++) {
        int c = nt*8 + lc;
        size_t off0 = base + (size_t)r0 * NHID + c;
        size_t off1 = base + (size_t)(r0+8) * NHID + c;
        *(uint32_t*)(O + off0) = pack_f16(o[nt][0]*inv0, o[nt][1]*inv0);
        *(uint32_t*)(O + off1) = pack_f16(o[nt][2]*inv1, o[nt][3]*inv1);
    }
}

// ---------------- host launcher ----------------
extern "C" void kernel_launch(void* const* d_in, const int* in_sizes, int n_in,
                              void* d_out, int out_size)
{
    const float* x        = (const float*)d_in[0];
    const float* wq_down  = (const float*)d_in[1];
    const float* wq_up    = (const float*)d_in[2];
    const float* wq_rope  = (const float*)d_in[3];
    const float* wk_rope  = (const float*)d_in[4];
    const float* wkv_down = (const float*)d_in[5];
    const float* wk_up    = (const float*)d_in[6];
    const float* wv_up    = (const float*)d_in[7];
    const float* wo       = (const float*)d_in[8];
    const float* bo       = (const float*)d_in[9];
    float* out = (float*)d_out;

    float *krr;
    cudaGetSymbolAddress((void**)&krr, g_krr);

    __half *xs, *wd, *wuq, *wukv, *woh, *lat, *qrh, *V, *Qs, *Ks, *ch;
    cudaGetSymbolAddress((void**)&xs,   g_xs);
    cudaGetSymbolAddress((void**)&wd,   g_wd);
    cudaGetSymbolAddress((void**)&wuq,  g_wuq);
    cudaGetSymbolAddress((void**)&wukv, g_wukv);
    cudaGetSymbolAddress((void**)&woh,  g_woh);
    cudaGetSymbolAddress((void**)&lat,  g_lat);
    cudaGetSymbolAddress((void**)&qrh,  g_qrh);
    cudaGetSymbolAddress((void**)&V,    g_V);
    cudaGetSymbolAddress((void**)&Qs,   g_Qs);
    cudaGetSymbolAddress((void**)&Ks,   g_Ks);
    cudaGetSymbolAddress((void**)&ch,   g_ch);

    const size_t XN = (size_t)NM*NHID;

    cudaFuncSetAttribute(hgemm_kernel<1>, cudaFuncAttributeMaxDynamicSharedMemorySize, HG_SMEM);
    cudaFuncSetAttribute(hgemm_kernel<4>, cudaFuncAttributeMaxDynamicSharedMemorySize, HG_SMEM);
    cudaFuncSetAttribute(hgemm_kernel<5>, cudaFuncAttributeMaxDynamicSharedMemorySize, HG_SMEM);
    cudaFuncSetAttribute(hgemm_kernel<6>, cudaFuncAttributeMaxDynamicSharedMemorySize, HG_SMEM);
    cudaFuncSetAttribute(flasht_kernel,   cudaFuncAttributeMaxDynamicSharedMemorySize, FL_SMEM);

    dim3 thr(256);
    dim3 gthr(128);

    // (1) RoPE LUT
    rope_lut_kernel<<<256, 256>>>();

    // (2) x -> fp16
    cvt4h_kernel<<<(unsigned)(XN/1024), 256>>>((const float4*)x, (uint32_t*)xs);

    // (3) batched weight transpose -> fp16 (8 weights)
    {
        TAll ta;
        const float* srcs[8] = { wq_down, wkv_down, wk_rope, wq_up, wq_rope, wk_up, wv_up, wo };
        __half* dsts[8] = { wd,            wd + (size_t)512*2048,  wd + (size_t)1024*2048,
                            wuq,           wuq + (size_t)1024*512,
                            wukv,          wukv + (size_t)1024*512,
                            woh };
        int Ks_[8] = { 2048, 2048, 2048, 512, 512, 512, 512, 2048 };
        int Ns_[8] = { 512, 512, 64, 1024, 1024, 1024, 2048, 2048 };
        int total = 0;
        for (int i = 0; i < 8; i++) {
            ta.src[i] = srcs[i]; ta.dst[i] = dsts[i];
            ta.K[i] = Ks_[i]; ta.N[i] = Ns_[i];
            ta.start[i] = total;
            total += (Ns_[i]/32) * (Ks_[i]/32);
        }
        ta.start[8] = total;
        wtrans_all_kernel<<<total, dim3(32, 8)>>>(ta);
    }

    // (4) fused down projection + wk_rope: N=1152 (EPI=4)
    hgemm_kernel<4><<<dim3(9, 64), gthr, HG_SMEM>>>(
        xs, wd, krr, lat, nullptr, nullptr,
        2048, 2048, 64, 1024, 1024);

    // (5) fused up-q (EPI=5): qc -> Qs head-remapped+scaled; qr -> qrh temp
    hgemm_kernel<5><<<dim3(16, 64), gthr, HG_SMEM>>>(
        lat, wuq, nullptr, Qs, qrh, nullptr,
        1024, 512, 0, 0, 1024);

    // (6) fused up-kv (EPI=6): kc -> Ks head-remapped; V direct
    hgemm_kernel<6><<<dim3(24, 64), gthr, HG_SMEM>>>(
        lat + 512, wukv, nullptr, Ks, V, nullptr,
        1024, 512, 0, 2048, 1024);

    // (7) rope-only pack: Q rope (from qrh) + K rope (from krr, broadcast)
    pack_rope_kernel<<<(2*NM*1024)/256, thr>>>();

    // (8) flash attention (all fp16) -> ctx fp16
    flasht_kernel<<<dim3(NS/64, NH, NB), 128, FL_SMEM>>>(Qs, Ks, V, ch);

    // (9) fp16 output projection + bias (EPI=1)
    hgemm_kernel<1><<<dim3(16, 64), gthr, HG_SMEM>>>(
        ch, woh, out, nullptr, nullptr, bo,
        2048, 2048, 2048, 0, 0);
}